// round 8
// baseline (speedup 1.0000x reference)
#include <cuda_runtime.h>
#include <cuda_bf16.h>
#include <math.h>
#include <stdint.h>

// Problem constants
#define BATCH   4
#define SEQ     1024
#define HID     4096
#define NQH     32
#define NKV     8
#define HD      128
#define QKV_N   6144                 // (NH + 2*NKV) * HD
#define BS_ROWS 4096                 // BATCH * SEQ

// ---------------------------------------------------------------------------
// Scratch (__device__ globals; allocation-free rule)
// ---------------------------------------------------------------------------
__device__ float         g_qkv[(size_t)BS_ROWS * QKV_N];
__device__ __nv_bfloat16 g_hid_hi[(size_t)BS_ROWS * HID];
__device__ __nv_bfloat16 g_hid_lo[(size_t)BS_ROWS * HID];
__device__ __nv_bfloat16 g_wqkvT_hi[(size_t)QKV_N * HID];     // [N, K] (B^T)
__device__ __nv_bfloat16 g_wqkvT_lo[(size_t)QKV_N * HID];
__device__ __nv_bfloat16 g_woT_hi[(size_t)HID * HID];
__device__ __nv_bfloat16 g_woT_lo[(size_t)HID * HID];
__device__ __nv_bfloat16 g_attn_hi[(size_t)BS_ROWS * HID];
__device__ __nv_bfloat16 g_attn_lo[(size_t)BS_ROWS * HID];

__device__ __forceinline__ uint32_t smem_u32(const void* p) {
    uint32_t a;
    asm("{ .reg .u64 t; cvta.to.shared.u64 t, %1; cvt.u32.u64 %0, t; }" : "=r"(a) : "l"(p));
    return a;
}

// ---------------------------------------------------------------------------
// Split kernels: f32 -> (hi, lo) bf16
// ---------------------------------------------------------------------------
__global__ void split_act(const float* __restrict__ in,
                          __nv_bfloat16* __restrict__ hi,
                          __nv_bfloat16* __restrict__ lo, int n4) {
    int i = blockIdx.x * blockDim.x + threadIdx.x;
    if (i >= n4) return;
    float4 v = ((const float4*)in)[i];
    float x[4] = {v.x, v.y, v.z, v.w};
#pragma unroll
    for (int j = 0; j < 4; j++) {
        __nv_bfloat16 h = __float2bfloat16(x[j]);
        hi[i * 4 + j] = h;
        lo[i * 4 + j] = __float2bfloat16(x[j] - __bfloat162float(h));
    }
}

// W[Kdim, Ndim] f32 -> transposed hi/lo [Ndim, Kdim] bf16 (tiled 32x32)
__global__ void split_T(const float* __restrict__ W,
                        __nv_bfloat16* __restrict__ hiT,
                        __nv_bfloat16* __restrict__ loT, int Kdim, int Ndim) {
    __shared__ float t[32][33];
    int n0 = blockIdx.x * 32, k0 = blockIdx.y * 32;
    t[threadIdx.y][threadIdx.x] = W[(long)(k0 + threadIdx.y) * Ndim + n0 + threadIdx.x];
    __syncthreads();
    float x = t[threadIdx.x][threadIdx.y];
    long o = (long)(n0 + threadIdx.y) * Kdim + k0 + threadIdx.x;
    __nv_bfloat16 h = __float2bfloat16(x);
    hiT[o] = h;
    loT[o] = __float2bfloat16(x - __bfloat162float(h));
}

// ---------------------------------------------------------------------------
// HMMA GEMM: C[M,N] = A[M,K] @ Bt[N,K]^T, hi/lo 3-pass bf16 mma.sync.
// CTA 128x128, BK=32, 512 threads = 16 warps (4Mx4N), warp tile 32x32.
// Smem: contiguous 8x8-bf16 matrices (128B), 3-stage cp.async ring,
// ONE __syncthreads per K-tile. MMA issue is PASS-MAJOR so consecutive
// MMAs hit different accumulators (hides HMMA accumulator RAW latency).
// ---------------------------------------------------------------------------
#define STAGE_BYTES 32768
#define NSTAGE 3
#define A_HI_OFF 0
#define A_LO_OFF 8192
#define B_HI_OFF 16384
#define B_LO_OFF 24576
// matrix (rm, km) of a 128x32 operand block lives at (rm*4+km)*128

#define LDSM4(R, ADDR) \
    asm volatile("ldmatrix.sync.aligned.m8n8.x4.shared.b16 {%0,%1,%2,%3}, [%4];" \
                 : "=r"((R)[0]), "=r"((R)[1]), "=r"((R)[2]), "=r"((R)[3]) : "r"(ADDR))

#define MMA_BF16(ACC, A, B) \
    asm volatile("mma.sync.aligned.m16n8k16.row.col.f32.bf16.bf16.f32 " \
                 "{%0,%1,%2,%3}, {%4,%5,%6,%7}, {%8,%9}, {%0,%1,%2,%3};" \
                 : "+f"((ACC)[0]), "+f"((ACC)[1]), "+f"((ACC)[2]), "+f"((ACC)[3]) \
                 : "r"((A)[0]), "r"((A)[1]), "r"((A)[2]), "r"((A)[3]), \
                   "r"((B)[0]), "r"((B)[1]))

__device__ __forceinline__ void cp16(uint32_t dst, const void* src) {
    asm volatile("cp.async.cg.shared.global [%0], [%1], 16;" :: "r"(dst), "l"(src));
}

__device__ __forceinline__ void g2s_tile(
    uint32_t sb,
    const __nv_bfloat16* __restrict__ Ahi, const __nv_bfloat16* __restrict__ Alo,
    const __nv_bfloat16* __restrict__ Bhi, const __nv_bfloat16* __restrict__ Blo,
    long bm, long bn, int k0, int K, int tid)
{
    // 512 threads: each does one 16B chunk per tensor
    int r  = tid >> 2;               // 0..127
    int kc = tid & 3;                // 16B chunk within BK=32
    uint32_t moff = (uint32_t)((((r >> 3) << 2) + kc) * 128 + (r & 7) * 16);
    long ga = (bm + r) * (long)K + k0 + kc * 8;
    long gb = (bn + r) * (long)K + k0 + kc * 8;
    cp16(sb + A_HI_OFF + moff, Ahi + ga);
    cp16(sb + A_LO_OFF + moff, Alo + ga);
    cp16(sb + B_HI_OFF + moff, Bhi + gb);
    cp16(sb + B_LO_OFF + moff, Blo + gb);
}

__global__ __launch_bounds__(512, 1)
void gemm_mma3(const __nv_bfloat16* __restrict__ Ahi, const __nv_bfloat16* __restrict__ Alo,
               const __nv_bfloat16* __restrict__ Bhi, const __nv_bfloat16* __restrict__ Blo,
               float* __restrict__ C, int N, int K)
{
    extern __shared__ char smx[];
    const uint32_t s0 = smem_u32(smx);
    const int tid  = threadIdx.x;
    const int wid  = tid >> 5;
    const int lane = tid & 31;
    const int wm   = wid >> 2;        // 0..3  (M)
    const int wn   = wid & 3;         // 0..3  (N)
    const int sel  = lane >> 3;       // ldmatrix lane group
    const int rowin = lane & 7;
    const int g    = lane >> 2;       // mma row group
    const int tq   = lane & 3;        // mma quad thread
    const long bm = (long)blockIdx.y * 128;
    const long bn = (long)blockIdx.x * 128;

    float acc[2][4][4];
#pragma unroll
    for (int i = 0; i < 2; i++)
#pragma unroll
        for (int j = 0; j < 4; j++)
#pragma unroll
            for (int k = 0; k < 4; k++) acc[i][j][k] = 0.f;

    const int NT = K >> 5;

    // Prologue: prefetch tiles 0 and 1
    g2s_tile(s0, Ahi, Alo, Bhi, Blo, bm, bn, 0, K, tid);
    asm volatile("cp.async.commit_group;" ::: "memory");
    g2s_tile(s0 + STAGE_BYTES, Ahi, Alo, Bhi, Blo, bm, bn, 32, K, tid);
    asm volatile("cp.async.commit_group;" ::: "memory");

    int stage = 0;            // buffer index of tile t
    int nstage = 2;           // buffer index of tile t+2 (== (stage+2)%3)
    for (int t = 0; t < NT; t++) {
        if (t == NT - 1) {
            asm volatile("cp.async.wait_group 0;" ::: "memory");
        } else {
            asm volatile("cp.async.wait_group 1;" ::: "memory");
        }
        __syncthreads();      // tile t ready; all warps done with buffer (t+2)%3

        if (t + 2 < NT) {
            g2s_tile(s0 + nstage * STAGE_BYTES,
                     Ahi, Alo, Bhi, Blo, bm, bn, (t + 2) << 5, K, tid);
            asm volatile("cp.async.commit_group;" ::: "memory");
        }

        const uint32_t sb = s0 + stage * STAGE_BYTES;
#pragma unroll
        for (int ks = 0; ks < 2; ks++) {
            uint32_t ah[2][4], al[2][4], bh[4][2], bl[4][2];
#pragma unroll
            for (int mt = 0; mt < 2; mt++) {
                int rm = wm * 4 + 2 * mt + (sel & 1);
                int km = 2 * ks + (sel >> 1);
                uint32_t off = (uint32_t)(((rm << 2) + km) * 128 + rowin * 16);
                LDSM4(ah[mt], sb + A_HI_OFF + off);
                LDSM4(al[mt], sb + A_LO_OFF + off);
            }
#pragma unroll
            for (int bt = 0; bt < 2; bt++) {
                int nm = wn * 4 + 2 * bt + (sel >> 1);
                int km = 2 * ks + (sel & 1);
                uint32_t off = (uint32_t)(((nm << 2) + km) * 128 + rowin * 16);
                uint32_t r4[4];
                LDSM4(r4, sb + B_HI_OFF + off);
                bh[2 * bt][0] = r4[0]; bh[2 * bt][1] = r4[1];
                bh[2 * bt + 1][0] = r4[2]; bh[2 * bt + 1][1] = r4[3];
                LDSM4(r4, sb + B_LO_OFF + off);
                bl[2 * bt][0] = r4[0]; bl[2 * bt][1] = r4[1];
                bl[2 * bt + 1][0] = r4[2]; bl[2 * bt + 1][1] = r4[3];
            }
            // PASS-MAJOR: consecutive MMAs hit different accumulators
            // (8 independent in flight before any acc is revisited).
#pragma unroll
            for (int mt = 0; mt < 2; mt++)
#pragma unroll
                for (int nt = 0; nt < 4; nt++)
                    MMA_BF16(acc[mt][nt], ah[mt], bh[nt]);
#pragma unroll
            for (int mt = 0; mt < 2; mt++)
#pragma unroll
                for (int nt = 0; nt < 4; nt++)
                    MMA_BF16(acc[mt][nt], ah[mt], bl[nt]);
#pragma unroll
            for (int mt = 0; mt < 2; mt++)
#pragma unroll
                for (int nt = 0; nt < 4; nt++)
                    MMA_BF16(acc[mt][nt], al[mt], bh[nt]);
        }
        stage  = (stage == NSTAGE - 1) ? 0 : stage + 1;
        nstage = (nstage == NSTAGE - 1) ? 0 : nstage + 1;
    }

    // Epilogue: direct global stores (float2 per 4-lane quad-row)
#pragma unroll
    for (int mt = 0; mt < 2; mt++) {
        long row0 = bm + wm * 32 + mt * 16 + g;
#pragma unroll
        for (int nt = 0; nt < 4; nt++) {
            long col = bn + wn * 32 + nt * 8 + tq * 2;
            *(float2*)&C[row0 * N + col]       = make_float2(acc[mt][nt][0], acc[mt][nt][1]);
            *(float2*)&C[(row0 + 8) * N + col] = make_float2(acc[mt][nt][2], acc[mt][nt][3]);
        }
    }
}

// ---------------------------------------------------------------------------
// RoPE (NeoX, full head_dim) in-place on q|k of g_qkv
// ---------------------------------------------------------------------------
__global__ void rope_kernel(const int* __restrict__ pos) {
    const int TOT = BS_ROWS * (NQH + NKV) * 64;
    int idx = blockIdx.x * blockDim.x + threadIdx.x;
    if (idx >= TOT) return;
    int i   = idx & 63;
    int h   = (idx >> 6) % (NQH + NKV);
    int row = idx / (64 * (NQH + NKV));
    int p   = pos[row];

    float* ptr = g_qkv + (long)row * QKV_N + (long)h * HD;
    float inv = expf(-(float)i * 0.14391156831212787f);   // ln(10000)/64
    float ang = (float)p * inv;
    float sn, cs;
    sincosf(ang, &sn, &cs);
    float x1 = ptr[i], x2 = ptr[i + 64];
    ptr[i]      = x1 * cs - x2 * sn;
    ptr[i + 64] = x2 * cs + x1 * sn;
}

// ---------------------------------------------------------------------------
// Flash attention (fp32, causal, GQA rep=4); emits hi/lo bf16 for GEMM2.
// ---------------------------------------------------------------------------
__global__ __launch_bounds__(256, 1)
void flash_attn() {
    extern __shared__ float smf[];
    float* QsT = smf;             // [128][64]
    float* KsT = smf + 8192;      // [128][64]
    float* Vs  = smf + 16384;     // [64][128]
    float* Ps  = smf + 24576;     // [64][64]

    const float* qkv = g_qkv;
    const int tid = threadIdx.x;
    const int qt  = blockIdx.x;
    const int h   = blockIdx.y;
    const int b   = blockIdx.z;
    const int kvh = h >> 2;
    const int q0  = qt << 6;
    const int ty  = tid >> 4;
    const int tx  = tid & 15;

    const float* gq = qkv + ((long)(b * SEQ + q0)) * QKV_N + h * HD;
#pragma unroll
    for (int e = tid; e < 2048; e += 256) {
        int c = e & 63;
        int d = (e >> 6) << 2;
        float4 v = *(const float4*)(gq + (long)c * QKV_N + d);
        QsT[(d + 0) * 64 + c] = v.x;
        QsT[(d + 1) * 64 + c] = v.y;
        QsT[(d + 2) * 64 + c] = v.z;
        QsT[(d + 3) * 64 + c] = v.w;
    }

    float m_prev[4], l_run[4], o[4][8];
#pragma unroll
    for (int i = 0; i < 4; i++) {
        m_prev[i] = -3.0e38f;
        l_run[i]  = 0.f;
#pragma unroll
        for (int j = 0; j < 8; j++) o[i][j] = 0.f;
    }

    const float scale = 0.08838834764831845f;

    for (int kt = 0; kt <= qt; kt++) {
        const int k0 = kt << 6;
        __syncthreads();

        const float* gk = qkv + ((long)(b * SEQ + k0)) * QKV_N + NQH * HD + kvh * HD;
#pragma unroll
        for (int e = tid; e < 2048; e += 256) {
            int c = e & 63;
            int d = (e >> 6) << 2;
            float4 v = *(const float4*)(gk + (long)c * QKV_N + d);
            KsT[(d + 0) * 64 + c] = v.x;
            KsT[(d + 1) * 64 + c] = v.y;
            KsT[(d + 2) * 64 + c] = v.z;
            KsT[(d + 3) * 64 + c] = v.w;
        }
        const float* gv = gk + NKV * HD;
#pragma unroll
        for (int e = tid; e < 2048; e += 256) {
            int r = e >> 5;
            int d = (e & 31) << 2;
            *(float4*)&Vs[r * 128 + d] = *(const float4*)(gv + (long)r * QKV_N + d);
        }
        __syncthreads();

        float acc[4][4];
#pragma unroll
        for (int i = 0; i < 4; i++)
#pragma unroll
            for (int j = 0; j < 4; j++) acc[i][j] = 0.f;

#pragma unroll 8
        for (int d = 0; d < 128; d++) {
            float4 q4 = *(const float4*)&QsT[d * 64 + (ty << 2)];
            float4 k4 = *(const float4*)&KsT[d * 64 + (tx << 2)];
            float qa[4] = {q4.x, q4.y, q4.z, q4.w};
            float ka[4] = {k4.x, k4.y, k4.z, k4.w};
#pragma unroll
            for (int i = 0; i < 4; i++)
#pragma unroll
                for (int j = 0; j < 4; j++)
                    acc[i][j] = fmaf(qa[i], ka[j], acc[i][j]);
        }

        const bool diag = (kt == qt);
        float alpha[4];
#pragma unroll
        for (int i = 0; i < 4; i++) {
            const int qrow = q0 + (ty << 2) + i;
            float tmp[4];
#pragma unroll
            for (int j = 0; j < 4; j++) {
                float s = acc[i][j] * scale;
                if (diag && (k0 + (tx << 2) + j > qrow)) s = -1.0e30f;
                tmp[j] = s;
            }
            float rm = fmaxf(fmaxf(tmp[0], tmp[1]), fmaxf(tmp[2], tmp[3]));
            rm = fmaxf(rm, __shfl_xor_sync(0xffffffffu, rm, 1, 16));
            rm = fmaxf(rm, __shfl_xor_sync(0xffffffffu, rm, 2, 16));
            rm = fmaxf(rm, __shfl_xor_sync(0xffffffffu, rm, 4, 16));
            rm = fmaxf(rm, __shfl_xor_sync(0xffffffffu, rm, 8, 16));
            float m_new = fmaxf(m_prev[i], rm);
            float al = expf(m_prev[i] - m_new);
            float rs = 0.f;
#pragma unroll
            for (int j = 0; j < 4; j++) {
                float p = expf(tmp[j] - m_new);
                tmp[j] = p;
                rs += p;
            }
            rs += __shfl_xor_sync(0xffffffffu, rs, 1, 16);
            rs += __shfl_xor_sync(0xffffffffu, rs, 2, 16);
            rs += __shfl_xor_sync(0xffffffffu, rs, 4, 16);
            rs += __shfl_xor_sync(0xffffffffu, rs, 8, 16);
            l_run[i]  = l_run[i] * al + rs;
            m_prev[i] = m_new;
            alpha[i]  = al;
            *(float4*)&Ps[(((ty << 2) + i) << 6) + (tx << 2)] =
                make_float4(tmp[0], tmp[1], tmp[2], tmp[3]);
        }
        __syncthreads();

#pragma unroll
        for (int i = 0; i < 4; i++)
#pragma unroll
            for (int j = 0; j < 8; j++) o[i][j] *= alpha[i];

#pragma unroll 4
        for (int k = 0; k < 64; k++) {
            float pv[4];
#pragma unroll
            for (int i = 0; i < 4; i++) pv[i] = Ps[(((ty << 2) + i) << 6) + k];
            float4 v0 = *(const float4*)&Vs[k * 128 + (tx << 3)];
            float4 v1 = *(const float4*)&Vs[k * 128 + (tx << 3) + 4];
            float vv[8] = {v0.x, v0.y, v0.z, v0.w, v1.x, v1.y, v1.z, v1.w};
#pragma unroll
            for (int i = 0; i < 4; i++)
#pragma unroll
                for (int j = 0; j < 8; j++)
                    o[i][j] = fmaf(pv[i], vv[j], o[i][j]);
        }
    }

    // Normalize; write hi/lo bf16 (GEMM2 operand A)
#pragma unroll
    for (int i = 0; i < 4; i++) {
        float inv = 1.0f / l_run[i];
        long row = (long)(b * SEQ + q0 + (ty << 2) + i);
        long off = row * HID + h * HD + (tx << 3);
#pragma unroll
        for (int j = 0; j < 8; j++) {
            float v = o[i][j] * inv;
            __nv_bfloat16 hb = __float2bfloat16(v);
            g_attn_hi[off + j] = hb;
            g_attn_lo[off + j] = __float2bfloat16(v - __bfloat162float(hb));
        }
    }
}

// ---------------------------------------------------------------------------
// Launch: splits -> QKV HMMA-GEMM -> RoPE -> flash -> O HMMA-GEMM
// ---------------------------------------------------------------------------
extern "C" void kernel_launch(void* const* d_in, const int* in_sizes, int n_in,
                              void* d_out, int out_size) {
    const int*   positions = (const int*)d_in[0];
    const float* hidden    = (const float*)d_in[1];
    const float* w_qkv     = (const float*)d_in[2];
    const float* w_o       = (const float*)d_in[3];
    float*       out       = (float*)d_out;

    static __nv_bfloat16 *hid_hi, *hid_lo, *wqT_hi, *wqT_lo, *woT_hi, *woT_lo;
    static __nv_bfloat16 *attn_hi, *attn_lo;
    static float* qkv;
    static bool init = false;
    if (!init) {
        cudaGetSymbolAddress((void**)&hid_hi,  g_hid_hi);
        cudaGetSymbolAddress((void**)&hid_lo,  g_hid_lo);
        cudaGetSymbolAddress((void**)&wqT_hi,  g_wqkvT_hi);
        cudaGetSymbolAddress((void**)&wqT_lo,  g_wqkvT_lo);
        cudaGetSymbolAddress((void**)&woT_hi,  g_woT_hi);
        cudaGetSymbolAddress((void**)&woT_lo,  g_woT_lo);
        cudaGetSymbolAddress((void**)&attn_hi, g_attn_hi);
        cudaGetSymbolAddress((void**)&attn_lo, g_attn_lo);
        cudaGetSymbolAddress((void**)&qkv,     g_qkv);
        cudaFuncSetAttribute(gemm_mma3, cudaFuncAttributeMaxDynamicSharedMemorySize,
                             NSTAGE * STAGE_BYTES);
        cudaFuncSetAttribute(flash_attn, cudaFuncAttributeMaxDynamicSharedMemorySize, 114688);
        init = true;
    }

    // Split inputs to bf16 hi/lo (weights transposed to [N, K])
    {
        int n4 = BS_ROWS * HID / 4;
        split_act<<<(n4 + 255) / 256, 256>>>(hidden, hid_hi, hid_lo, n4);
    }
    split_T<<<dim3(QKV_N / 32, HID / 32), dim3(32, 32)>>>(w_qkv, wqT_hi, wqT_lo, HID, QKV_N);
    split_T<<<dim3(HID / 32, HID / 32), dim3(32, 32)>>>(w_o, woT_hi, woT_lo, HID, HID);

    // QKV projection: [4096,4096] @ [4096,6144] -> g_qkv (f32)
    gemm_mma3<<<dim3(QKV_N / 128, BS_ROWS / 128), 512, NSTAGE * STAGE_BYTES>>>(
        hid_hi, hid_lo, wqT_hi, wqT_lo, qkv, QKV_N, HID);

    const int tot = BS_ROWS * (NQH + NKV) * 64;
    rope_kernel<<<(tot + 255) / 256, 256>>>(positions);

    flash_attn<<<dim3(SEQ / 64, NQH, BATCH), 256, 114688>>>();

    // Output projection: [4096,4096] @ [4096,4096] -> out
    gemm_mma3<<<dim3(HID / 128, BS_ROWS / 128), 512, NSTAGE * STAGE_BYTES>>>(
        attn_hi, attn_lo, woT_hi, woT_lo, out, HID, HID);
}

// round 9
// speedup vs baseline: 1.4010x; 1.4010x over previous
#include <cuda_runtime.h>
#include <cuda_fp16.h>
#include <math.h>
#include <stdint.h>

// Problem constants
#define BATCH   4
#define SEQ     1024
#define HID     4096
#define NQH     32
#define NKV     8
#define HD      128
#define QKV_N   6144                 // (NH + 2*NKV) * HD
#define BS_ROWS 4096                 // BATCH * SEQ

// ---------------------------------------------------------------------------
// Scratch (__device__ globals; allocation-free rule)
// ---------------------------------------------------------------------------
__device__ float  g_qkv[(size_t)BS_ROWS * QKV_N];
__device__ __half g_hid_f16[(size_t)BS_ROWS * HID];        // A of GEMM1 (single)
__device__ __half g_wqkvT_hi[(size_t)QKV_N * HID];         // [N, K] (B^T) hi
__device__ __half g_wqkvT_lo[(size_t)QKV_N * HID];         // lo
__device__ __half g_woT_hi[(size_t)HID * HID];
__device__ __half g_woT_lo[(size_t)HID * HID];
__device__ __half g_attn_f16[(size_t)BS_ROWS * HID];       // A of GEMM2 (single)

__device__ __forceinline__ uint32_t smem_u32(const void* p) {
    uint32_t a;
    asm("{ .reg .u64 t; cvta.to.shared.u64 t, %1; cvt.u32.u64 %0, t; }" : "=r"(a) : "l"(p));
    return a;
}

// ---------------------------------------------------------------------------
// Split kernels
// ---------------------------------------------------------------------------
__global__ void act_to_f16(const float* __restrict__ in, __half* __restrict__ out, int n4) {
    int i = blockIdx.x * blockDim.x + threadIdx.x;
    if (i >= n4) return;
    float4 v = ((const float4*)in)[i];
    __half2* o = (__half2*)(out + i * 4);
    o[0] = __floats2half2_rn(v.x, v.y);
    o[1] = __floats2half2_rn(v.z, v.w);
}

// W[Kdim, Ndim] f32 -> transposed hi/lo [Ndim, Kdim] fp16 (tiled 32x32)
__global__ void split_T(const float* __restrict__ W,
                        __half* __restrict__ hiT,
                        __half* __restrict__ loT, int Kdim, int Ndim) {
    __shared__ float t[32][33];
    int n0 = blockIdx.x * 32, k0 = blockIdx.y * 32;
    t[threadIdx.y][threadIdx.x] = W[(long)(k0 + threadIdx.y) * Ndim + n0 + threadIdx.x];
    __syncthreads();
    float x = t[threadIdx.x][threadIdx.y];
    long o = (long)(n0 + threadIdx.y) * Kdim + k0 + threadIdx.x;
    __half h = __float2half(x);
    hiT[o] = h;
    loT[o] = __float2half(x - __half2float(h));
}

// ---------------------------------------------------------------------------
// HMMA GEMM: C[M,N] = A[M,K] @ Bt[N,K]^T, fp16 2-pass (A single, B hi/lo).
// CTA 256x128 (MxN), BK=32, 512 threads = 16 warps (4Mx4N), warp tile 64x32.
// Smem: contiguous 8x8-fp16 matrices (128B), 3-stage cp.async ring,
// ONE __syncthreads per K-tile.
// ---------------------------------------------------------------------------
#define STAGE_BYTES 32768
#define NSTAGE 3
#define A_OFF    0            // 16 KB: 256 rows x 32 k
#define B_HI_OFF 16384        // 8 KB: 128 rows x 32 k
#define B_LO_OFF 24576        // 8 KB
// matrix (rm, km) of an operand block lives at (rm*4+km)*128

#define LDSM4(R, ADDR) \
    asm volatile("ldmatrix.sync.aligned.m8n8.x4.shared.b16 {%0,%1,%2,%3}, [%4];" \
                 : "=r"((R)[0]), "=r"((R)[1]), "=r"((R)[2]), "=r"((R)[3]) : "r"(ADDR))

#define MMA_F16(ACC, A, B) \
    asm volatile("mma.sync.aligned.m16n8k16.row.col.f32.f16.f16.f32 " \
                 "{%0,%1,%2,%3}, {%4,%5,%6,%7}, {%8,%9}, {%0,%1,%2,%3};" \
                 : "+f"((ACC)[0]), "+f"((ACC)[1]), "+f"((ACC)[2]), "+f"((ACC)[3]) \
                 : "r"((A)[0]), "r"((A)[1]), "r"((A)[2]), "r"((A)[3]), \
                   "r"((B)[0]), "r"((B)[1]))

__device__ __forceinline__ void cp16(uint32_t dst, const void* src) {
    asm volatile("cp.async.cg.shared.global [%0], [%1], 16;" :: "r"(dst), "l"(src));
}

__device__ __forceinline__ void g2s_tile(
    uint32_t sb,
    const __half* __restrict__ A,
    const __half* __restrict__ Bhi, const __half* __restrict__ Blo,
    long bm, long bn, int k0, int K, int tid)
{
    // A: 1024 chunks (2 per thread); Bhi/Blo: 512 chunks (1 per thread each)
#pragma unroll
    for (int i = 0; i < 2; i++) {
        int e  = tid + i * 512;          // 0..1023
        int r  = e >> 2;                 // 0..255
        int kc = e & 3;
        uint32_t moff = (uint32_t)((((r >> 3) << 2) + kc) * 128 + (r & 7) * 16);
        cp16(sb + A_OFF + moff, A + (bm + r) * (long)K + k0 + kc * 8);
    }
    {
        int r  = tid >> 2;               // 0..127
        int kc = tid & 3;
        uint32_t moff = (uint32_t)((((r >> 3) << 2) + kc) * 128 + (r & 7) * 16);
        long gb = (bn + r) * (long)K + k0 + kc * 8;
        cp16(sb + B_HI_OFF + moff, Bhi + gb);
        cp16(sb + B_LO_OFF + moff, Blo + gb);
    }
}

__global__ __launch_bounds__(512, 1)
void gemm_f16x2(const __half* __restrict__ A,
                const __half* __restrict__ Bhi, const __half* __restrict__ Blo,
                float* __restrict__ C, int N, int K)
{
    extern __shared__ char smx[];
    const uint32_t s0 = smem_u32(smx);
    const int tid  = threadIdx.x;
    const int wid  = tid >> 5;
    const int lane = tid & 31;
    const int wm   = wid >> 2;        // 0..3  (M, 64 rows each)
    const int wn   = wid & 3;         // 0..3  (N, 32 cols each)
    const int sel  = lane >> 3;       // ldmatrix lane group
    const int rowin = lane & 7;
    const int g    = lane >> 2;       // mma row group
    const int tq   = lane & 3;        // mma quad thread
    const long bm = (long)blockIdx.y * 256;
    const long bn = (long)blockIdx.x * 128;

    float acc[4][4][4];
#pragma unroll
    for (int i = 0; i < 4; i++)
#pragma unroll
        for (int j = 0; j < 4; j++)
#pragma unroll
            for (int k = 0; k < 4; k++) acc[i][j][k] = 0.f;

    const int NT = K >> 5;

    // Prologue: prefetch tiles 0 and 1
    g2s_tile(s0, A, Bhi, Blo, bm, bn, 0, K, tid);
    asm volatile("cp.async.commit_group;" ::: "memory");
    g2s_tile(s0 + STAGE_BYTES, A, Bhi, Blo, bm, bn, 32, K, tid);
    asm volatile("cp.async.commit_group;" ::: "memory");

    int stage = 0;
    int nstage = 2;
    for (int t = 0; t < NT; t++) {
        if (t == NT - 1) {
            asm volatile("cp.async.wait_group 0;" ::: "memory");
        } else {
            asm volatile("cp.async.wait_group 1;" ::: "memory");
        }
        __syncthreads();

        if (t + 2 < NT) {
            g2s_tile(s0 + nstage * STAGE_BYTES, A, Bhi, Blo, bm, bn, (t + 2) << 5, K, tid);
            asm volatile("cp.async.commit_group;" ::: "memory");
        }

        const uint32_t sb = s0 + stage * STAGE_BYTES;
#pragma unroll
        for (int ks = 0; ks < 2; ks++) {
            uint32_t a[4][4], bh[4][2], bl[4][2];
#pragma unroll
            for (int mt = 0; mt < 4; mt++) {
                int rm = wm * 8 + 2 * mt + (sel & 1);
                int km = 2 * ks + (sel >> 1);
                uint32_t off = (uint32_t)(((rm << 2) + km) * 128 + rowin * 16);
                LDSM4(a[mt], sb + A_OFF + off);
            }
#pragma unroll
            for (int bt = 0; bt < 2; bt++) {
                int nm = wn * 4 + 2 * bt + (sel >> 1);
                int km = 2 * ks + (sel & 1);
                uint32_t off = (uint32_t)(((nm << 2) + km) * 128 + rowin * 16);
                uint32_t r4[4];
                LDSM4(r4, sb + B_HI_OFF + off);
                bh[2 * bt][0] = r4[0]; bh[2 * bt][1] = r4[1];
                bh[2 * bt + 1][0] = r4[2]; bh[2 * bt + 1][1] = r4[3];
                LDSM4(r4, sb + B_LO_OFF + off);
                bl[2 * bt][0] = r4[0]; bl[2 * bt][1] = r4[1];
                bl[2 * bt + 1][0] = r4[2]; bl[2 * bt + 1][1] = r4[3];
            }
#pragma unroll
            for (int mt = 0; mt < 4; mt++)
#pragma unroll
                for (int nt = 0; nt < 4; nt++) {
                    MMA_F16(acc[mt][nt], a[mt], bh[nt]);
                    MMA_F16(acc[mt][nt], a[mt], bl[nt]);
                }
        }
        stage  = (stage == NSTAGE - 1) ? 0 : stage + 1;
        nstage = (nstage == NSTAGE - 1) ? 0 : nstage + 1;
    }

    // Epilogue: direct global stores (float2 per 4-lane quad-row)
#pragma unroll
    for (int mt = 0; mt < 4; mt++) {
        long row0 = bm + wm * 64 + mt * 16 + g;
#pragma unroll
        for (int nt = 0; nt < 4; nt++) {
            long col = bn + wn * 32 + nt * 8 + tq * 2;
            *(float2*)&C[row0 * N + col]       = make_float2(acc[mt][nt][0], acc[mt][nt][1]);
            *(float2*)&C[(row0 + 8) * N + col] = make_float2(acc[mt][nt][2], acc[mt][nt][3]);
        }
    }
}

// ---------------------------------------------------------------------------
// RoPE (NeoX, full head_dim) in-place on q|k of g_qkv
// ---------------------------------------------------------------------------
__global__ void rope_kernel(const int* __restrict__ pos) {
    const int TOT = BS_ROWS * (NQH + NKV) * 64;
    int idx = blockIdx.x * blockDim.x + threadIdx.x;
    if (idx >= TOT) return;
    int i   = idx & 63;
    int h   = (idx >> 6) % (NQH + NKV);
    int row = idx / (64 * (NQH + NKV));
    int p   = pos[row];

    float* ptr = g_qkv + (long)row * QKV_N + (long)h * HD;
    float inv = expf(-(float)i * 0.14391156831212787f);   // ln(10000)/64
    float ang = (float)p * inv;
    float sn, cs;
    sincosf(ang, &sn, &cs);
    float x1 = ptr[i], x2 = ptr[i + 64];
    ptr[i]      = x1 * cs - x2 * sn;
    ptr[i + 64] = x2 * cs + x1 * sn;
}

// ---------------------------------------------------------------------------
// Flash attention (fp32, causal, GQA rep=4); emits fp16 for GEMM2.
// ---------------------------------------------------------------------------
__global__ __launch_bounds__(256, 1)
void flash_attn() {
    extern __shared__ float smf[];
    float* QsT = smf;             // [128][64]
    float* KsT = smf + 8192;      // [128][64]
    float* Vs  = smf + 16384;     // [64][128]
    float* Ps  = smf + 24576;     // [64][64]

    const float* qkv = g_qkv;
    const int tid = threadIdx.x;
    const int qt  = blockIdx.x;
    const int h   = blockIdx.y;
    const int b   = blockIdx.z;
    const int kvh = h >> 2;
    const int q0  = qt << 6;
    const int ty  = tid >> 4;
    const int tx  = tid & 15;

    const float* gq = qkv + ((long)(b * SEQ + q0)) * QKV_N + h * HD;
#pragma unroll
    for (int e = tid; e < 2048; e += 256) {
        int c = e & 63;
        int d = (e >> 6) << 2;
        float4 v = *(const float4*)(gq + (long)c * QKV_N + d);
        QsT[(d + 0) * 64 + c] = v.x;
        QsT[(d + 1) * 64 + c] = v.y;
        QsT[(d + 2) * 64 + c] = v.z;
        QsT[(d + 3) * 64 + c] = v.w;
    }

    float m_prev[4], l_run[4], o[4][8];
#pragma unroll
    for (int i = 0; i < 4; i++) {
        m_prev[i] = -3.0e38f;
        l_run[i]  = 0.f;
#pragma unroll
        for (int j = 0; j < 8; j++) o[i][j] = 0.f;
    }

    const float scale = 0.08838834764831845f;

    for (int kt = 0; kt <= qt; kt++) {
        const int k0 = kt << 6;
        __syncthreads();

        const float* gk = qkv + ((long)(b * SEQ + k0)) * QKV_N + NQH * HD + kvh * HD;
#pragma unroll
        for (int e = tid; e < 2048; e += 256) {
            int c = e & 63;
            int d = (e >> 6) << 2;
            float4 v = *(const float4*)(gk + (long)c * QKV_N + d);
            KsT[(d + 0) * 64 + c] = v.x;
            KsT[(d + 1) * 64 + c] = v.y;
            KsT[(d + 2) * 64 + c] = v.z;
            KsT[(d + 3) * 64 + c] = v.w;
        }
        const float* gv = gk + NKV * HD;
#pragma unroll
        for (int e = tid; e < 2048; e += 256) {
            int r = e >> 5;
            int d = (e & 31) << 2;
            *(float4*)&Vs[r * 128 + d] = *(const float4*)(gv + (long)r * QKV_N + d);
        }
        __syncthreads();

        float acc[4][4];
#pragma unroll
        for (int i = 0; i < 4; i++)
#pragma unroll
            for (int j = 0; j < 4; j++) acc[i][j] = 0.f;

#pragma unroll 8
        for (int d = 0; d < 128; d++) {
            float4 q4 = *(const float4*)&QsT[d * 64 + (ty << 2)];
            float4 k4 = *(const float4*)&KsT[d * 64 + (tx << 2)];
            float qa[4] = {q4.x, q4.y, q4.z, q4.w};
            float ka[4] = {k4.x, k4.y, k4.z, k4.w};
#pragma unroll
            for (int i = 0; i < 4; i++)
#pragma unroll
                for (int j = 0; j < 4; j++)
                    acc[i][j] = fmaf(qa[i], ka[j], acc[i][j]);
        }

        const bool diag = (kt == qt);
        float alpha[4];
#pragma unroll
        for (int i = 0; i < 4; i++) {
            const int qrow = q0 + (ty << 2) + i;
            float tmp[4];
#pragma unroll
            for (int j = 0; j < 4; j++) {
                float s = acc[i][j] * scale;
                if (diag && (k0 + (tx << 2) + j > qrow)) s = -1.0e30f;
                tmp[j] = s;
            }
            float rm = fmaxf(fmaxf(tmp[0], tmp[1]), fmaxf(tmp[2], tmp[3]));
            rm = fmaxf(rm, __shfl_xor_sync(0xffffffffu, rm, 1, 16));
            rm = fmaxf(rm, __shfl_xor_sync(0xffffffffu, rm, 2, 16));
            rm = fmaxf(rm, __shfl_xor_sync(0xffffffffu, rm, 4, 16));
            rm = fmaxf(rm, __shfl_xor_sync(0xffffffffu, rm, 8, 16));
            float m_new = fmaxf(m_prev[i], rm);
            float al = expf(m_prev[i] - m_new);
            float rs = 0.f;
#pragma unroll
            for (int j = 0; j < 4; j++) {
                float p = expf(tmp[j] - m_new);
                tmp[j] = p;
                rs += p;
            }
            rs += __shfl_xor_sync(0xffffffffu, rs, 1, 16);
            rs += __shfl_xor_sync(0xffffffffu, rs, 2, 16);
            rs += __shfl_xor_sync(0xffffffffu, rs, 4, 16);
            rs += __shfl_xor_sync(0xffffffffu, rs, 8, 16);
            l_run[i]  = l_run[i] * al + rs;
            m_prev[i] = m_new;
            alpha[i]  = al;
            *(float4*)&Ps[(((ty << 2) + i) << 6) + (tx << 2)] =
                make_float4(tmp[0], tmp[1], tmp[2], tmp[3]);
        }
        __syncthreads();

#pragma unroll
        for (int i = 0; i < 4; i++)
#pragma unroll
            for (int j = 0; j < 8; j++) o[i][j] *= alpha[i];

#pragma unroll 4
        for (int k = 0; k < 64; k++) {
            float pv[4];
#pragma unroll
            for (int i = 0; i < 4; i++) pv[i] = Ps[(((ty << 2) + i) << 6) + k];
            float4 v0 = *(const float4*)&Vs[k * 128 + (tx << 3)];
            float4 v1 = *(const float4*)&Vs[k * 128 + (tx << 3) + 4];
            float vv[8] = {v0.x, v0.y, v0.z, v0.w, v1.x, v1.y, v1.z, v1.w};
#pragma unroll
            for (int i = 0; i < 4; i++)
#pragma unroll
                for (int j = 0; j < 8; j++)
                    o[i][j] = fmaf(pv[i], vv[j], o[i][j]);
        }
    }

    // Normalize; write fp16 (GEMM2 operand A)
#pragma unroll
    for (int i = 0; i < 4; i++) {
        float inv = 1.0f / l_run[i];
        long row = (long)(b * SEQ + q0 + (ty << 2) + i);
        long off = row * HID + h * HD + (tx << 3);
        __half2* po = (__half2*)(g_attn_f16 + off);
#pragma unroll
        for (int j = 0; j < 4; j++)
            po[j] = __floats2half2_rn(o[i][2 * j] * inv, o[i][2 * j + 1] * inv);
    }
}

// ---------------------------------------------------------------------------
// Launch: convert/split -> QKV GEMM -> RoPE -> flash -> O GEMM
// ---------------------------------------------------------------------------
extern "C" void kernel_launch(void* const* d_in, const int* in_sizes, int n_in,
                              void* d_out, int out_size) {
    const int*   positions = (const int*)d_in[0];
    const float* hidden    = (const float*)d_in[1];
    const float* w_qkv     = (const float*)d_in[2];
    const float* w_o       = (const float*)d_in[3];
    float*       out       = (float*)d_out;

    static __half *hid_f16, *wqT_hi, *wqT_lo, *woT_hi, *woT_lo, *attn_f16;
    static float* qkv;
    static bool init = false;
    if (!init) {
        cudaGetSymbolAddress((void**)&hid_f16,  g_hid_f16);
        cudaGetSymbolAddress((void**)&wqT_hi,   g_wqkvT_hi);
        cudaGetSymbolAddress((void**)&wqT_lo,   g_wqkvT_lo);
        cudaGetSymbolAddress((void**)&woT_hi,   g_woT_hi);
        cudaGetSymbolAddress((void**)&woT_lo,   g_woT_lo);
        cudaGetSymbolAddress((void**)&attn_f16, g_attn_f16);
        cudaGetSymbolAddress((void**)&qkv,      g_qkv);
        cudaFuncSetAttribute(gemm_f16x2, cudaFuncAttributeMaxDynamicSharedMemorySize,
                             NSTAGE * STAGE_BYTES);
        cudaFuncSetAttribute(flash_attn, cudaFuncAttributeMaxDynamicSharedMemorySize, 114688);
        init = true;
    }

    // Convert activations (single fp16) and split weights (hi/lo fp16, [N,K])
    {
        int n4 = BS_ROWS * HID / 4;
        act_to_f16<<<(n4 + 255) / 256, 256>>>(hidden, hid_f16, n4);
    }
    split_T<<<dim3(QKV_N / 32, HID / 32), dim3(32, 32)>>>(w_qkv, wqT_hi, wqT_lo, HID, QKV_N);
    split_T<<<dim3(HID / 32, HID / 32), dim3(32, 32)>>>(w_o, woT_hi, woT_lo, HID, HID);

    // QKV projection: [4096,4096] @ [4096,6144] -> g_qkv (f32)
    gemm_f16x2<<<dim3(QKV_N / 128, BS_ROWS / 256), 512, NSTAGE * STAGE_BYTES>>>(
        hid_f16, wqT_hi, wqT_lo, qkv, QKV_N, HID);

    const int tot = BS_ROWS * (NQH + NKV) * 64;
    rope_kernel<<<(tot + 255) / 256, 256>>>(positions);

    flash_attn<<<dim3(SEQ / 64, NQH, BATCH), 256, 114688>>>();

    // Output projection: [4096,4096] @ [4096,4096] -> out
    gemm_f16x2<<<dim3(HID / 128, BS_ROWS / 256), 512, NSTAGE * STAGE_BYTES>>>(
        attn_f16, woT_hi, woT_lo, out, HID, HID);
}

// round 10
// speedup vs baseline: 1.8149x; 1.2955x over previous
#include <cuda_runtime.h>
#include <cuda_fp16.h>
#include <math.h>
#include <stdint.h>

// Problem constants
#define BATCH   4
#define SEQ     1024
#define HID     4096
#define NQH     32
#define NKV     8
#define HD      128
#define QKV_N   6144                 // (NH + 2*NKV) * HD
#define BS_ROWS 4096                 // BATCH * SEQ

// ---------------------------------------------------------------------------
// Scratch (__device__ globals). Tile-packed fp16 layouts:
//  A tensors: tiles of 256 rows x 32 k = 8192 halves (16KB), contiguous;
//             tile (mb, kt) at ((mb*(K/32)+kt)<<13) halves.
//  B tensors: tiles of [hi 128x32 | lo 128x32] = 8192 halves (16KB);
//             tile (nb, kt) at ((nb*(K/32)+kt)<<13); lo at +4096 halves.
//  In-tile:   halves offset = ((r>>3)*4 + kc)*64 + (r&7)*8 + (k&7)
// ---------------------------------------------------------------------------
__device__ float  g_qkv[(size_t)BS_ROWS * QKV_N];
__device__ __half g_hid_pk[(size_t)BS_ROWS * HID];
__device__ __half g_wqkv_pk[(size_t)QKV_N * HID * 2];     // hi+lo packed
__device__ __half g_wo_pk[(size_t)HID * HID * 2];
__device__ __half g_attn_pk[(size_t)BS_ROWS * HID];

__device__ __forceinline__ uint32_t smem_u32(const void* p) {
    uint32_t a;
    asm("{ .reg .u64 t; cvta.to.shared.u64 t, %1; cvt.u32.u64 %0, t; }" : "=r"(a) : "l"(p));
    return a;
}

#define MBAR_INIT(addr, cnt) \
    asm volatile("mbarrier.init.shared.b64 [%0], %1;" :: "r"(addr), "r"(cnt) : "memory")
#define MBAR_EXPECT_TX(addr, bytes) \
    asm volatile("mbarrier.arrive.expect_tx.shared.b64 _, [%0], %1;" \
                 :: "r"(addr), "r"(bytes) : "memory")
__device__ __forceinline__ void mbar_wait(uint32_t addr, uint32_t parity) {
    asm volatile(
        "{\n\t.reg .pred P;\n\t"
        "WL%=:\n\t"
        "mbarrier.try_wait.parity.acquire.cta.shared::cta.b64 P, [%0], %1, 0x989680;\n\t"
        "@!P bra WL%=;\n\t}"
        :: "r"(addr), "r"(parity) : "memory");
}
__device__ __forceinline__ void bulk_g2s(uint32_t dst, const void* src,
                                         uint32_t bytes, uint32_t mbar) {
    asm volatile(
        "cp.async.bulk.shared::cluster.global.mbarrier::complete_tx::bytes "
        "[%0], [%1], %2, [%3];"
        :: "r"(dst), "l"(src), "r"(bytes), "r"(mbar) : "memory");
}

// ---------------------------------------------------------------------------
// Packing kernels
// ---------------------------------------------------------------------------
// hidden f32 [row, 4096] -> packed fp16 A tiles. One 16B chunk per thread.
__global__ void act_pack(const float* __restrict__ in, __half* __restrict__ out) {
    int i = blockIdx.x * blockDim.x + threadIdx.x;   // 0 .. BS_ROWS*512-1
    if (i >= BS_ROWS * 512) return;
    int row = i >> 9;
    int k8  = i & 511;                                // 8-half chunk index
    const float4* s = (const float4*)(in + ((size_t)row << 12) + (k8 << 3));
    float4 v0 = s[0], v1 = s[1];
    __half2 h[4];
    h[0] = __floats2half2_rn(v0.x, v0.y);
    h[1] = __floats2half2_rn(v0.z, v0.w);
    h[2] = __floats2half2_rn(v1.x, v1.y);
    h[3] = __floats2half2_rn(v1.z, v1.w);
    size_t mb = row >> 8;
    int r  = row & 255;
    int kt = k8 >> 2;
    int kc = k8 & 3;
    __half* d = out + (((mb << 7) + kt) << 13)
              + (((((r >> 3) << 2) + kc) << 6) + ((r & 7) << 3));
    *(uint4*)d = *(uint4*)h;
}

// W[Kdim, Ndim] f32 -> packed hi/lo B tiles [Ndim/128 x Kdim/32]
__global__ void split_T_pack(const float* __restrict__ W,
                             __half* __restrict__ pk, int Kdim, int Ndim) {
    __shared__ float t[32][33];
    int n0 = blockIdx.x * 32, k0 = blockIdx.y * 32;
    t[threadIdx.y][threadIdx.x] = W[(long)(k0 + threadIdx.y) * Ndim + n0 + threadIdx.x];
    __syncthreads();
    float x = t[threadIdx.x][threadIdx.y];
    int n = n0 + threadIdx.y;
    int k = k0 + threadIdx.x;
    int nb = n >> 7, r = n & 127;
    int kt = k >> 5, kc = (k >> 3) & 3, kin = k & 7;
    size_t base = ((size_t)(nb * (Kdim >> 5) + kt)) << 13;
    int off = ((((r >> 3) << 2) + kc) << 6) + ((r & 7) << 3) + kin;
    __half h = __float2half(x);
    pk[base + off]        = h;                                   // hi
    pk[base + 4096 + off] = __float2half(x - __half2float(h));   // lo
}

// ---------------------------------------------------------------------------
// HMMA GEMM: C[M,N] = A[M,K] @ Bt[N,K]^T, fp16 2-pass (A single, B hi/lo).
// CTA 256x128 (MxN), BK=32, 512 threads = 16 warps (4Mx4N), warp tile 64x32.
// Loads: ONE cp.async.bulk per operand per K-tile (TMA), 4-stage mbarrier ring.
// ---------------------------------------------------------------------------
#define STAGE_BYTES 32768
#define NSTAGE 4
#define SMEM_TILES 1024       // stage buffers start here; mbarriers at 0..31
#define A_OFF    0            // 16 KB
#define B_HI_OFF 16384        // 8 KB
#define B_LO_OFF 24576        // 8 KB
#define GEMM_SMEM (SMEM_TILES + NSTAGE * STAGE_BYTES)

#define LDSM4(R, ADDR) \
    asm volatile("ldmatrix.sync.aligned.m8n8.x4.shared.b16 {%0,%1,%2,%3}, [%4];" \
                 : "=r"((R)[0]), "=r"((R)[1]), "=r"((R)[2]), "=r"((R)[3]) : "r"(ADDR))

#define MMA_F16(ACC, A, B) \
    asm volatile("mma.sync.aligned.m16n8k16.row.col.f32.f16.f16.f32 " \
                 "{%0,%1,%2,%3}, {%4,%5,%6,%7}, {%8,%9}, {%0,%1,%2,%3};" \
                 : "+f"((ACC)[0]), "+f"((ACC)[1]), "+f"((ACC)[2]), "+f"((ACC)[3]) \
                 : "r"((A)[0]), "r"((A)[1]), "r"((A)[2]), "r"((A)[3]), \
                   "r"((B)[0]), "r"((B)[1]))

__global__ __launch_bounds__(512, 1)
void gemm_f16x2(const __half* __restrict__ Apk, const __half* __restrict__ Bpk,
                float* __restrict__ C, int N, int K)
{
    extern __shared__ char smx[];
    const uint32_t s0 = smem_u32(smx);
    const int tid  = threadIdx.x;
    const int wid  = tid >> 5;
    const int lane = tid & 31;
    const int wm   = wid >> 2;        // 0..3  (M, 64 rows each)
    const int wn   = wid & 3;         // 0..3  (N, 32 cols each)
    const int sel  = lane >> 3;
    const int rowin = lane & 7;
    const int g    = lane >> 2;
    const int tq   = lane & 3;
    const long bm = (long)blockIdx.y * 256;
    const long bn = (long)blockIdx.x * 128;
    const int NKT = K >> 5;           // 128

    const __half* gA = Apk + ((size_t)(blockIdx.y * NKT) << 13);
    const __half* gB = Bpk + ((size_t)(blockIdx.x * NKT) << 13);

    if (tid == 0) {
#pragma unroll
        for (int s = 0; s < NSTAGE; s++) MBAR_INIT(s0 + s * 8, 1);
    }
    __syncthreads();

    // Prologue: issue tiles 0..NSTAGE-2 into buffers 0..NSTAGE-2
    if (tid == 0) {
#pragma unroll
        for (int p = 0; p < NSTAGE - 1; p++) {
            uint32_t mb = s0 + p * 8;
            uint32_t db = s0 + SMEM_TILES + p * STAGE_BYTES;
            MBAR_EXPECT_TX(mb, 2 * 16384);
            bulk_g2s(db + A_OFF,    gA + ((size_t)p << 13), 16384, mb);
            bulk_g2s(db + B_HI_OFF, gB + ((size_t)p << 13), 16384, mb);
        }
    }

    float acc[4][4][4];
#pragma unroll
    for (int i = 0; i < 4; i++)
#pragma unroll
        for (int j = 0; j < 4; j++)
#pragma unroll
            for (int k = 0; k < 4; k++) acc[i][j][k] = 0.f;

    for (int t = 0; t < NKT; t++) {
        const int s = t & (NSTAGE - 1);
        // Issue tile t+NSTAGE-1 into buffer (t-1)&3 (freed by prev iteration's sync)
        if (tid == 0 && t + NSTAGE - 1 < NKT) {
            const int tp = t + NSTAGE - 1;
            const int sp = tp & (NSTAGE - 1);
            uint32_t mb = s0 + sp * 8;
            uint32_t db = s0 + SMEM_TILES + sp * STAGE_BYTES;
            MBAR_EXPECT_TX(mb, 2 * 16384);
            bulk_g2s(db + A_OFF,    gA + ((size_t)tp << 13), 16384, mb);
            bulk_g2s(db + B_HI_OFF, gB + ((size_t)tp << 13), 16384, mb);
        }
        mbar_wait(s0 + s * 8, (t >> 2) & 1);

        const uint32_t sb = s0 + SMEM_TILES + s * STAGE_BYTES;
#pragma unroll
        for (int ks = 0; ks < 2; ks++) {
            uint32_t a[4][4], bh[4][2], bl[4][2];
#pragma unroll
            for (int mt = 0; mt < 4; mt++) {
                int rm = wm * 8 + 2 * mt + (sel & 1);
                int km = 2 * ks + (sel >> 1);
                uint32_t off = (uint32_t)(((rm << 2) + km) * 128 + rowin * 16);
                LDSM4(a[mt], sb + A_OFF + off);
            }
#pragma unroll
            for (int bt = 0; bt < 2; bt++) {
                int nm = wn * 4 + 2 * bt + (sel >> 1);
                int km = 2 * ks + (sel & 1);
                uint32_t off = (uint32_t)(((nm << 2) + km) * 128 + rowin * 16);
                uint32_t r4[4];
                LDSM4(r4, sb + B_HI_OFF + off);
                bh[2 * bt][0] = r4[0]; bh[2 * bt][1] = r4[1];
                bh[2 * bt + 1][0] = r4[2]; bh[2 * bt + 1][1] = r4[3];
                LDSM4(r4, sb + B_LO_OFF + off);
                bl[2 * bt][0] = r4[0]; bl[2 * bt][1] = r4[1];
                bl[2 * bt + 1][0] = r4[2]; bl[2 * bt + 1][1] = r4[3];
            }
#pragma unroll
            for (int mt = 0; mt < 4; mt++)
#pragma unroll
                for (int nt = 0; nt < 4; nt++) {
                    MMA_F16(acc[mt][nt], a[mt], bh[nt]);
                    MMA_F16(acc[mt][nt], a[mt], bl[nt]);
                }
        }
        __syncthreads();   // all warps done with buffer s before its reuse
    }

    // Epilogue: direct global stores
#pragma unroll
    for (int mt = 0; mt < 4; mt++) {
        long row0 = bm + wm * 64 + mt * 16 + g;
#pragma unroll
        for (int nt = 0; nt < 4; nt++) {
            long col = bn + wn * 32 + nt * 8 + tq * 2;
            *(float2*)&C[row0 * N + col]       = make_float2(acc[mt][nt][0], acc[mt][nt][1]);
            *(float2*)&C[(row0 + 8) * N + col] = make_float2(acc[mt][nt][2], acc[mt][nt][3]);
        }
    }
}

// ---------------------------------------------------------------------------
// RoPE (NeoX, full head_dim) in-place on q|k of g_qkv
// ---------------------------------------------------------------------------
__global__ void rope_kernel(const int* __restrict__ pos) {
    const int TOT = BS_ROWS * (NQH + NKV) * 64;
    int idx = blockIdx.x * blockDim.x + threadIdx.x;
    if (idx >= TOT) return;
    int i   = idx & 63;
    int h   = (idx >> 6) % (NQH + NKV);
    int row = idx / (64 * (NQH + NKV));
    int p   = pos[row];

    float* ptr = g_qkv + (long)row * QKV_N + (long)h * HD;
    float inv = expf(-(float)i * 0.14391156831212787f);   // ln(10000)/64
    float ang = (float)p * inv;
    float sn, cs;
    sincosf(ang, &sn, &cs);
    float x1 = ptr[i], x2 = ptr[i + 64];
    ptr[i]      = x1 * cs - x2 * sn;
    ptr[i + 64] = x2 * cs + x1 * sn;
}

// ---------------------------------------------------------------------------
// Flash attention (fp32, causal, GQA rep=4); emits packed fp16 for GEMM2.
// ---------------------------------------------------------------------------
__global__ __launch_bounds__(256, 1)
void flash_attn() {
    extern __shared__ float smf[];
    float* QsT = smf;             // [128][64]
    float* KsT = smf + 8192;      // [128][64]
    float* Vs  = smf + 16384;     // [64][128]
    float* Ps  = smf + 24576;     // [64][64]

    const float* qkv = g_qkv;
    const int tid = threadIdx.x;
    const int qt  = blockIdx.x;
    const int h   = blockIdx.y;
    const int b   = blockIdx.z;
    const int kvh = h >> 2;
    const int q0  = qt << 6;
    const int ty  = tid >> 4;
    const int tx  = tid & 15;

    const float* gq = qkv + ((long)(b * SEQ + q0)) * QKV_N + h * HD;
#pragma unroll
    for (int e = tid; e < 2048; e += 256) {
        int c = e & 63;
        int d = (e >> 6) << 2;
        float4 v = *(const float4*)(gq + (long)c * QKV_N + d);
        QsT[(d + 0) * 64 + c] = v.x;
        QsT[(d + 1) * 64 + c] = v.y;
        QsT[(d + 2) * 64 + c] = v.z;
        QsT[(d + 3) * 64 + c] = v.w;
    }

    float m_prev[4], l_run[4], o[4][8];
#pragma unroll
    for (int i = 0; i < 4; i++) {
        m_prev[i] = -3.0e38f;
        l_run[i]  = 0.f;
#pragma unroll
        for (int j = 0; j < 8; j++) o[i][j] = 0.f;
    }

    const float scale = 0.08838834764831845f;

    for (int kt = 0; kt <= qt; kt++) {
        const int k0 = kt << 6;
        __syncthreads();

        const float* gk = qkv + ((long)(b * SEQ + k0)) * QKV_N + NQH * HD + kvh * HD;
#pragma unroll
        for (int e = tid; e < 2048; e += 256) {
            int c = e & 63;
            int d = (e >> 6) << 2;
            float4 v = *(const float4*)(gk + (long)c * QKV_N + d);
            KsT[(d + 0) * 64 + c] = v.x;
            KsT[(d + 1) * 64 + c] = v.y;
            KsT[(d + 2) * 64 + c] = v.z;
            KsT[(d + 3) * 64 + c] = v.w;
        }
        const float* gv = gk + NKV * HD;
#pragma unroll
        for (int e = tid; e < 2048; e += 256) {
            int r = e >> 5;
            int d = (e & 31) << 2;
            *(float4*)&Vs[r * 128 + d] = *(const float4*)(gv + (long)r * QKV_N + d);
        }
        __syncthreads();

        float acc[4][4];
#pragma unroll
        for (int i = 0; i < 4; i++)
#pragma unroll
            for (int j = 0; j < 4; j++) acc[i][j] = 0.f;

#pragma unroll 8
        for (int d = 0; d < 128; d++) {
            float4 q4 = *(const float4*)&QsT[d * 64 + (ty << 2)];
            float4 k4 = *(const float4*)&KsT[d * 64 + (tx << 2)];
            float qa[4] = {q4.x, q4.y, q4.z, q4.w};
            float ka[4] = {k4.x, k4.y, k4.z, k4.w};
#pragma unroll
            for (int i = 0; i < 4; i++)
#pragma unroll
                for (int j = 0; j < 4; j++)
                    acc[i][j] = fmaf(qa[i], ka[j], acc[i][j]);
        }

        const bool diag = (kt == qt);
        float alpha[4];
#pragma unroll
        for (int i = 0; i < 4; i++) {
            const int qrow = q0 + (ty << 2) + i;
            float tmp[4];
#pragma unroll
            for (int j = 0; j < 4; j++) {
                float s = acc[i][j] * scale;
                if (diag && (k0 + (tx << 2) + j > qrow)) s = -1.0e30f;
                tmp[j] = s;
            }
            float rm = fmaxf(fmaxf(tmp[0], tmp[1]), fmaxf(tmp[2], tmp[3]));
            rm = fmaxf(rm, __shfl_xor_sync(0xffffffffu, rm, 1, 16));
            rm = fmaxf(rm, __shfl_xor_sync(0xffffffffu, rm, 2, 16));
            rm = fmaxf(rm, __shfl_xor_sync(0xffffffffu, rm, 4, 16));
            rm = fmaxf(rm, __shfl_xor_sync(0xffffffffu, rm, 8, 16));
            float m_new = fmaxf(m_prev[i], rm);
            float al = expf(m_prev[i] - m_new);
            float rs = 0.f;
#pragma unroll
            for (int j = 0; j < 4; j++) {
                float p = expf(tmp[j] - m_new);
                tmp[j] = p;
                rs += p;
            }
            rs += __shfl_xor_sync(0xffffffffu, rs, 1, 16);
            rs += __shfl_xor_sync(0xffffffffu, rs, 2, 16);
            rs += __shfl_xor_sync(0xffffffffu, rs, 4, 16);
            rs += __shfl_xor_sync(0xffffffffu, rs, 8, 16);
            l_run[i]  = l_run[i] * al + rs;
            m_prev[i] = m_new;
            alpha[i]  = al;
            *(float4*)&Ps[(((ty << 2) + i) << 6) + (tx << 2)] =
                make_float4(tmp[0], tmp[1], tmp[2], tmp[3]);
        }
        __syncthreads();

#pragma unroll
        for (int i = 0; i < 4; i++)
#pragma unroll
            for (int j = 0; j < 8; j++) o[i][j] *= alpha[i];

#pragma unroll 4
        for (int k = 0; k < 64; k++) {
            float pv[4];
#pragma unroll
            for (int i = 0; i < 4; i++) pv[i] = Ps[(((ty << 2) + i) << 6) + k];
            float4 v0 = *(const float4*)&Vs[k * 128 + (tx << 3)];
            float4 v1 = *(const float4*)&Vs[k * 128 + (tx << 3) + 4];
            float vv[8] = {v0.x, v0.y, v0.z, v0.w, v1.x, v1.y, v1.z, v1.w};
#pragma unroll
            for (int i = 0; i < 4; i++)
#pragma unroll
                for (int j = 0; j < 8; j++)
                    o[i][j] = fmaf(pv[i], vv[j], o[i][j]);
        }
    }

    // Normalize; write packed fp16 (GEMM2 operand A): chunk (row, k8=h*16+tx)
#pragma unroll
    for (int i = 0; i < 4; i++) {
        float inv = 1.0f / l_run[i];
        int row = b * SEQ + q0 + (ty << 2) + i;
        int k8  = h * 16 + tx;
        size_t mb = row >> 8;
        int r  = row & 255;
        int kt2 = k8 >> 2;
        int kc = k8 & 3;
        __half* d = g_attn_pk + (((mb << 7) + kt2) << 13)
                  + (((((r >> 3) << 2) + kc) << 6) + ((r & 7) << 3));
        __half2 hv[4];
#pragma unroll
        for (int j = 0; j < 4; j++)
            hv[j] = __floats2half2_rn(o[i][2 * j] * inv, o[i][2 * j + 1] * inv);
        *(uint4*)d = *(uint4*)hv;
    }
}

// ---------------------------------------------------------------------------
// Launch: pack/split -> QKV GEMM -> RoPE -> flash -> O GEMM
// ---------------------------------------------------------------------------
extern "C" void kernel_launch(void* const* d_in, const int* in_sizes, int n_in,
                              void* d_out, int out_size) {
    const int*   positions = (const int*)d_in[0];
    const float* hidden    = (const float*)d_in[1];
    const float* w_qkv     = (const float*)d_in[2];
    const float* w_o       = (const float*)d_in[3];
    float*       out       = (float*)d_out;

    static __half *hid_pk, *wqkv_pk, *wo_pk, *attn_pk;
    static float* qkv;
    static bool init = false;
    if (!init) {
        cudaGetSymbolAddress((void**)&hid_pk,  g_hid_pk);
        cudaGetSymbolAddress((void**)&wqkv_pk, g_wqkv_pk);
        cudaGetSymbolAddress((void**)&wo_pk,   g_wo_pk);
        cudaGetSymbolAddress((void**)&attn_pk, g_attn_pk);
        cudaGetSymbolAddress((void**)&qkv,     g_qkv);
        cudaFuncSetAttribute(gemm_f16x2, cudaFuncAttributeMaxDynamicSharedMemorySize,
                             GEMM_SMEM);
        cudaFuncSetAttribute(flash_attn, cudaFuncAttributeMaxDynamicSharedMemorySize, 114688);
        init = true;
    }

    // Pack activations; split+pack weights (hi/lo fp16, [N,K] tiles)
    act_pack<<<(BS_ROWS * 512 + 255) / 256, 256>>>(hidden, hid_pk);
    split_T_pack<<<dim3(QKV_N / 32, HID / 32), dim3(32, 32)>>>(w_qkv, wqkv_pk, HID, QKV_N);
    split_T_pack<<<dim3(HID / 32, HID / 32), dim3(32, 32)>>>(w_o, wo_pk, HID, HID);

    // QKV projection: [4096,4096] @ [4096,6144] -> g_qkv (f32)
    gemm_f16x2<<<dim3(QKV_N / 128, BS_ROWS / 256), 512, GEMM_SMEM>>>(
        hid_pk, wqkv_pk, qkv, QKV_N, HID);

    const int tot = BS_ROWS * (NQH + NKV) * 64;
    rope_kernel<<<(tot + 255) / 256, 256>>>(positions);

    flash_attn<<<dim3(SEQ / 64, NQH, BATCH), 256, 114688>>>();

    // Output projection: [4096,4096] @ [4096,4096] -> out
    gemm_f16x2<<<dim3(HID / 128, BS_ROWS / 256), 512, GEMM_SMEM>>>(
        attn_pk, wo_pk, out, HID, HID);
}

// round 11
// speedup vs baseline: 2.8747x; 1.5839x over previous
#include <cuda_runtime.h>
#include <cuda_fp16.h>
#include <math.h>
#include <stdint.h>

// Problem constants
#define BATCH   4
#define SEQ     1024
#define HID     4096
#define NQH     32
#define NKV     8
#define HD      128
#define QKV_N   6144
#define BS_ROWS 4096

// ---------------------------------------------------------------------------
// Scratch. Tile-packed fp16 layouts (8x8-matrix contiguous, 128B per matrix):
//  elem (r, c) in a tile with nc8 col-blocks: matrix (r>>3)*nc8 + (c>>3),
//  half offset = matrix*64 + (r&7)*8 + (c&7).
// ---------------------------------------------------------------------------
__device__ float  g_qkv[(size_t)BS_ROWS * QKV_N];
__device__ __half g_hid_pk[(size_t)BS_ROWS * HID];
__device__ __half g_wqkv_pk[(size_t)QKV_N * HID * 2];
__device__ __half g_wo_pk[(size_t)HID * HID * 2];
__device__ __half g_attn_pk[(size_t)BS_ROWS * HID];
__device__ __half g_q16[(size_t)BATCH * NQH * 16 * 8192];   // [b][h][qt][64x128 pk]
__device__ __half g_k16[(size_t)BATCH * NKV * 16 * 8192];   // [b][kv][st][64x128 pk]
__device__ __half g_vT16[(size_t)BATCH * NKV * 16 * 8192];  // [b][kv][st][128x64 pk]

__device__ __forceinline__ uint32_t smem_u32(const void* p) {
    uint32_t a;
    asm("{ .reg .u64 t; cvta.to.shared.u64 t, %1; cvt.u32.u64 %0, t; }" : "=r"(a) : "l"(p));
    return a;
}
__device__ __forceinline__ uint32_t f22u(float a, float b) {
    __half2 h = __floats2half2_rn(a, b);
    return *(uint32_t*)&h;
}

#define MBAR_INIT(addr, cnt) \
    asm volatile("mbarrier.init.shared.b64 [%0], %1;" :: "r"(addr), "r"(cnt) : "memory")
#define MBAR_EXPECT_TX(addr, bytes) \
    asm volatile("mbarrier.arrive.expect_tx.shared.b64 _, [%0], %1;" \
                 :: "r"(addr), "r"(bytes) : "memory")
__device__ __forceinline__ void mbar_wait(uint32_t addr, uint32_t parity) {
    asm volatile(
        "{\n\t.reg .pred P;\n\t"
        "WL%=:\n\t"
        "mbarrier.try_wait.parity.acquire.cta.shared::cta.b64 P, [%0], %1, 0x989680;\n\t"
        "@!P bra WL%=;\n\t}"
        :: "r"(addr), "r"(parity) : "memory");
}
__device__ __forceinline__ void bulk_g2s(uint32_t dst, const void* src,
                                         uint32_t bytes, uint32_t mbar) {
    asm volatile(
        "cp.async.bulk.shared::cluster.global.mbarrier::complete_tx::bytes "
        "[%0], [%1], %2, [%3];"
        :: "r"(dst), "l"(src), "r"(bytes), "r"(mbar) : "memory");
}

#define LDSM4(R, ADDR) \
    asm volatile("ldmatrix.sync.aligned.m8n8.x4.shared.b16 {%0,%1,%2,%3}, [%4];" \
                 : "=r"((R)[0]), "=r"((R)[1]), "=r"((R)[2]), "=r"((R)[3]) : "r"(ADDR))
#define MMA_F16(ACC, A, B) \
    asm volatile("mma.sync.aligned.m16n8k16.row.col.f32.f16.f16.f32 " \
                 "{%0,%1,%2,%3}, {%4,%5,%6,%7}, {%8,%9}, {%0,%1,%2,%3};" \
                 : "+f"((ACC)[0]), "+f"((ACC)[1]), "+f"((ACC)[2]), "+f"((ACC)[3]) \
                 : "r"((A)[0]), "r"((A)[1]), "r"((A)[2]), "r"((A)[3]), \
                   "r"((B)[0]), "r"((B)[1]))

// ---------------------------------------------------------------------------
// Packing kernels
// ---------------------------------------------------------------------------
__global__ void act_pack(const float* __restrict__ in, __half* __restrict__ out) {
    int i = blockIdx.x * blockDim.x + threadIdx.x;
    if (i >= BS_ROWS * 512) return;
    int row = i >> 9;
    int k8  = i & 511;
    const float4* s = (const float4*)(in + ((size_t)row << 12) + (k8 << 3));
    float4 v0 = s[0], v1 = s[1];
    __half2 h[4];
    h[0] = __floats2half2_rn(v0.x, v0.y);
    h[1] = __floats2half2_rn(v0.z, v0.w);
    h[2] = __floats2half2_rn(v1.x, v1.y);
    h[3] = __floats2half2_rn(v1.z, v1.w);
    size_t mb = row >> 8;
    int r = row & 255, kt = k8 >> 2, kc = k8 & 3;
    __half* d = out + (((mb << 7) + kt) << 13)
              + (((((r >> 3) << 2) + kc) << 6) + ((r & 7) << 3));
    *(uint4*)d = *(uint4*)h;
}

__global__ void split_T_pack(const float* __restrict__ W,
                             __half* __restrict__ pk, int Kdim, int Ndim) {
    __shared__ float t[32][33];
    int n0 = blockIdx.x * 32, k0 = blockIdx.y * 32;
    t[threadIdx.y][threadIdx.x] = W[(long)(k0 + threadIdx.y) * Ndim + n0 + threadIdx.x];
    __syncthreads();
    float x = t[threadIdx.x][threadIdx.y];
    int n = n0 + threadIdx.y;
    int k = k0 + threadIdx.x;
    int nb = n >> 7, r = n & 127;
    int kt = k >> 5, kc = (k >> 3) & 3, kin = k & 7;
    size_t base = ((size_t)(nb * (Kdim >> 5) + kt)) << 13;
    int off = ((((r >> 3) << 2) + kc) << 6) + ((r & 7) << 3) + kin;
    __half h = __float2half(x);
    pk[base + off]        = h;
    pk[base + 4096 + off] = __float2half(x - __half2float(h));
}

// RoPE + pack q/k as fp16 tiles. Thread per (row, head 0..39, lane): 2 pairs.
__global__ void qk_pack(const int* __restrict__ pos) {
    int idx = blockIdx.x * blockDim.x + threadIdx.x;
    if (idx >= BS_ROWS * 40 * 32) return;
    int lane = idx & 31;
    int h    = (idx >> 5) % 40;
    int row  = idx / (40 * 32);
    int p    = pos[row];
    const float* src = g_qkv + (long)row * QKV_N + h * HD;
    int i0 = 2 * lane;
    float x1a = src[i0], x1b = src[i0 + 1], x2a = src[i0 + 64], x2b = src[i0 + 65];
    float sa, ca, sb, cb;
    sincosf((float)p * expf(-(float)i0 * 0.14391156831212787f), &sa, &ca);
    sincosf((float)p * expf(-(float)(i0 + 1) * 0.14391156831212787f), &sb, &cb);
    float y1a = x1a * ca - x2a * sa, y1b = x1b * cb - x2b * sb;
    float y2a = x2a * ca + x1a * sa, y2b = x2b * cb + x1b * sb;
    int s = row & (SEQ - 1), b = row >> 10;
    int st = s >> 6, r = s & 63;
    __half* base = (h < NQH)
        ? g_q16 + ((size_t)((b * NQH + h) * 16 + st) << 13)
        : g_k16 + ((size_t)((b * NKV + (h - NQH)) * 16 + st) << 13);
    int roff = ((r >> 3) << 10) + ((r & 7) << 3);        // (r>>3)*16*64 + (r&7)*8
    *(__half2*)(base + roff + ((i0 >> 3) << 6) + (i0 & 7))              = __floats2half2_rn(y1a, y1b);
    int c2 = i0 + 64;
    *(__half2*)(base + roff + ((c2 >> 3) << 6) + (c2 & 7))              = __floats2half2_rn(y2a, y2b);
}

// V f32 [s][d] -> V^T fp16 packed [d(128) x k(64)] tiles. Block per (st, kv, b).
__global__ __launch_bounds__(256) void v_pack() {
    __shared__ float vt[64][129];
    int st = blockIdx.x, kvh = blockIdx.y, b = blockIdx.z;
    int tid = threadIdx.x;
    const float* src = g_qkv + ((long)(b * SEQ + st * 64)) * QKV_N + (NQH + NKV) * HD + kvh * HD;
    for (int e = tid; e < 64 * 32; e += 256) {
        int r = e >> 5, d4 = (e & 31) << 2;
        float4 v = *(const float4*)(src + (long)r * QKV_N + d4);
        vt[r][d4] = v.x; vt[r][d4 + 1] = v.y; vt[r][d4 + 2] = v.z; vt[r][d4 + 3] = v.w;
    }
    __syncthreads();
    __half* dst = g_vT16 + ((size_t)((b * NKV + kvh) * 16 + st) << 13);
    for (int e = tid; e < 1024; e += 256) {
        int m = e >> 3, rr = e & 7;
        int dr = ((m >> 3) << 3) + rr;     // d row
        int c0 = (m & 7) << 3;             // k col base
        __half2 hv[4];
#pragma unroll
        for (int j = 0; j < 4; j++)
            hv[j] = __floats2half2_rn(vt[c0 + 2 * j][dr], vt[c0 + 2 * j + 1][dr]);
        *(uint4*)(dst + (m << 6) + (rr << 3)) = *(uint4*)hv;
    }
}

// ---------------------------------------------------------------------------
// HMMA GEMM (unchanged from round 10)
// ---------------------------------------------------------------------------
#define STAGE_BYTES 32768
#define NSTAGE 4
#define SMEM_TILES 1024
#define A_OFF    0
#define B_HI_OFF 16384
#define B_LO_OFF 24576
#define GEMM_SMEM (SMEM_TILES + NSTAGE * STAGE_BYTES)

__global__ __launch_bounds__(512, 1)
void gemm_f16x2(const __half* __restrict__ Apk, const __half* __restrict__ Bpk,
                float* __restrict__ C, int N, int K)
{
    extern __shared__ char smx[];
    const uint32_t s0 = smem_u32(smx);
    const int tid  = threadIdx.x;
    const int wid  = tid >> 5;
    const int lane = tid & 31;
    const int wm   = wid >> 2;
    const int wn   = wid & 3;
    const int sel  = lane >> 3;
    const int rowin = lane & 7;
    const int g    = lane >> 2;
    const int tq   = lane & 3;
    const long bm = (long)blockIdx.y * 256;
    const long bn = (long)blockIdx.x * 128;
    const int NKT = K >> 5;

    const __half* gA = Apk + ((size_t)(blockIdx.y * NKT) << 13);
    const __half* gB = Bpk + ((size_t)(blockIdx.x * NKT) << 13);

    if (tid == 0) {
#pragma unroll
        for (int s = 0; s < NSTAGE; s++) MBAR_INIT(s0 + s * 8, 1);
    }
    __syncthreads();

    if (tid == 0) {
#pragma unroll
        for (int p = 0; p < NSTAGE - 1; p++) {
            uint32_t mb = s0 + p * 8;
            uint32_t db = s0 + SMEM_TILES + p * STAGE_BYTES;
            MBAR_EXPECT_TX(mb, 2 * 16384);
            bulk_g2s(db + A_OFF,    gA + ((size_t)p << 13), 16384, mb);
            bulk_g2s(db + B_HI_OFF, gB + ((size_t)p << 13), 16384, mb);
        }
    }

    float acc[4][4][4];
#pragma unroll
    for (int i = 0; i < 4; i++)
#pragma unroll
        for (int j = 0; j < 4; j++)
#pragma unroll
            for (int k = 0; k < 4; k++) acc[i][j][k] = 0.f;

    for (int t = 0; t < NKT; t++) {
        const int s = t & (NSTAGE - 1);
        if (tid == 0 && t + NSTAGE - 1 < NKT) {
            const int tp = t + NSTAGE - 1;
            const int sp = tp & (NSTAGE - 1);
            uint32_t mb = s0 + sp * 8;
            uint32_t db = s0 + SMEM_TILES + sp * STAGE_BYTES;
            MBAR_EXPECT_TX(mb, 2 * 16384);
            bulk_g2s(db + A_OFF,    gA + ((size_t)tp << 13), 16384, mb);
            bulk_g2s(db + B_HI_OFF, gB + ((size_t)tp << 13), 16384, mb);
        }
        mbar_wait(s0 + s * 8, (t >> 2) & 1);

        const uint32_t sb = s0 + SMEM_TILES + s * STAGE_BYTES;
#pragma unroll
        for (int ks = 0; ks < 2; ks++) {
            uint32_t a[4][4], bh[4][2], bl[4][2];
#pragma unroll
            for (int mt = 0; mt < 4; mt++) {
                int rm = wm * 8 + 2 * mt + (sel & 1);
                int km = 2 * ks + (sel >> 1);
                uint32_t off = (uint32_t)(((rm << 2) + km) * 128 + rowin * 16);
                LDSM4(a[mt], sb + A_OFF + off);
            }
#pragma unroll
            for (int bt = 0; bt < 2; bt++) {
                int nm = wn * 4 + 2 * bt + (sel >> 1);
                int km = 2 * ks + (sel & 1);
                uint32_t off = (uint32_t)(((nm << 2) + km) * 128 + rowin * 16);
                uint32_t r4[4];
                LDSM4(r4, sb + B_HI_OFF + off);
                bh[2 * bt][0] = r4[0]; bh[2 * bt][1] = r4[1];
                bh[2 * bt + 1][0] = r4[2]; bh[2 * bt + 1][1] = r4[3];
                LDSM4(r4, sb + B_LO_OFF + off);
                bl[2 * bt][0] = r4[0]; bl[2 * bt][1] = r4[1];
                bl[2 * bt + 1][0] = r4[2]; bl[2 * bt + 1][1] = r4[3];
            }
#pragma unroll
            for (int mt = 0; mt < 4; mt++)
#pragma unroll
                for (int nt = 0; nt < 4; nt++) {
                    MMA_F16(acc[mt][nt], a[mt], bh[nt]);
                    MMA_F16(acc[mt][nt], a[mt], bl[nt]);
                }
        }
        __syncthreads();
    }

#pragma unroll
    for (int mt = 0; mt < 4; mt++) {
        long row0 = bm + wm * 64 + mt * 16 + g;
#pragma unroll
        for (int nt = 0; nt < 4; nt++) {
            long col = bn + wn * 32 + nt * 8 + tq * 2;
            *(float2*)&C[row0 * N + col]       = make_float2(acc[mt][nt][0], acc[mt][nt][1]);
            *(float2*)&C[(row0 + 8) * N + col] = make_float2(acc[mt][nt][2], acc[mt][nt][3]);
        }
    }
}

// ---------------------------------------------------------------------------
// Flash attention with mma.sync (FA2-style). 128 threads, BQ=BK=64.
// ---------------------------------------------------------------------------
#define FQ_OFF 1024
#define FK_OFF (1024 + 16384)
#define FV_OFF (1024 + 16384 + 16384)
#define FSTAGE 32768
#define FLASH_SMEM (1024 + 16384 + 2 * FSTAGE)

__global__ __launch_bounds__(128, 2) void flash_mma() {
    extern __shared__ char smf[];
    const uint32_t s0 = smem_u32(smf);
    const int tid  = threadIdx.x;
    const int warp = tid >> 5;
    const int lane = tid & 31;
    const int g    = lane >> 2;
    const int tq   = lane & 3;
    const int sel  = lane >> 3;
    const int rowin = lane & 7;
    const int qt = blockIdx.x, h = blockIdx.y, b = blockIdx.z;
    const int kvh = h >> 2;

    const __half* gQ = g_q16 + ((size_t)((b * NQH + h) * 16 + qt) << 13);
    const __half* gK = g_k16 + ((size_t)((b * NKV + kvh) * 16) << 13);
    const __half* gV = g_vT16 + ((size_t)((b * NKV + kvh) * 16) << 13);

    if (tid == 0) { MBAR_INIT(s0, 1); MBAR_INIT(s0 + 8, 1); }
    __syncthreads();
    const int NT = qt + 1;
    if (tid == 0) {
        MBAR_EXPECT_TX(s0, 3 * 16384);
        bulk_g2s(s0 + FQ_OFF, gQ, 16384, s0);
        bulk_g2s(s0 + FK_OFF, gK, 16384, s0);
        bulk_g2s(s0 + FV_OFF, gV, 16384, s0);
        if (NT > 1) {
            MBAR_EXPECT_TX(s0 + 8, 2 * 16384);
            bulk_g2s(s0 + FK_OFF + FSTAGE, gK + 8192, 16384, s0 + 8);
            bulk_g2s(s0 + FV_OFF + FSTAGE, gV + 8192, 16384, s0 + 8);
        }
    }

    float oacc[16][4];
#pragma unroll
    for (int i = 0; i < 16; i++)
#pragma unroll
        for (int j = 0; j < 4; j++) oacc[i][j] = 0.f;
    float m0 = -3.0e38f, m1 = -3.0e38f, l0 = 0.f, l1 = 0.f;
    const float scale = 0.08838834764831845f;

    for (int t = 0; t < NT; t++) {
        const int s = t & 1;
        mbar_wait(s0 + s * 8, (t >> 1) & 1);
        const uint32_t Qb = s0 + FQ_OFF;
        const uint32_t Kb = s0 + FK_OFF + s * FSTAGE;
        const uint32_t Vb = s0 + FV_OFF + s * FSTAGE;

        // S = Q K^T   (c-frags: rows g/g+8 of warp*16 block, 8 n8-tiles)
        float sacc[8][4];
#pragma unroll
        for (int i = 0; i < 8; i++)
#pragma unroll
            for (int j = 0; j < 4; j++) sacc[i][j] = 0.f;

#pragma unroll
        for (int ks = 0; ks < 8; ks++) {
            uint32_t qa[4];
            {
                int rm = warp * 2 + (sel & 1);
                int km = 2 * ks + (sel >> 1);
                LDSM4(qa, Qb + (uint32_t)(((rm << 4) + km) * 128 + rowin * 16));
            }
            uint32_t kb[8][2];
#pragma unroll
            for (int bt = 0; bt < 4; bt++) {
                int nm = 2 * bt + (sel >> 1);
                int km = 2 * ks + (sel & 1);
                uint32_t r4[4];
                LDSM4(r4, Kb + (uint32_t)(((nm << 4) + km) * 128 + rowin * 16));
                kb[2 * bt][0] = r4[0]; kb[2 * bt][1] = r4[1];
                kb[2 * bt + 1][0] = r4[2]; kb[2 * bt + 1][1] = r4[3];
            }
#pragma unroll
            for (int nt = 0; nt < 8; nt++) MMA_F16(sacc[nt], qa, kb[nt]);
        }

        // scale + causal mask (diag tile only)
        const bool diag = (t == qt);
#pragma unroll
        for (int nt = 0; nt < 8; nt++) {
#pragma unroll
            for (int c = 0; c < 4; c++) {
                float v = sacc[nt][c] * scale;
                if (diag) {
                    int kcol = nt * 8 + 2 * tq + (c & 1);
                    int qr = warp * 16 + g + ((c >= 2) ? 8 : 0);
                    if (kcol > qr) v = -1.0e30f;
                }
                sacc[nt][c] = v;
            }
        }

        // online softmax (rows g and g+8)
        float rm0 = -3.0e38f, rm1 = -3.0e38f;
#pragma unroll
        for (int nt = 0; nt < 8; nt++) {
            rm0 = fmaxf(rm0, fmaxf(sacc[nt][0], sacc[nt][1]));
            rm1 = fmaxf(rm1, fmaxf(sacc[nt][2], sacc[nt][3]));
        }
        rm0 = fmaxf(rm0, __shfl_xor_sync(0xffffffffu, rm0, 1));
        rm0 = fmaxf(rm0, __shfl_xor_sync(0xffffffffu, rm0, 2));
        rm1 = fmaxf(rm1, __shfl_xor_sync(0xffffffffu, rm1, 1));
        rm1 = fmaxf(rm1, __shfl_xor_sync(0xffffffffu, rm1, 2));
        float mn0 = fmaxf(m0, rm0), mn1 = fmaxf(m1, rm1);
        float a0 = expf(m0 - mn0), a1 = expf(m1 - mn1);
        m0 = mn0; m1 = mn1;
        float rs0 = 0.f, rs1 = 0.f;
#pragma unroll
        for (int nt = 0; nt < 8; nt++) {
            float p0 = expf(sacc[nt][0] - mn0);
            float p1 = expf(sacc[nt][1] - mn0);
            float p2 = expf(sacc[nt][2] - mn1);
            float p3 = expf(sacc[nt][3] - mn1);
            sacc[nt][0] = p0; sacc[nt][1] = p1; sacc[nt][2] = p2; sacc[nt][3] = p3;
            rs0 += p0 + p1; rs1 += p2 + p3;
        }
        rs0 += __shfl_xor_sync(0xffffffffu, rs0, 1);
        rs0 += __shfl_xor_sync(0xffffffffu, rs0, 2);
        rs1 += __shfl_xor_sync(0xffffffffu, rs1, 1);
        rs1 += __shfl_xor_sync(0xffffffffu, rs1, 2);
        l0 = l0 * a0 + rs0;
        l1 = l1 * a1 + rs1;
#pragma unroll
        for (int nt = 0; nt < 16; nt++) {
            oacc[nt][0] *= a0; oacc[nt][1] *= a0;
            oacc[nt][2] *= a1; oacc[nt][3] *= a1;
        }

        // P c-frag -> a-frag (register identity)
        uint32_t pf[4][4];
#pragma unroll
        for (int s4 = 0; s4 < 4; s4++) {
            pf[s4][0] = f22u(sacc[2 * s4][0],     sacc[2 * s4][1]);
            pf[s4][1] = f22u(sacc[2 * s4][2],     sacc[2 * s4][3]);
            pf[s4][2] = f22u(sacc[2 * s4 + 1][0], sacc[2 * s4 + 1][1]);
            pf[s4][3] = f22u(sacc[2 * s4 + 1][2], sacc[2 * s4 + 1][3]);
        }

        // O += P V   (V^T packed: rows d, cols k)
#pragma unroll
        for (int s4 = 0; s4 < 4; s4++) {
#pragma unroll
            for (int bt = 0; bt < 8; bt++) {
                int dm = 2 * bt + (sel >> 1);
                int km2 = 2 * s4 + (sel & 1);
                uint32_t r4[4];
                LDSM4(r4, Vb + (uint32_t)(((dm << 3) + km2) * 128 + rowin * 16));
                MMA_F16(oacc[2 * bt],     pf[s4], r4);
                MMA_F16(oacc[2 * bt + 1], pf[s4], (r4 + 2));
            }
        }

        __syncthreads();
        if (tid == 0 && t + 2 < NT) {
            MBAR_EXPECT_TX(s0 + s * 8, 2 * 16384);
            bulk_g2s(Kb, gK + ((size_t)(t + 2) << 13), 16384, s0 + s * 8);
            bulk_g2s(Vb, gV + ((size_t)(t + 2) << 13), 16384, s0 + s * 8);
        }
    }

    // Epilogue: normalize; write packed fp16 (GEMM2 A layout)
    float i0 = 1.0f / l0, i1 = 1.0f / l1;
    int rowg = b * SEQ + qt * 64 + warp * 16 + g;
#pragma unroll
    for (int nt = 0; nt < 16; nt++) {
        int c8 = h * 16 + nt;
        int ktl = c8 >> 2, kc = c8 & 3;
        {
            int r = rowg;
            size_t mb = r >> 8; int rr = r & 255;
            __half* d = g_attn_pk + (((mb << 7) + ktl) << 13)
                      + (((((rr >> 3) << 2) + kc) << 6) + ((rr & 7) << 3)) + 2 * tq;
            *(__half2*)d = __floats2half2_rn(oacc[nt][0] * i0, oacc[nt][1] * i0);
        }
        {
            int r = rowg + 8;
            size_t mb = r >> 8; int rr = r & 255;
            __half* d = g_attn_pk + (((mb << 7) + ktl) << 13)
                      + (((((rr >> 3) << 2) + kc) << 6) + ((rr & 7) << 3)) + 2 * tq;
            *(__half2*)d = __floats2half2_rn(oacc[nt][2] * i1, oacc[nt][3] * i1);
        }
    }
}

// ---------------------------------------------------------------------------
// Launch
// ---------------------------------------------------------------------------
extern "C" void kernel_launch(void* const* d_in, const int* in_sizes, int n_in,
                              void* d_out, int out_size) {
    const int*   positions = (const int*)d_in[0];
    const float* hidden    = (const float*)d_in[1];
    const float* w_qkv     = (const float*)d_in[2];
    const float* w_o       = (const float*)d_in[3];
    float*       out       = (float*)d_out;

    static __half *hid_pk, *wqkv_pk, *wo_pk, *attn_pk;
    static float* qkv;
    static bool init = false;
    if (!init) {
        cudaGetSymbolAddress((void**)&hid_pk,  g_hid_pk);
        cudaGetSymbolAddress((void**)&wqkv_pk, g_wqkv_pk);
        cudaGetSymbolAddress((void**)&wo_pk,   g_wo_pk);
        cudaGetSymbolAddress((void**)&attn_pk, g_attn_pk);
        cudaGetSymbolAddress((void**)&qkv,     g_qkv);
        cudaFuncSetAttribute(gemm_f16x2, cudaFuncAttributeMaxDynamicSharedMemorySize,
                             GEMM_SMEM);
        cudaFuncSetAttribute(flash_mma, cudaFuncAttributeMaxDynamicSharedMemorySize,
                             FLASH_SMEM);
        init = true;
    }

    act_pack<<<(BS_ROWS * 512 + 255) / 256, 256>>>(hidden, hid_pk);
    split_T_pack<<<dim3(QKV_N / 32, HID / 32), dim3(32, 32)>>>(w_qkv, wqkv_pk, HID, QKV_N);
    split_T_pack<<<dim3(HID / 32, HID / 32), dim3(32, 32)>>>(w_o, wo_pk, HID, HID);

    gemm_f16x2<<<dim3(QKV_N / 128, BS_ROWS / 256), 512, GEMM_SMEM>>>(
        hid_pk, wqkv_pk, qkv, QKV_N, HID);

    qk_pack<<<(BS_ROWS * 40 * 32 + 255) / 256, 256>>>(positions);
    v_pack<<<dim3(16, NKV, BATCH), 256>>>();

    flash_mma<<<dim3(SEQ / 64, NQH, BATCH), 128, FLASH_SMEM>>>();

    gemm_f16x2<<<dim3(HID / 128, BS_ROWS / 256), 512, GEMM_SMEM>>>(
        attn_pk, wo_pk, out, HID, HID);
}

// round 12
// speedup vs baseline: 4.7520x; 1.6530x over previous
#include <cuda_runtime.h>
#include <cuda_fp16.h>
#include <math.h>
#include <stdint.h>

// Problem constants
#define BATCH   4
#define SEQ     1024
#define HID     4096
#define NQH     32
#define NKV     8
#define HD      128
#define QKV_N   6144
#define BS_ROWS 4096

// ---------------------------------------------------------------------------
// Scratch. Tile-packed fp16 layouts (8x8-matrix contiguous, 128B per matrix).
//  A tensors: 256x32 tiles (16KB), tile (mb,kt) at ((mb*(K/32)+kt)<<13) halves.
//  B tensors: 128x32 tiles (8KB),  tile (nb,kt) at ((nb*(K/32)+kt)<<12) halves.
// ---------------------------------------------------------------------------
__device__ float  g_qkv[(size_t)BS_ROWS * QKV_N];
__device__ __half g_hid_pk[(size_t)BS_ROWS * HID];
__device__ __half g_wqkv_pk[(size_t)QKV_N * HID];
__device__ __half g_wo_pk[(size_t)HID * HID];
__device__ __half g_attn_pk[(size_t)BS_ROWS * HID];
__device__ __half g_q16[(size_t)BATCH * NQH * 16 * 8192];
__device__ __half g_k16[(size_t)BATCH * NKV * 16 * 8192];
__device__ __half g_vT16[(size_t)BATCH * NKV * 16 * 8192];

__device__ __forceinline__ uint32_t smem_u32(const void* p) {
    uint32_t a;
    asm("{ .reg .u64 t; cvta.to.shared.u64 t, %1; cvt.u32.u64 %0, t; }" : "=r"(a) : "l"(p));
    return a;
}
__device__ __forceinline__ uint32_t f22u(float a, float b) {
    __half2 h = __floats2half2_rn(a, b);
    return *(uint32_t*)&h;
}

#define MBAR_INIT(addr, cnt) \
    asm volatile("mbarrier.init.shared.b64 [%0], %1;" :: "r"(addr), "r"(cnt) : "memory")
#define MBAR_EXPECT_TX(addr, bytes) \
    asm volatile("mbarrier.arrive.expect_tx.shared.b64 _, [%0], %1;" \
                 :: "r"(addr), "r"(bytes) : "memory")
__device__ __forceinline__ void mbar_wait(uint32_t addr, uint32_t parity) {
    asm volatile(
        "{\n\t.reg .pred P;\n\t"
        "WL%=:\n\t"
        "mbarrier.try_wait.parity.acquire.cta.shared::cta.b64 P, [%0], %1, 0x989680;\n\t"
        "@!P bra WL%=;\n\t}"
        :: "r"(addr), "r"(parity) : "memory");
}
__device__ __forceinline__ void bulk_g2s(uint32_t dst, const void* src,
                                         uint32_t bytes, uint32_t mbar) {
    asm volatile(
        "cp.async.bulk.shared::cluster.global.mbarrier::complete_tx::bytes "
        "[%0], [%1], %2, [%3];"
        :: "r"(dst), "l"(src), "r"(bytes), "r"(mbar) : "memory");
}

#define LDSM4(R, ADDR) \
    asm volatile("ldmatrix.sync.aligned.m8n8.x4.shared.b16 {%0,%1,%2,%3}, [%4];" \
                 : "=r"((R)[0]), "=r"((R)[1]), "=r"((R)[2]), "=r"((R)[3]) : "r"(ADDR))
#define MMA_F16(ACC, A, B) \
    asm volatile("mma.sync.aligned.m16n8k16.row.col.f32.f16.f16.f32 " \
                 "{%0,%1,%2,%3}, {%4,%5,%6,%7}, {%8,%9}, {%0,%1,%2,%3};" \
                 : "+f"((ACC)[0]), "+f"((ACC)[1]), "+f"((ACC)[2]), "+f"((ACC)[3]) \
                 : "r"((A)[0]), "r"((A)[1]), "r"((A)[2]), "r"((A)[3]), \
                   "r"((B)[0]), "r"((B)[1]))

// ---------------------------------------------------------------------------
// Packing kernels
// ---------------------------------------------------------------------------
__global__ void act_pack(const float* __restrict__ in, __half* __restrict__ out) {
    int i = blockIdx.x * blockDim.x + threadIdx.x;
    if (i >= BS_ROWS * 512) return;
    int row = i >> 9;
    int k8  = i & 511;
    const float4* s = (const float4*)(in + ((size_t)row << 12) + (k8 << 3));
    float4 v0 = s[0], v1 = s[1];
    __half2 h[4];
    h[0] = __floats2half2_rn(v0.x, v0.y);
    h[1] = __floats2half2_rn(v0.z, v0.w);
    h[2] = __floats2half2_rn(v1.x, v1.y);
    h[3] = __floats2half2_rn(v1.z, v1.w);
    size_t mb = row >> 8;
    int r = row & 255, kt = k8 >> 2, kc = k8 & 3;
    __half* d = out + (((mb << 7) + kt) << 13)
              + (((((r >> 3) << 2) + kc) << 6) + ((r & 7) << 3));
    *(uint4*)d = *(uint4*)h;
}

// W[Kdim, Ndim] f32 -> packed fp16 B tiles [Ndim/128 x Kdim/32], 8KB each
__global__ void split_T_pack(const float* __restrict__ W,
                             __half* __restrict__ pk, int Kdim, int Ndim) {
    __shared__ float t[32][33];
    int n0 = blockIdx.x * 32, k0 = blockIdx.y * 32;
    t[threadIdx.y][threadIdx.x] = W[(long)(k0 + threadIdx.y) * Ndim + n0 + threadIdx.x];
    __syncthreads();
    float x = t[threadIdx.x][threadIdx.y];
    int n = n0 + threadIdx.y;
    int k = k0 + threadIdx.x;
    int nb = n >> 7, r = n & 127;
    int kt = k >> 5, kc = (k >> 3) & 3, kin = k & 7;
    size_t base = ((size_t)(nb * (Kdim >> 5) + kt)) << 12;
    int off = ((((r >> 3) << 2) + kc) << 6) + ((r & 7) << 3) + kin;
    pk[base + off] = __float2half(x);
}

// RoPE + pack q/k as fp16 tiles.
__global__ void qk_pack(const int* __restrict__ pos) {
    int idx = blockIdx.x * blockDim.x + threadIdx.x;
    if (idx >= BS_ROWS * 40 * 32) return;
    int lane = idx & 31;
    int h    = (idx >> 5) % 40;
    int row  = idx / (40 * 32);
    int p    = pos[row];
    const float* src = g_qkv + (long)row * QKV_N + h * HD;
    int i0 = 2 * lane;
    float x1a = src[i0], x1b = src[i0 + 1], x2a = src[i0 + 64], x2b = src[i0 + 65];
    float sa, ca, sb, cb;
    sincosf((float)p * expf(-(float)i0 * 0.14391156831212787f), &sa, &ca);
    sincosf((float)p * expf(-(float)(i0 + 1) * 0.14391156831212787f), &sb, &cb);
    float y1a = x1a * ca - x2a * sa, y1b = x1b * cb - x2b * sb;
    float y2a = x2a * ca + x1a * sa, y2b = x2b * cb + x1b * sb;
    int s = row & (SEQ - 1), b = row >> 10;
    int st = s >> 6, r = s & 63;
    __half* base = (h < NQH)
        ? g_q16 + ((size_t)((b * NQH + h) * 16 + st) << 13)
        : g_k16 + ((size_t)((b * NKV + (h - NQH)) * 16 + st) << 13);
    int roff = ((r >> 3) << 10) + ((r & 7) << 3);
    *(__half2*)(base + roff + ((i0 >> 3) << 6) + (i0 & 7)) = __floats2half2_rn(y1a, y1b);
    int c2 = i0 + 64;
    *(__half2*)(base + roff + ((c2 >> 3) << 6) + (c2 & 7)) = __floats2half2_rn(y2a, y2b);
}

// V f32 [s][d] -> V^T fp16 packed [128 x 64] tiles.
__global__ __launch_bounds__(256) void v_pack() {
    __shared__ float vt[64][129];
    int st = blockIdx.x, kvh = blockIdx.y, b = blockIdx.z;
    int tid = threadIdx.x;
    const float* src = g_qkv + ((long)(b * SEQ + st * 64)) * QKV_N + (NQH + NKV) * HD + kvh * HD;
    for (int e = tid; e < 64 * 32; e += 256) {
        int r = e >> 5, d4 = (e & 31) << 2;
        float4 v = *(const float4*)(src + (long)r * QKV_N + d4);
        vt[r][d4] = v.x; vt[r][d4 + 1] = v.y; vt[r][d4 + 2] = v.z; vt[r][d4 + 3] = v.w;
    }
    __syncthreads();
    __half* dst = g_vT16 + ((size_t)((b * NKV + kvh) * 16 + st) << 13);
    for (int e = tid; e < 1024; e += 256) {
        int m = e >> 3, rr = e & 7;
        int dr = ((m >> 3) << 3) + rr;
        int c0 = (m & 7) << 3;
        __half2 hv[4];
#pragma unroll
        for (int j = 0; j < 4; j++)
            hv[j] = __floats2half2_rn(vt[c0 + 2 * j][dr], vt[c0 + 2 * j + 1][dr]);
        *(uint4*)(dst + (m << 6) + (rr << 3)) = *(uint4*)hv;
    }
}

// ---------------------------------------------------------------------------
// HMMA GEMM: C[M,N] = A[M,K] @ Bt[N,K]^T, pure fp16.
// CTA 256x128, BK=32, 512 threads = 16 warps (4Mx4N), warp tile 64x32.
// 2 bulk copies per K-tile (A 16KB + B 8KB), 4-stage mbarrier ring.
// ---------------------------------------------------------------------------
#define STAGE_BYTES 24576
#define NSTAGE 4
#define SMEM_TILES 1024
#define A_OFF    0
#define B_OFF 16384
#define GEMM_SMEM (SMEM_TILES + NSTAGE * STAGE_BYTES)

__global__ __launch_bounds__(512, 1)
void gemm_f16(const __half* __restrict__ Apk, const __half* __restrict__ Bpk,
              float* __restrict__ C, int N, int K)
{
    extern __shared__ char smx[];
    const uint32_t s0 = smem_u32(smx);
    const int tid  = threadIdx.x;
    const int wid  = tid >> 5;
    const int lane = tid & 31;
    const int wm   = wid >> 2;
    const int wn   = wid & 3;
    const int sel  = lane >> 3;
    const int rowin = lane & 7;
    const int g    = lane >> 2;
    const int tq   = lane & 3;
    const long bm = (long)blockIdx.y * 256;
    const long bn = (long)blockIdx.x * 128;
    const int NKT = K >> 5;

    const __half* gA = Apk + ((size_t)(blockIdx.y * NKT) << 13);
    const __half* gB = Bpk + ((size_t)(blockIdx.x * NKT) << 12);

    if (tid == 0) {
#pragma unroll
        for (int s = 0; s < NSTAGE; s++) MBAR_INIT(s0 + s * 8, 1);
    }
    __syncthreads();

    if (tid == 0) {
#pragma unroll
        for (int p = 0; p < NSTAGE - 1; p++) {
            uint32_t mb = s0 + p * 8;
            uint32_t db = s0 + SMEM_TILES + p * STAGE_BYTES;
            MBAR_EXPECT_TX(mb, 24576);
            bulk_g2s(db + A_OFF, gA + ((size_t)p << 13), 16384, mb);
            bulk_g2s(db + B_OFF, gB + ((size_t)p << 12), 8192, mb);
        }
    }

    float acc[4][4][4];
#pragma unroll
    for (int i = 0; i < 4; i++)
#pragma unroll
        for (int j = 0; j < 4; j++)
#pragma unroll
            for (int k = 0; k < 4; k++) acc[i][j][k] = 0.f;

    for (int t = 0; t < NKT; t++) {
        const int s = t & (NSTAGE - 1);
        if (tid == 0 && t + NSTAGE - 1 < NKT) {
            const int tp = t + NSTAGE - 1;
            const int sp = tp & (NSTAGE - 1);
            uint32_t mb = s0 + sp * 8;
            uint32_t db = s0 + SMEM_TILES + sp * STAGE_BYTES;
            MBAR_EXPECT_TX(mb, 24576);
            bulk_g2s(db + A_OFF, gA + ((size_t)tp << 13), 16384, mb);
            bulk_g2s(db + B_OFF, gB + ((size_t)tp << 12), 8192, mb);
        }
        mbar_wait(s0 + s * 8, (t >> 2) & 1);

        const uint32_t sb = s0 + SMEM_TILES + s * STAGE_BYTES;
#pragma unroll
        for (int ks = 0; ks < 2; ks++) {
            uint32_t a[4][4], bf[4][2];
#pragma unroll
            for (int mt = 0; mt < 4; mt++) {
                int rm = wm * 8 + 2 * mt + (sel & 1);
                int km = 2 * ks + (sel >> 1);
                uint32_t off = (uint32_t)(((rm << 2) + km) * 128 + rowin * 16);
                LDSM4(a[mt], sb + A_OFF + off);
            }
#pragma unroll
            for (int bt = 0; bt < 2; bt++) {
                int nm = wn * 4 + 2 * bt + (sel >> 1);
                int km = 2 * ks + (sel & 1);
                uint32_t off = (uint32_t)(((nm << 2) + km) * 128 + rowin * 16);
                uint32_t r4[4];
                LDSM4(r4, sb + B_OFF + off);
                bf[2 * bt][0] = r4[0]; bf[2 * bt][1] = r4[1];
                bf[2 * bt + 1][0] = r4[2]; bf[2 * bt + 1][1] = r4[3];
            }
#pragma unroll
            for (int mt = 0; mt < 4; mt++)
#pragma unroll
                for (int nt = 0; nt < 4; nt++)
                    MMA_F16(acc[mt][nt], a[mt], bf[nt]);
        }
        __syncthreads();
    }

#pragma unroll
    for (int mt = 0; mt < 4; mt++) {
        long row0 = bm + wm * 64 + mt * 16 + g;
#pragma unroll
        for (int nt = 0; nt < 4; nt++) {
            long col = bn + wn * 32 + nt * 8 + tq * 2;
            *(float2*)&C[row0 * N + col]       = make_float2(acc[mt][nt][0], acc[mt][nt][1]);
            *(float2*)&C[(row0 + 8) * N + col] = make_float2(acc[mt][nt][2], acc[mt][nt][3]);
        }
    }
}

// ---------------------------------------------------------------------------
// Flash attention with mma.sync (unchanged from round 11)
// ---------------------------------------------------------------------------
#define FQ_OFF 1024
#define FK_OFF (1024 + 16384)
#define FV_OFF (1024 + 16384 + 16384)
#define FSTAGE 32768
#define FLASH_SMEM (1024 + 16384 + 2 * FSTAGE)

__global__ __launch_bounds__(128, 2) void flash_mma() {
    extern __shared__ char smf[];
    const uint32_t s0 = smem_u32(smf);
    const int tid  = threadIdx.x;
    const int warp = tid >> 5;
    const int lane = tid & 31;
    const int g    = lane >> 2;
    const int tq   = lane & 3;
    const int sel  = lane >> 3;
    const int rowin = lane & 7;
    const int qt = blockIdx.x, h = blockIdx.y, b = blockIdx.z;
    const int kvh = h >> 2;

    const __half* gQ = g_q16 + ((size_t)((b * NQH + h) * 16 + qt) << 13);
    const __half* gK = g_k16 + ((size_t)((b * NKV + kvh) * 16) << 13);
    const __half* gV = g_vT16 + ((size_t)((b * NKV + kvh) * 16) << 13);

    if (tid == 0) { MBAR_INIT(s0, 1); MBAR_INIT(s0 + 8, 1); }
    __syncthreads();
    const int NT = qt + 1;
    if (tid == 0) {
        MBAR_EXPECT_TX(s0, 3 * 16384);
        bulk_g2s(s0 + FQ_OFF, gQ, 16384, s0);
        bulk_g2s(s0 + FK_OFF, gK, 16384, s0);
        bulk_g2s(s0 + FV_OFF, gV, 16384, s0);
        if (NT > 1) {
            MBAR_EXPECT_TX(s0 + 8, 2 * 16384);
            bulk_g2s(s0 + FK_OFF + FSTAGE, gK + 8192, 16384, s0 + 8);
            bulk_g2s(s0 + FV_OFF + FSTAGE, gV + 8192, 16384, s0 + 8);
        }
    }

    float oacc[16][4];
#pragma unroll
    for (int i = 0; i < 16; i++)
#pragma unroll
        for (int j = 0; j < 4; j++) oacc[i][j] = 0.f;
    float m0 = -3.0e38f, m1 = -3.0e38f, l0 = 0.f, l1 = 0.f;
    const float scale = 0.08838834764831845f;

    for (int t = 0; t < NT; t++) {
        const int s = t & 1;
        mbar_wait(s0 + s * 8, (t >> 1) & 1);
        const uint32_t Qb = s0 + FQ_OFF;
        const uint32_t Kb = s0 + FK_OFF + s * FSTAGE;
        const uint32_t Vb = s0 + FV_OFF + s * FSTAGE;

        float sacc[8][4];
#pragma unroll
        for (int i = 0; i < 8; i++)
#pragma unroll
            for (int j = 0; j < 4; j++) sacc[i][j] = 0.f;

#pragma unroll
        for (int ks = 0; ks < 8; ks++) {
            uint32_t qa[4];
            {
                int rm = warp * 2 + (sel & 1);
                int km = 2 * ks + (sel >> 1);
                LDSM4(qa, Qb + (uint32_t)(((rm << 4) + km) * 128 + rowin * 16));
            }
            uint32_t kb[8][2];
#pragma unroll
            for (int bt = 0; bt < 4; bt++) {
                int nm = 2 * bt + (sel >> 1);
                int km = 2 * ks + (sel & 1);
                uint32_t r4[4];
                LDSM4(r4, Kb + (uint32_t)(((nm << 4) + km) * 128 + rowin * 16));
                kb[2 * bt][0] = r4[0]; kb[2 * bt][1] = r4[1];
                kb[2 * bt + 1][0] = r4[2]; kb[2 * bt + 1][1] = r4[3];
            }
#pragma unroll
            for (int nt = 0; nt < 8; nt++) MMA_F16(sacc[nt], qa, kb[nt]);
        }

        const bool diag = (t == qt);
#pragma unroll
        for (int nt = 0; nt < 8; nt++) {
#pragma unroll
            for (int c = 0; c < 4; c++) {
                float v = sacc[nt][c] * scale;
                if (diag) {
                    int kcol = nt * 8 + 2 * tq + (c & 1);
                    int qr = warp * 16 + g + ((c >= 2) ? 8 : 0);
                    if (kcol > qr) v = -1.0e30f;
                }
                sacc[nt][c] = v;
            }
        }

        float rm0 = -3.0e38f, rm1 = -3.0e38f;
#pragma unroll
        for (int nt = 0; nt < 8; nt++) {
            rm0 = fmaxf(rm0, fmaxf(sacc[nt][0], sacc[nt][1]));
            rm1 = fmaxf(rm1, fmaxf(sacc[nt][2], sacc[nt][3]));
        }
        rm0 = fmaxf(rm0, __shfl_xor_sync(0xffffffffu, rm0, 1));
        rm0 = fmaxf(rm0, __shfl_xor_sync(0xffffffffu, rm0, 2));
        rm1 = fmaxf(rm1, __shfl_xor_sync(0xffffffffu, rm1, 1));
        rm1 = fmaxf(rm1, __shfl_xor_sync(0xffffffffu, rm1, 2));
        float mn0 = fmaxf(m0, rm0), mn1 = fmaxf(m1, rm1);
        float a0 = expf(m0 - mn0), a1 = expf(m1 - mn1);
        m0 = mn0; m1 = mn1;
        float rs0 = 0.f, rs1 = 0.f;
#pragma unroll
        for (int nt = 0; nt < 8; nt++) {
            float p0 = expf(sacc[nt][0] - mn0);
            float p1 = expf(sacc[nt][1] - mn0);
            float p2 = expf(sacc[nt][2] - mn1);
            float p3 = expf(sacc[nt][3] - mn1);
            sacc[nt][0] = p0; sacc[nt][1] = p1; sacc[nt][2] = p2; sacc[nt][3] = p3;
            rs0 += p0 + p1; rs1 += p2 + p3;
        }
        rs0 += __shfl_xor_sync(0xffffffffu, rs0, 1);
        rs0 += __shfl_xor_sync(0xffffffffu, rs0, 2);
        rs1 += __shfl_xor_sync(0xffffffffu, rs1, 1);
        rs1 += __shfl_xor_sync(0xffffffffu, rs1, 2);
        l0 = l0 * a0 + rs0;
        l1 = l1 * a1 + rs1;
#pragma unroll
        for (int nt = 0; nt < 16; nt++) {
            oacc[nt][0] *= a0; oacc[nt][1] *= a0;
            oacc[nt][2] *= a1; oacc[nt][3] *= a1;
        }

        uint32_t pf[4][4];
#pragma unroll
        for (int s4 = 0; s4 < 4; s4++) {
            pf[s4][0] = f22u(sacc[2 * s4][0],     sacc[2 * s4][1]);
            pf[s4][1] = f22u(sacc[2 * s4][2],     sacc[2 * s4][3]);
            pf[s4][2] = f22u(sacc[2 * s4 + 1][0], sacc[2 * s4 + 1][1]);
            pf[s4][3] = f22u(sacc[2 * s4 + 1][2], sacc[2 * s4 + 1][3]);
        }

#pragma unroll
        for (int s4 = 0; s4 < 4; s4++) {
#pragma unroll
            for (int bt = 0; bt < 8; bt++) {
                int dm = 2 * bt + (sel >> 1);
                int km2 = 2 * s4 + (sel & 1);
                uint32_t r4[4];
                LDSM4(r4, Vb + (uint32_t)(((dm << 3) + km2) * 128 + rowin * 16));
                MMA_F16(oacc[2 * bt],     pf[s4], r4);
                MMA_F16(oacc[2 * bt + 1], pf[s4], (r4 + 2));
            }
        }

        __syncthreads();
        if (tid == 0 && t + 2 < NT) {
            MBAR_EXPECT_TX(s0 + s * 8, 2 * 16384);
            bulk_g2s(Kb, gK + ((size_t)(t + 2) << 13), 16384, s0 + s * 8);
            bulk_g2s(Vb, gV + ((size_t)(t + 2) << 13), 16384, s0 + s * 8);
        }
    }

    float i0 = 1.0f / l0, i1 = 1.0f / l1;
    int rowg = b * SEQ + qt * 64 + warp * 16 + g;
#pragma unroll
    for (int nt = 0; nt < 16; nt++) {
        int c8 = h * 16 + nt;
        int ktl = c8 >> 2, kc = c8 & 3;
        {
            int r = rowg;
            size_t mb = r >> 8; int rr = r & 255;
            __half* d = g_attn_pk + (((mb << 7) + ktl) << 13)
                      + (((((rr >> 3) << 2) + kc) << 6) + ((rr & 7) << 3)) + 2 * tq;
            *(__half2*)d = __floats2half2_rn(oacc[nt][0] * i0, oacc[nt][1] * i0);
        }
        {
            int r = rowg + 8;
            size_t mb = r >> 8; int rr = r & 255;
            __half* d = g_attn_pk + (((mb << 7) + ktl) << 13)
                      + (((((rr >> 3) << 2) + kc) << 6) + ((rr & 7) << 3)) + 2 * tq;
            *(__half2*)d = __floats2half2_rn(oacc[nt][2] * i1, oacc[nt][3] * i1);
        }
    }
}

// ---------------------------------------------------------------------------
// Launch
// ---------------------------------------------------------------------------
extern "C" void kernel_launch(void* const* d_in, const int* in_sizes, int n_in,
                              void* d_out, int out_size) {
    const int*   positions = (const int*)d_in[0];
    const float* hidden    = (const float*)d_in[1];
    const float* w_qkv     = (const float*)d_in[2];
    const float* w_o       = (const float*)d_in[3];
    float*       out       = (float*)d_out;

    static __half *hid_pk, *wqkv_pk, *wo_pk, *attn_pk;
    static float* qkv;
    static bool init = false;
    if (!init) {
        cudaGetSymbolAddress((void**)&hid_pk,  g_hid_pk);
        cudaGetSymbolAddress((void**)&wqkv_pk, g_wqkv_pk);
        cudaGetSymbolAddress((void**)&wo_pk,   g_wo_pk);
        cudaGetSymbolAddress((void**)&attn_pk, g_attn_pk);
        cudaGetSymbolAddress((void**)&qkv,     g_qkv);
        cudaFuncSetAttribute(gemm_f16, cudaFuncAttributeMaxDynamicSharedMemorySize,
                             GEMM_SMEM);
        cudaFuncSetAttribute(flash_mma, cudaFuncAttributeMaxDynamicSharedMemorySize,
                             FLASH_SMEM);
        init = true;
    }

    act_pack<<<(BS_ROWS * 512 + 255) / 256, 256>>>(hidden, hid_pk);
    split_T_pack<<<dim3(QKV_N / 32, HID / 32), dim3(32, 32)>>>(w_qkv, wqkv_pk, HID, QKV_N);
    split_T_pack<<<dim3(HID / 32, HID / 32), dim3(32, 32)>>>(w_o, wo_pk, HID, HID);

    gemm_f16<<<dim3(QKV_N / 128, BS_ROWS / 256), 512, GEMM_SMEM>>>(
        hid_pk, wqkv_pk, qkv, QKV_N, HID);

    qk_pack<<<(BS_ROWS * 40 * 32 + 255) / 256, 256>>>(positions);
    v_pack<<<dim3(16, NKV, BATCH), 256>>>();

    flash_mma<<<dim3(SEQ / 64, NQH, BATCH), 128, FLASH_SMEM>>>();

    gemm_f16<<<dim3(HID / 128, BS_ROWS / 256), 512, GEMM_SMEM>>>(
        attn_pk, wo_pk, out, HID, HID);
}

// round 13
// speedup vs baseline: 5.4558x; 1.1481x over previous
#include <cuda_runtime.h>
#include <cuda_fp16.h>
#include <math.h>
#include <stdint.h>

// Problem constants
#define BATCH   4
#define SEQ     1024
#define HID     4096
#define NQH     32
#define NKV     8
#define HD      128
#define QKV_N   6144
#define BS_ROWS 4096

// ---------------------------------------------------------------------------
// Scratch. Tile-packed fp16 layouts (8x8-matrix contiguous, 128B per matrix).
//  A tensors: 128x32 tiles (8KB), tile (mb,kt) at ((mb*(K/32)+kt)<<12) halves.
//  B tensors: 128x32 tiles (8KB), tile (nb,kt) at ((nb*(K/32)+kt)<<12) halves.
// ---------------------------------------------------------------------------
__device__ float  g_qkv[(size_t)BS_ROWS * QKV_N];
__device__ __half g_hid_pk[(size_t)BS_ROWS * HID];
__device__ __half g_wqkv_pk[(size_t)QKV_N * HID];
__device__ __half g_wo_pk[(size_t)HID * HID];
__device__ __half g_attn_pk[(size_t)BS_ROWS * HID];
__device__ __half g_q16[(size_t)BATCH * NQH * 16 * 8192];
__device__ __half g_k16[(size_t)BATCH * NKV * 16 * 8192];
__device__ __half g_vT16[(size_t)BATCH * NKV * 16 * 8192];
__device__ float2 g_rope[(size_t)BS_ROWS * 64];            // cos/sin per (row, i)

__device__ __forceinline__ uint32_t smem_u32(const void* p) {
    uint32_t a;
    asm("{ .reg .u64 t; cvta.to.shared.u64 t, %1; cvt.u32.u64 %0, t; }" : "=r"(a) : "l"(p));
    return a;
}
__device__ __forceinline__ uint32_t f22u(float a, float b) {
    __half2 h = __floats2half2_rn(a, b);
    return *(uint32_t*)&h;
}

#define MBAR_INIT(addr, cnt) \
    asm volatile("mbarrier.init.shared.b64 [%0], %1;" :: "r"(addr), "r"(cnt) : "memory")
#define MBAR_EXPECT_TX(addr, bytes) \
    asm volatile("mbarrier.arrive.expect_tx.shared.b64 _, [%0], %1;" \
                 :: "r"(addr), "r"(bytes) : "memory")
__device__ __forceinline__ void mbar_wait(uint32_t addr, uint32_t parity) {
    asm volatile(
        "{\n\t.reg .pred P;\n\t"
        "WL%=:\n\t"
        "mbarrier.try_wait.parity.acquire.cta.shared::cta.b64 P, [%0], %1, 0x989680;\n\t"
        "@!P bra WL%=;\n\t}"
        :: "r"(addr), "r"(parity) : "memory");
}
__device__ __forceinline__ void bulk_g2s(uint32_t dst, const void* src,
                                         uint32_t bytes, uint32_t mbar) {
    asm volatile(
        "cp.async.bulk.shared::cluster.global.mbarrier::complete_tx::bytes "
        "[%0], [%1], %2, [%3];"
        :: "r"(dst), "l"(src), "r"(bytes), "r"(mbar) : "memory");
}

#define LDSM4(R, ADDR) \
    asm volatile("ldmatrix.sync.aligned.m8n8.x4.shared.b16 {%0,%1,%2,%3}, [%4];" \
                 : "=r"((R)[0]), "=r"((R)[1]), "=r"((R)[2]), "=r"((R)[3]) : "r"(ADDR))
#define MMA_F16(ACC, A, B) \
    asm volatile("mma.sync.aligned.m16n8k16.row.col.f32.f16.f16.f32 " \
                 "{%0,%1,%2,%3}, {%4,%5,%6,%7}, {%8,%9}, {%0,%1,%2,%3};" \
                 : "+f"((ACC)[0]), "+f"((ACC)[1]), "+f"((ACC)[2]), "+f"((ACC)[3]) \
                 : "r"((A)[0]), "r"((A)[1]), "r"((A)[2]), "r"((A)[3]), \
                   "r"((B)[0]), "r"((B)[1]))

// ---------------------------------------------------------------------------
// Packing kernels
// ---------------------------------------------------------------------------
// hidden f32 -> packed fp16 A tiles (128 rows x 32 k, 8KB)
__global__ void act_pack(const float* __restrict__ in, __half* __restrict__ out) {
    int i = blockIdx.x * blockDim.x + threadIdx.x;
    if (i >= BS_ROWS * 512) return;
    int row = i >> 9;
    int k8  = i & 511;
    const float4* s = (const float4*)(in + ((size_t)row << 12) + (k8 << 3));
    float4 v0 = s[0], v1 = s[1];
    __half2 h[4];
    h[0] = __floats2half2_rn(v0.x, v0.y);
    h[1] = __floats2half2_rn(v0.z, v0.w);
    h[2] = __floats2half2_rn(v1.x, v1.y);
    h[3] = __floats2half2_rn(v1.z, v1.w);
    size_t mb = row >> 7;
    int r = row & 127, kt = k8 >> 2, kc = k8 & 3;
    __half* d = out + (((mb << 7) + kt) << 12)
              + (((((r >> 3) << 2) + kc) << 6) + ((r & 7) << 3));
    *(uint4*)d = *(uint4*)h;
}

// W[Kdim, Ndim] f32 -> packed fp16 B tiles [Ndim/128 x Kdim/32], 8KB each
__global__ void split_T_pack(const float* __restrict__ W,
                             __half* __restrict__ pk, int Kdim, int Ndim) {
    __shared__ float t[32][33];
    int n0 = blockIdx.x * 32, k0 = blockIdx.y * 32;
    t[threadIdx.y][threadIdx.x] = W[(long)(k0 + threadIdx.y) * Ndim + n0 + threadIdx.x];
    __syncthreads();
    float x = t[threadIdx.x][threadIdx.y];
    int n = n0 + threadIdx.y;
    int k = k0 + threadIdx.x;
    int nb = n >> 7, r = n & 127;
    int kt = k >> 5, kc = (k >> 3) & 3, kin = k & 7;
    size_t base = ((size_t)(nb * (Kdim >> 5) + kt)) << 12;
    int off = ((((r >> 3) << 2) + kc) << 6) + ((r & 7) << 3) + kin;
    pk[base + off] = __float2half(x);
}

// RoPE cos/sin table: one entry per (row, freq index)
__global__ void rope_tab(const int* __restrict__ pos) {
    int idx = blockIdx.x * blockDim.x + threadIdx.x;
    if (idx >= BS_ROWS * 64) return;
    int i = idx & 63, row = idx >> 6;
    float ang = (float)pos[row] * expf(-(float)i * 0.14391156831212787f);
    float sn, cs;
    sincosf(ang, &sn, &cs);
    g_rope[idx] = make_float2(cs, sn);
}

// RoPE (table) + pack q/k as fp16 tiles.
__global__ void qk_pack() {
    int idx = blockIdx.x * blockDim.x + threadIdx.x;
    if (idx >= BS_ROWS * 40 * 32) return;
    int lane = idx & 31;
    int h    = (idx >> 5) % 40;
    int row  = idx / (40 * 32);
    const float* src = g_qkv + (long)row * QKV_N + h * HD;
    int i0 = 2 * lane;
    float x1a = src[i0], x1b = src[i0 + 1], x2a = src[i0 + 64], x2b = src[i0 + 65];
    float4 cssn = *(const float4*)&g_rope[(size_t)row * 64 + i0];  // (ca,sa,cb,sb)
    float ca = cssn.x, sa = cssn.y, cb = cssn.z, sb = cssn.w;
    float y1a = x1a * ca - x2a * sa, y1b = x1b * cb - x2b * sb;
    float y2a = x2a * ca + x1a * sa, y2b = x2b * cb + x1b * sb;
    int s = row & (SEQ - 1), b = row >> 10;
    int st = s >> 6, r = s & 63;
    __half* base = (h < NQH)
        ? g_q16 + ((size_t)((b * NQH + h) * 16 + st) << 13)
        : g_k16 + ((size_t)((b * NKV + (h - NQH)) * 16 + st) << 13);
    int roff = ((r >> 3) << 10) + ((r & 7) << 3);
    *(__half2*)(base + roff + ((i0 >> 3) << 6) + (i0 & 7)) = __floats2half2_rn(y1a, y1b);
    int c2 = i0 + 64;
    *(__half2*)(base + roff + ((c2 >> 3) << 6) + (c2 & 7)) = __floats2half2_rn(y2a, y2b);
}

// V f32 [s][d] -> V^T fp16 packed [128 x 64] tiles.
__global__ __launch_bounds__(256) void v_pack() {
    __shared__ float vt[64][129];
    int st = blockIdx.x, kvh = blockIdx.y, b = blockIdx.z;
    int tid = threadIdx.x;
    const float* src = g_qkv + ((long)(b * SEQ + st * 64)) * QKV_N + (NQH + NKV) * HD + kvh * HD;
    for (int e = tid; e < 64 * 32; e += 256) {
        int r = e >> 5, d4 = (e & 31) << 2;
        float4 v = *(const float4*)(src + (long)r * QKV_N + d4);
        vt[r][d4] = v.x; vt[r][d4 + 1] = v.y; vt[r][d4 + 2] = v.z; vt[r][d4 + 3] = v.w;
    }
    __syncthreads();
    __half* dst = g_vT16 + ((size_t)((b * NKV + kvh) * 16 + st) << 13);
    for (int e = tid; e < 1024; e += 256) {
        int m = e >> 3, rr = e & 7;
        int dr = ((m >> 3) << 3) + rr;
        int c0 = (m & 7) << 3;
        __half2 hv[4];
#pragma unroll
        for (int j = 0; j < 4; j++)
            hv[j] = __floats2half2_rn(vt[c0 + 2 * j][dr], vt[c0 + 2 * j + 1][dr]);
        *(uint4*)(dst + (m << 6) + (rr << 3)) = *(uint4*)hv;
    }
}

// ---------------------------------------------------------------------------
// HMMA GEMM: C[M,N] = A[M,K] @ Bt[N,K]^T, pure fp16.
// CTA 128x128, BK=32, 256 threads = 8 warps (2Mx4N), warp tile 64x32,
// 2 CTAs/SM for latency overlap. 2 bulk copies per K-tile, 4-stage ring.
// ---------------------------------------------------------------------------
#define STAGE_BYTES 16384
#define NSTAGE 4
#define SMEM_TILES 1024
#define A_OFF 0
#define B_OFF 8192
#define GEMM_SMEM (SMEM_TILES + NSTAGE * STAGE_BYTES)

__global__ __launch_bounds__(256, 2)
void gemm_f16(const __half* __restrict__ Apk, const __half* __restrict__ Bpk,
              float* __restrict__ C, int N, int K)
{
    extern __shared__ char smx[];
    const uint32_t s0 = smem_u32(smx);
    const int tid  = threadIdx.x;
    const int wid  = tid >> 5;
    const int lane = tid & 31;
    const int wm   = wid >> 2;        // 0..1 (M, 64 rows)
    const int wn   = wid & 3;         // 0..3 (N, 32 cols)
    const int sel  = lane >> 3;
    const int rowin = lane & 7;
    const int g    = lane >> 2;
    const int tq   = lane & 3;
    const long bm = (long)blockIdx.y * 128;
    const long bn = (long)blockIdx.x * 128;
    const int NKT = K >> 5;

    const __half* gA = Apk + ((size_t)(blockIdx.y * NKT) << 12);
    const __half* gB = Bpk + ((size_t)(blockIdx.x * NKT) << 12);

    if (tid == 0) {
#pragma unroll
        for (int s = 0; s < NSTAGE; s++) MBAR_INIT(s0 + s * 8, 1);
    }
    __syncthreads();

    if (tid == 0) {
#pragma unroll
        for (int p = 0; p < NSTAGE - 1; p++) {
            uint32_t mb = s0 + p * 8;
            uint32_t db = s0 + SMEM_TILES + p * STAGE_BYTES;
            MBAR_EXPECT_TX(mb, 16384);
            bulk_g2s(db + A_OFF, gA + ((size_t)p << 12), 8192, mb);
            bulk_g2s(db + B_OFF, gB + ((size_t)p << 12), 8192, mb);
        }
    }

    float acc[4][4][4];
#pragma unroll
    for (int i = 0; i < 4; i++)
#pragma unroll
        for (int j = 0; j < 4; j++)
#pragma unroll
            for (int k = 0; k < 4; k++) acc[i][j][k] = 0.f;

    for (int t = 0; t < NKT; t++) {
        const int s = t & (NSTAGE - 1);
        if (tid == 0 && t + NSTAGE - 1 < NKT) {
            const int tp = t + NSTAGE - 1;
            const int sp = tp & (NSTAGE - 1);
            uint32_t mb = s0 + sp * 8;
            uint32_t db = s0 + SMEM_TILES + sp * STAGE_BYTES;
            MBAR_EXPECT_TX(mb, 16384);
            bulk_g2s(db + A_OFF, gA + ((size_t)tp << 12), 8192, mb);
            bulk_g2s(db + B_OFF, gB + ((size_t)tp << 12), 8192, mb);
        }
        mbar_wait(s0 + s * 8, (t >> 2) & 1);

        const uint32_t sb = s0 + SMEM_TILES + s * STAGE_BYTES;
#pragma unroll
        for (int ks = 0; ks < 2; ks++) {
            uint32_t a[4][4], bf[4][2];
#pragma unroll
            for (int mt = 0; mt < 4; mt++) {
                int rm = wm * 8 + 2 * mt + (sel & 1);
                int km = 2 * ks + (sel >> 1);
                uint32_t off = (uint32_t)(((rm << 2) + km) * 128 + rowin * 16);
                LDSM4(a[mt], sb + A_OFF + off);
            }
#pragma unroll
            for (int bt = 0; bt < 2; bt++) {
                int nm = wn * 4 + 2 * bt + (sel >> 1);
                int km = 2 * ks + (sel & 1);
                uint32_t off = (uint32_t)(((nm << 2) + km) * 128 + rowin * 16);
                uint32_t r4[4];
                LDSM4(r4, sb + B_OFF + off);
                bf[2 * bt][0] = r4[0]; bf[2 * bt][1] = r4[1];
                bf[2 * bt + 1][0] = r4[2]; bf[2 * bt + 1][1] = r4[3];
            }
#pragma unroll
            for (int mt = 0; mt < 4; mt++)
#pragma unroll
                for (int nt = 0; nt < 4; nt++)
                    MMA_F16(acc[mt][nt], a[mt], bf[nt]);
        }
        __syncthreads();
    }

#pragma unroll
    for (int mt = 0; mt < 4; mt++) {
        long row0 = bm + wm * 64 + mt * 16 + g;
#pragma unroll
        for (int nt = 0; nt < 4; nt++) {
            long col = bn + wn * 32 + nt * 8 + tq * 2;
            *(float2*)&C[row0 * N + col]       = make_float2(acc[mt][nt][0], acc[mt][nt][1]);
            *(float2*)&C[(row0 + 8) * N + col] = make_float2(acc[mt][nt][2], acc[mt][nt][3]);
        }
    }
}

// ---------------------------------------------------------------------------
// Flash attention with mma.sync (round-11 design; epilogue uses 128-row tiles)
// ---------------------------------------------------------------------------
#define FQ_OFF 1024
#define FK_OFF (1024 + 16384)
#define FV_OFF (1024 + 16384 + 16384)
#define FSTAGE 32768
#define FLASH_SMEM (1024 + 16384 + 2 * FSTAGE)

__global__ __launch_bounds__(128, 2) void flash_mma() {
    extern __shared__ char smf[];
    const uint32_t s0 = smem_u32(smf);
    const int tid  = threadIdx.x;
    const int warp = tid >> 5;
    const int lane = tid & 31;
    const int g    = lane >> 2;
    const int tq   = lane & 3;
    const int sel  = lane >> 3;
    const int rowin = lane & 7;
    const int qt = blockIdx.x, h = blockIdx.y, b = blockIdx.z;
    const int kvh = h >> 2;

    const __half* gQ = g_q16 + ((size_t)((b * NQH + h) * 16 + qt) << 13);
    const __half* gK = g_k16 + ((size_t)((b * NKV + kvh) * 16) << 13);
    const __half* gV = g_vT16 + ((size_t)((b * NKV + kvh) * 16) << 13);

    if (tid == 0) { MBAR_INIT(s0, 1); MBAR_INIT(s0 + 8, 1); }
    __syncthreads();
    const int NT = qt + 1;
    if (tid == 0) {
        MBAR_EXPECT_TX(s0, 3 * 16384);
        bulk_g2s(s0 + FQ_OFF, gQ, 16384, s0);
        bulk_g2s(s0 + FK_OFF, gK, 16384, s0);
        bulk_g2s(s0 + FV_OFF, gV, 16384, s0);
        if (NT > 1) {
            MBAR_EXPECT_TX(s0 + 8, 2 * 16384);
            bulk_g2s(s0 + FK_OFF + FSTAGE, gK + 8192, 16384, s0 + 8);
            bulk_g2s(s0 + FV_OFF + FSTAGE, gV + 8192, 16384, s0 + 8);
        }
    }

    float oacc[16][4];
#pragma unroll
    for (int i = 0; i < 16; i++)
#pragma unroll
        for (int j = 0; j < 4; j++) oacc[i][j] = 0.f;
    float m0 = -3.0e38f, m1 = -3.0e38f, l0 = 0.f, l1 = 0.f;
    const float scale = 0.08838834764831845f;

    for (int t = 0; t < NT; t++) {
        const int s = t & 1;
        mbar_wait(s0 + s * 8, (t >> 1) & 1);
        const uint32_t Qb = s0 + FQ_OFF;
        const uint32_t Kb = s0 + FK_OFF + s * FSTAGE;
        const uint32_t Vb = s0 + FV_OFF + s * FSTAGE;

        float sacc[8][4];
#pragma unroll
        for (int i = 0; i < 8; i++)
#pragma unroll
            for (int j = 0; j < 4; j++) sacc[i][j] = 0.f;

#pragma unroll
        for (int ks = 0; ks < 8; ks++) {
            uint32_t qa[4];
            {
                int rm = warp * 2 + (sel & 1);
                int km = 2 * ks + (sel >> 1);
                LDSM4(qa, Qb + (uint32_t)(((rm << 4) + km) * 128 + rowin * 16));
            }
            uint32_t kb[8][2];
#pragma unroll
            for (int bt = 0; bt < 4; bt++) {
                int nm = 2 * bt + (sel >> 1);
                int km = 2 * ks + (sel & 1);
                uint32_t r4[4];
                LDSM4(r4, Kb + (uint32_t)(((nm << 4) + km) * 128 + rowin * 16));
                kb[2 * bt][0] = r4[0]; kb[2 * bt][1] = r4[1];
                kb[2 * bt + 1][0] = r4[2]; kb[2 * bt + 1][1] = r4[3];
            }
#pragma unroll
            for (int nt = 0; nt < 8; nt++) MMA_F16(sacc[nt], qa, kb[nt]);
        }

        const bool diag = (t == qt);
#pragma unroll
        for (int nt = 0; nt < 8; nt++) {
#pragma unroll
            for (int c = 0; c < 4; c++) {
                float v = sacc[nt][c] * scale;
                if (diag) {
                    int kcol = nt * 8 + 2 * tq + (c & 1);
                    int qr = warp * 16 + g + ((c >= 2) ? 8 : 0);
                    if (kcol > qr) v = -1.0e30f;
                }
                sacc[nt][c] = v;
            }
        }

        float rm0 = -3.0e38f, rm1 = -3.0e38f;
#pragma unroll
        for (int nt = 0; nt < 8; nt++) {
            rm0 = fmaxf(rm0, fmaxf(sacc[nt][0], sacc[nt][1]));
            rm1 = fmaxf(rm1, fmaxf(sacc[nt][2], sacc[nt][3]));
        }
        rm0 = fmaxf(rm0, __shfl_xor_sync(0xffffffffu, rm0, 1));
        rm0 = fmaxf(rm0, __shfl_xor_sync(0xffffffffu, rm0, 2));
        rm1 = fmaxf(rm1, __shfl_xor_sync(0xffffffffu, rm1, 1));
        rm1 = fmaxf(rm1, __shfl_xor_sync(0xffffffffu, rm1, 2));
        float mn0 = fmaxf(m0, rm0), mn1 = fmaxf(m1, rm1);
        float a0 = expf(m0 - mn0), a1 = expf(m1 - mn1);
        m0 = mn0; m1 = mn1;
        float rs0 = 0.f, rs1 = 0.f;
#pragma unroll
        for (int nt = 0; nt < 8; nt++) {
            float p0 = expf(sacc[nt][0] - mn0);
            float p1 = expf(sacc[nt][1] - mn0);
            float p2 = expf(sacc[nt][2] - mn1);
            float p3 = expf(sacc[nt][3] - mn1);
            sacc[nt][0] = p0; sacc[nt][1] = p1; sacc[nt][2] = p2; sacc[nt][3] = p3;
            rs0 += p0 + p1; rs1 += p2 + p3;
        }
        rs0 += __shfl_xor_sync(0xffffffffu, rs0, 1);
        rs0 += __shfl_xor_sync(0xffffffffu, rs0, 2);
        rs1 += __shfl_xor_sync(0xffffffffu, rs1, 1);
        rs1 += __shfl_xor_sync(0xffffffffu, rs1, 2);
        l0 = l0 * a0 + rs0;
        l1 = l1 * a1 + rs1;
#pragma unroll
        for (int nt = 0; nt < 16; nt++) {
            oacc[nt][0] *= a0; oacc[nt][1] *= a0;
            oacc[nt][2] *= a1; oacc[nt][3] *= a1;
        }

        uint32_t pf[4][4];
#pragma unroll
        for (int s4 = 0; s4 < 4; s4++) {
            pf[s4][0] = f22u(sacc[2 * s4][0],     sacc[2 * s4][1]);
            pf[s4][1] = f22u(sacc[2 * s4][2],     sacc[2 * s4][3]);
            pf[s4][2] = f22u(sacc[2 * s4 + 1][0], sacc[2 * s4 + 1][1]);
            pf[s4][3] = f22u(sacc[2 * s4 + 1][2], sacc[2 * s4 + 1][3]);
        }

#pragma unroll
        for (int s4 = 0; s4 < 4; s4++) {
#pragma unroll
            for (int bt = 0; bt < 8; bt++) {
                int dm = 2 * bt + (sel >> 1);
                int km2 = 2 * s4 + (sel & 1);
                uint32_t r4[4];
                LDSM4(r4, Vb + (uint32_t)(((dm << 3) + km2) * 128 + rowin * 16));
                MMA_F16(oacc[2 * bt],     pf[s4], r4);
                MMA_F16(oacc[2 * bt + 1], pf[s4], (r4 + 2));
            }
        }

        __syncthreads();
        if (tid == 0 && t + 2 < NT) {
            MBAR_EXPECT_TX(s0 + s * 8, 2 * 16384);
            bulk_g2s(Kb, gK + ((size_t)(t + 2) << 13), 16384, s0 + s * 8);
            bulk_g2s(Vb, gV + ((size_t)(t + 2) << 13), 16384, s0 + s * 8);
        }
    }

    // Epilogue: normalize; write packed fp16 (128-row A tiles for GEMM2)
    float i0 = 1.0f / l0, i1 = 1.0f / l1;
    int rowg = b * SEQ + qt * 64 + warp * 16 + g;
#pragma unroll
    for (int nt = 0; nt < 16; nt++) {
        int c8 = h * 16 + nt;
        int ktl = c8 >> 2, kc = c8 & 3;
        {
            int r = rowg;
            size_t mb = r >> 7; int rr = r & 127;
            __half* d = g_attn_pk + (((mb << 7) + ktl) << 12)
                      + (((((rr >> 3) << 2) + kc) << 6) + ((rr & 7) << 3)) + 2 * tq;
            *(__half2*)d = __floats2half2_rn(oacc[nt][0] * i0, oacc[nt][1] * i0);
        }
        {
            int r = rowg + 8;
            size_t mb = r >> 7; int rr = r & 127;
            __half* d = g_attn_pk + (((mb << 7) + ktl) << 12)
                      + (((((rr >> 3) << 2) + kc) << 6) + ((rr & 7) << 3)) + 2 * tq;
            *(__half2*)d = __floats2half2_rn(oacc[nt][2] * i1, oacc[nt][3] * i1);
        }
    }
}

// ---------------------------------------------------------------------------
// Launch
// ---------------------------------------------------------------------------
extern "C" void kernel_launch(void* const* d_in, const int* in_sizes, int n_in,
                              void* d_out, int out_size) {
    const int*   positions = (const int*)d_in[0];
    const float* hidden    = (const float*)d_in[1];
    const float* w_qkv     = (const float*)d_in[2];
    const float* w_o       = (const float*)d_in[3];
    float*       out       = (float*)d_out;

    static __half *hid_pk, *wqkv_pk, *wo_pk, *attn_pk;
    static float* qkv;
    static bool init = false;
    if (!init) {
        cudaGetSymbolAddress((void**)&hid_pk,  g_hid_pk);
        cudaGetSymbolAddress((void**)&wqkv_pk, g_wqkv_pk);
        cudaGetSymbolAddress((void**)&wo_pk,   g_wo_pk);
        cudaGetSymbolAddress((void**)&attn_pk, g_attn_pk);
        cudaGetSymbolAddress((void**)&qkv,     g_qkv);
        cudaFuncSetAttribute(gemm_f16, cudaFuncAttributeMaxDynamicSharedMemorySize,
                             GEMM_SMEM);
        cudaFuncSetAttribute(flash_mma, cudaFuncAttributeMaxDynamicSharedMemorySize,
                             FLASH_SMEM);
        init = true;
    }

    rope_tab<<<(BS_ROWS * 64 + 255) / 256, 256>>>(positions);
    act_pack<<<(BS_ROWS * 512 + 255) / 256, 256>>>(hidden, hid_pk);
    split_T_pack<<<dim3(QKV_N / 32, HID / 32), dim3(32, 32)>>>(w_qkv, wqkv_pk, HID, QKV_N);
    split_T_pack<<<dim3(HID / 32, HID / 32), dim3(32, 32)>>>(w_o, wo_pk, HID, HID);

    gemm_f16<<<dim3(QKV_N / 128, BS_ROWS / 128), 256, GEMM_SMEM>>>(
        hid_pk, wqkv_pk, qkv, QKV_N, HID);

    qk_pack<<<(BS_ROWS * 40 * 32 + 255) / 256, 256>>>();
    v_pack<<<dim3(16, NKV, BATCH), 256>>>();

    flash_mma<<<dim3(SEQ / 64, NQH, BATCH), 128, FLASH_SMEM>>>();

    gemm_f16<<<dim3(HID / 128, BS_ROWS / 128), 256, GEMM_SMEM>>>(
        attn_pk, wo_pk, out, HID, HID);
}

// round 14
// speedup vs baseline: 6.1124x; 1.1203x over previous
#include <cuda_runtime.h>
#include <cuda_fp16.h>
#include <math.h>
#include <stdint.h>

// Problem constants
#define BATCH   4
#define SEQ     1024
#define HID     4096
#define NQH     32
#define NKV     8
#define HD      128
#define QKV_N   6144
#define BS_ROWS 4096

// ---------------------------------------------------------------------------
// Scratch. Tile-packed fp16 layouts (8x8-matrix contiguous, 128B per matrix).
//  A tensors: 128x32 tiles (8KB), tile (mb,kt) at ((mb*(K/32)+kt)<<12) halves.
//  B tensors: 128x32 tiles (8KB), tile (nb,kt) at ((nb*(K/32)+kt)<<12) halves.
// ---------------------------------------------------------------------------
__device__ float  g_qkv[(size_t)BS_ROWS * QKV_N];
__device__ __half g_hid_pk[(size_t)BS_ROWS * HID];
__device__ __half g_wqkv_pk[(size_t)QKV_N * HID];
__device__ __half g_wo_pk[(size_t)HID * HID];
__device__ __half g_attn_pk[(size_t)BS_ROWS * HID];
__device__ __half g_q16[(size_t)BATCH * NQH * 16 * 8192];
__device__ __half g_k16[(size_t)BATCH * NKV * 16 * 8192];
__device__ __half g_vT16[(size_t)BATCH * NKV * 16 * 8192];
__device__ float2 g_rope[(size_t)BS_ROWS * 64];            // cos/sin per (row, i)

__device__ __forceinline__ uint32_t smem_u32(const void* p) {
    uint32_t a;
    asm("{ .reg .u64 t; cvta.to.shared.u64 t, %1; cvt.u32.u64 %0, t; }" : "=r"(a) : "l"(p));
    return a;
}
__device__ __forceinline__ uint32_t f22u(float a, float b) {
    __half2 h = __floats2half2_rn(a, b);
    return *(uint32_t*)&h;
}

#define MBAR_INIT(addr, cnt) \
    asm volatile("mbarrier.init.shared.b64 [%0], %1;" :: "r"(addr), "r"(cnt) : "memory")
#define MBAR_EXPECT_TX(addr, bytes) \
    asm volatile("mbarrier.arrive.expect_tx.shared.b64 _, [%0], %1;" \
                 :: "r"(addr), "r"(bytes) : "memory")
__device__ __forceinline__ void mbar_wait(uint32_t addr, uint32_t parity) {
    asm volatile(
        "{\n\t.reg .pred P;\n\t"
        "WL%=:\n\t"
        "mbarrier.try_wait.parity.acquire.cta.shared::cta.b64 P, [%0], %1, 0x989680;\n\t"
        "@!P bra WL%=;\n\t}"
        :: "r"(addr), "r"(parity) : "memory");
}
__device__ __forceinline__ void bulk_g2s(uint32_t dst, const void* src,
                                         uint32_t bytes, uint32_t mbar) {
    asm volatile(
        "cp.async.bulk.shared::cluster.global.mbarrier::complete_tx::bytes "
        "[%0], [%1], %2, [%3];"
        :: "r"(dst), "l"(src), "r"(bytes), "r"(mbar) : "memory");
}

#define LDSM4(R, ADDR) \
    asm volatile("ldmatrix.sync.aligned.m8n8.x4.shared.b16 {%0,%1,%2,%3}, [%4];" \
                 : "=r"((R)[0]), "=r"((R)[1]), "=r"((R)[2]), "=r"((R)[3]) : "r"(ADDR))
#define MMA_F16(ACC, A, B) \
    asm volatile("mma.sync.aligned.m16n8k16.row.col.f32.f16.f16.f32 " \
                 "{%0,%1,%2,%3}, {%4,%5,%6,%7}, {%8,%9}, {%0,%1,%2,%3};" \
                 : "+f"((ACC)[0]), "+f"((ACC)[1]), "+f"((ACC)[2]), "+f"((ACC)[3]) \
                 : "r"((A)[0]), "r"((A)[1]), "r"((A)[2]), "r"((A)[3]), \
                   "r"((B)[0]), "r"((B)[1]))

// ---------------------------------------------------------------------------
// Packing kernels
// ---------------------------------------------------------------------------
// hidden f32 -> packed fp16 A tiles. Thread = one 16B chunk in OUTPUT memory
// order (tile, m, rr): writes contiguous per warp; reads tile input sectors.
__global__ void act_pack(const float* __restrict__ in, __half* __restrict__ out) {
    int e = blockIdx.x * blockDim.x + threadIdx.x;
    if (e >= BS_ROWS * 512) return;
    int tile = e >> 9;              // mb*128 + kt  (K/32 = 128)
    int mb = tile >> 7;
    int kt = tile & 127;
    int m  = (e >> 3) & 63, rr = e & 7;
    int R  = m >> 2, kc = m & 3;
    int row = (mb << 7) + R * 8 + rr;
    const float* s = in + ((size_t)row << 12) + ((kt * 4 + kc) << 3);
    float4 v0 = ((const float4*)s)[0], v1 = ((const float4*)s)[1];
    __half2 h[4];
    h[0] = __floats2half2_rn(v0.x, v0.y);
    h[1] = __floats2half2_rn(v0.z, v0.w);
    h[2] = __floats2half2_rn(v1.x, v1.y);
    h[3] = __floats2half2_rn(v1.z, v1.w);
    *(uint4*)(out + ((size_t)tile << 12) + (m << 6) + (rr << 3)) = *(uint4*)h;
}

// W[Kdim, Ndim] f32 -> packed fp16 B tiles. Block = one full tile (128n x 32k).
// Coalesced float4 loads -> smem (pad 133: conflict-free column reads) ->
// coalesced uint4 stores in output memory order.
__global__ __launch_bounds__(256)
void split_T_pack(const float* __restrict__ W, __half* __restrict__ pk,
                  int Kdim, int Ndim) {
    __shared__ float st[32][133];
    const int nb = blockIdx.x;       // 128-col group of N
    const int kt = blockIdx.y;       // 32-row group of K
    const int tid = threadIdx.x;
    const float* src = W + (size_t)(kt * 32) * Ndim + nb * 128;
#pragma unroll
    for (int i = 0; i < 4; i++) {
        int e = tid + i * 256;       // 0..1023
        int row = e >> 5;            // 0..31 (k)
        int c4  = (e & 31) << 2;     // 0..124 (n)
        float4 v = *(const float4*)(src + (size_t)row * Ndim + c4);
        st[row][c4] = v.x; st[row][c4 + 1] = v.y;
        st[row][c4 + 2] = v.z; st[row][c4 + 3] = v.w;
    }
    __syncthreads();
    __half* dst = pk + ((size_t)(nb * (Kdim >> 5) + kt) << 12);
#pragma unroll
    for (int i = 0; i < 2; i++) {
        int c = tid + i * 256;       // 0..511 (memory order)
        int m = c >> 3, rr = c & 7;
        int R = m >> 2, kc = m & 3;
        int r = R * 8 + rr;          // n index 0..127
        __half2 hv[4];
#pragma unroll
        for (int j = 0; j < 4; j++)
            hv[j] = __floats2half2_rn(st[kc * 8 + 2 * j][r], st[kc * 8 + 2 * j + 1][r]);
        *(uint4*)(dst + (m << 6) + (rr << 3)) = *(uint4*)hv;
    }
}

// RoPE cos/sin table: one entry per (row, freq index)
__global__ void rope_tab(const int* __restrict__ pos) {
    int idx = blockIdx.x * blockDim.x + threadIdx.x;
    if (idx >= BS_ROWS * 64) return;
    int i = idx & 63, row = idx >> 6;
    float ang = (float)pos[row] * expf(-(float)i * 0.14391156831212787f);
    float sn, cs;
    sincosf(ang, &sn, &cs);
    g_rope[idx] = make_float2(cs, sn);
}

// RoPE (table) + pack q/k as fp16 tiles.
__global__ void qk_pack() {
    int idx = blockIdx.x * blockDim.x + threadIdx.x;
    if (idx >= BS_ROWS * 40 * 32) return;
    int lane = idx & 31;
    int h    = (idx >> 5) % 40;
    int row  = idx / (40 * 32);
    const float* src = g_qkv + (long)row * QKV_N + h * HD;
    int i0 = 2 * lane;
    float x1a = src[i0], x1b = src[i0 + 1], x2a = src[i0 + 64], x2b = src[i0 + 65];
    float4 cssn = *(const float4*)&g_rope[(size_t)row * 64 + i0];  // (ca,sa,cb,sb)
    float ca = cssn.x, sa = cssn.y, cb = cssn.z, sb = cssn.w;
    float y1a = x1a * ca - x2a * sa, y1b = x1b * cb - x2b * sb;
    float y2a = x2a * ca + x1a * sa, y2b = x2b * cb + x1b * sb;
    int s = row & (SEQ - 1), b = row >> 10;
    int st = s >> 6, r = s & 63;
    __half* base = (h < NQH)
        ? g_q16 + ((size_t)((b * NQH + h) * 16 + st) << 13)
        : g_k16 + ((size_t)((b * NKV + (h - NQH)) * 16 + st) << 13);
    int roff = ((r >> 3) << 10) + ((r & 7) << 3);
    *(__half2*)(base + roff + ((i0 >> 3) << 6) + (i0 & 7)) = __floats2half2_rn(y1a, y1b);
    int c2 = i0 + 64;
    *(__half2*)(base + roff + ((c2 >> 3) << 6) + (c2 & 7)) = __floats2half2_rn(y2a, y2b);
}

// V f32 [s][d] -> V^T fp16 packed [128 x 64] tiles.
__global__ __launch_bounds__(256) void v_pack() {
    __shared__ float vt[64][129];
    int st = blockIdx.x, kvh = blockIdx.y, b = blockIdx.z;
    int tid = threadIdx.x;
    const float* src = g_qkv + ((long)(b * SEQ + st * 64)) * QKV_N + (NQH + NKV) * HD + kvh * HD;
    for (int e = tid; e < 64 * 32; e += 256) {
        int r = e >> 5, d4 = (e & 31) << 2;
        float4 v = *(const float4*)(src + (long)r * QKV_N + d4);
        vt[r][d4] = v.x; vt[r][d4 + 1] = v.y; vt[r][d4 + 2] = v.z; vt[r][d4 + 3] = v.w;
    }
    __syncthreads();
    __half* dst = g_vT16 + ((size_t)((b * NKV + kvh) * 16 + st) << 13);
    for (int e = tid; e < 1024; e += 256) {
        int m = e >> 3, rr = e & 7;
        int dr = ((m >> 3) << 3) + rr;
        int c0 = (m & 7) << 3;
        __half2 hv[4];
#pragma unroll
        for (int j = 0; j < 4; j++)
            hv[j] = __floats2half2_rn(vt[c0 + 2 * j][dr], vt[c0 + 2 * j + 1][dr]);
        *(uint4*)(dst + (m << 6) + (rr << 3)) = *(uint4*)hv;
    }
}

// ---------------------------------------------------------------------------
// HMMA GEMM: C[M,N] = A[M,K] @ Bt[N,K]^T, pure fp16.
// CTA 128x128, BK=32, 256 threads = 8 warps (2Mx4N), warp tile 64x32,
// 2 CTAs/SM. 2 bulk copies per K-tile, 4-stage mbarrier ring.
// ---------------------------------------------------------------------------
#define STAGE_BYTES 16384
#define NSTAGE 4
#define SMEM_TILES 1024
#define A_OFF 0
#define B_OFF 8192
#define GEMM_SMEM (SMEM_TILES + NSTAGE * STAGE_BYTES)

__global__ __launch_bounds__(256, 2)
void gemm_f16(const __half* __restrict__ Apk, const __half* __restrict__ Bpk,
              float* __restrict__ C, int N, int K)
{
    extern __shared__ char smx[];
    const uint32_t s0 = smem_u32(smx);
    const int tid  = threadIdx.x;
    const int wid  = tid >> 5;
    const int lane = tid & 31;
    const int wm   = wid >> 2;
    const int wn   = wid & 3;
    const int sel  = lane >> 3;
    const int rowin = lane & 7;
    const int g    = lane >> 2;
    const int tq   = lane & 3;
    const long bm = (long)blockIdx.y * 128;
    const long bn = (long)blockIdx.x * 128;
    const int NKT = K >> 5;

    const __half* gA = Apk + ((size_t)(blockIdx.y * NKT) << 12);
    const __half* gB = Bpk + ((size_t)(blockIdx.x * NKT) << 12);

    if (tid == 0) {
#pragma unroll
        for (int s = 0; s < NSTAGE; s++) MBAR_INIT(s0 + s * 8, 1);
    }
    __syncthreads();

    if (tid == 0) {
#pragma unroll
        for (int p = 0; p < NSTAGE - 1; p++) {
            uint32_t mb = s0 + p * 8;
            uint32_t db = s0 + SMEM_TILES + p * STAGE_BYTES;
            MBAR_EXPECT_TX(mb, 16384);
            bulk_g2s(db + A_OFF, gA + ((size_t)p << 12), 8192, mb);
            bulk_g2s(db + B_OFF, gB + ((size_t)p << 12), 8192, mb);
        }
    }

    float acc[4][4][4];
#pragma unroll
    for (int i = 0; i < 4; i++)
#pragma unroll
        for (int j = 0; j < 4; j++)
#pragma unroll
            for (int k = 0; k < 4; k++) acc[i][j][k] = 0.f;

    for (int t = 0; t < NKT; t++) {
        const int s = t & (NSTAGE - 1);
        if (tid == 0 && t + NSTAGE - 1 < NKT) {
            const int tp = t + NSTAGE - 1;
            const int sp = tp & (NSTAGE - 1);
            uint32_t mb = s0 + sp * 8;
            uint32_t db = s0 + SMEM_TILES + sp * STAGE_BYTES;
            MBAR_EXPECT_TX(mb, 16384);
            bulk_g2s(db + A_OFF, gA + ((size_t)tp << 12), 8192, mb);
            bulk_g2s(db + B_OFF, gB + ((size_t)tp << 12), 8192, mb);
        }
        mbar_wait(s0 + s * 8, (t >> 2) & 1);

        const uint32_t sb = s0 + SMEM_TILES + s * STAGE_BYTES;
#pragma unroll
        for (int ks = 0; ks < 2; ks++) {
            uint32_t a[4][4], bf[4][2];
#pragma unroll
            for (int mt = 0; mt < 4; mt++) {
                int rm = wm * 8 + 2 * mt + (sel & 1);
                int km = 2 * ks + (sel >> 1);
                uint32_t off = (uint32_t)(((rm << 2) + km) * 128 + rowin * 16);
                LDSM4(a[mt], sb + A_OFF + off);
            }
#pragma unroll
            for (int bt = 0; bt < 2; bt++) {
                int nm = wn * 4 + 2 * bt + (sel >> 1);
                int km = 2 * ks + (sel & 1);
                uint32_t off = (uint32_t)(((nm << 2) + km) * 128 + rowin * 16);
                uint32_t r4[4];
                LDSM4(r4, sb + B_OFF + off);
                bf[2 * bt][0] = r4[0]; bf[2 * bt][1] = r4[1];
                bf[2 * bt + 1][0] = r4[2]; bf[2 * bt + 1][1] = r4[3];
            }
#pragma unroll
            for (int mt = 0; mt < 4; mt++)
#pragma unroll
                for (int nt = 0; nt < 4; nt++)
                    MMA_F16(acc[mt][nt], a[mt], bf[nt]);
        }
        __syncthreads();
    }

#pragma unroll
    for (int mt = 0; mt < 4; mt++) {
        long row0 = bm + wm * 64 + mt * 16 + g;
#pragma unroll
        for (int nt = 0; nt < 4; nt++) {
            long col = bn + wn * 32 + nt * 8 + tq * 2;
            *(float2*)&C[row0 * N + col]       = make_float2(acc[mt][nt][0], acc[mt][nt][1]);
            *(float2*)&C[(row0 + 8) * N + col] = make_float2(acc[mt][nt][2], acc[mt][nt][3]);
        }
    }
}

// ---------------------------------------------------------------------------
// Flash attention with mma.sync (round-11 design; 128-row A-tile epilogue)
// ---------------------------------------------------------------------------
#define FQ_OFF 1024
#define FK_OFF (1024 + 16384)
#define FV_OFF (1024 + 16384 + 16384)
#define FSTAGE 32768
#define FLASH_SMEM (1024 + 16384 + 2 * FSTAGE)

__global__ __launch_bounds__(128, 2) void flash_mma() {
    extern __shared__ char smf[];
    const uint32_t s0 = smem_u32(smf);
    const int tid  = threadIdx.x;
    const int warp = tid >> 5;
    const int lane = tid & 31;
    const int g    = lane >> 2;
    const int tq   = lane & 3;
    const int sel  = lane >> 3;
    const int rowin = lane & 7;
    const int qt = blockIdx.x, h = blockIdx.y, b = blockIdx.z;
    const int kvh = h >> 2;

    const __half* gQ = g_q16 + ((size_t)((b * NQH + h) * 16 + qt) << 13);
    const __half* gK = g_k16 + ((size_t)((b * NKV + kvh) * 16) << 13);
    const __half* gV = g_vT16 + ((size_t)((b * NKV + kvh) * 16) << 13);

    if (tid == 0) { MBAR_INIT(s0, 1); MBAR_INIT(s0 + 8, 1); }
    __syncthreads();
    const int NT = qt + 1;
    if (tid == 0) {
        MBAR_EXPECT_TX(s0, 3 * 16384);
        bulk_g2s(s0 + FQ_OFF, gQ, 16384, s0);
        bulk_g2s(s0 + FK_OFF, gK, 16384, s0);
        bulk_g2s(s0 + FV_OFF, gV, 16384, s0);
        if (NT > 1) {
            MBAR_EXPECT_TX(s0 + 8, 2 * 16384);
            bulk_g2s(s0 + FK_OFF + FSTAGE, gK + 8192, 16384, s0 + 8);
            bulk_g2s(s0 + FV_OFF + FSTAGE, gV + 8192, 16384, s0 + 8);
        }
    }

    float oacc[16][4];
#pragma unroll
    for (int i = 0; i < 16; i++)
#pragma unroll
        for (int j = 0; j < 4; j++) oacc[i][j] = 0.f;
    float m0 = -3.0e38f, m1 = -3.0e38f, l0 = 0.f, l1 = 0.f;
    const float scale = 0.08838834764831845f;

    for (int t = 0; t < NT; t++) {
        const int s = t & 1;
        mbar_wait(s0 + s * 8, (t >> 1) & 1);
        const uint32_t Qb = s0 + FQ_OFF;
        const uint32_t Kb = s0 + FK_OFF + s * FSTAGE;
        const uint32_t Vb = s0 + FV_OFF + s * FSTAGE;

        float sacc[8][4];
#pragma unroll
        for (int i = 0; i < 8; i++)
#pragma unroll
            for (int j = 0; j < 4; j++) sacc[i][j] = 0.f;

#pragma unroll
        for (int ks = 0; ks < 8; ks++) {
            uint32_t qa[4];
            {
                int rm = warp * 2 + (sel & 1);
                int km = 2 * ks + (sel >> 1);
                LDSM4(qa, Qb + (uint32_t)(((rm << 4) + km) * 128 + rowin * 16));
            }
            uint32_t kb[8][2];
#pragma unroll
            for (int bt = 0; bt < 4; bt++) {
                int nm = 2 * bt + (sel >> 1);
                int km = 2 * ks + (sel & 1);
                uint32_t r4[4];
                LDSM4(r4, Kb + (uint32_t)(((nm << 4) + km) * 128 + rowin * 16));
                kb[2 * bt][0] = r4[0]; kb[2 * bt][1] = r4[1];
                kb[2 * bt + 1][0] = r4[2]; kb[2 * bt + 1][1] = r4[3];
            }
#pragma unroll
            for (int nt = 0; nt < 8; nt++) MMA_F16(sacc[nt], qa, kb[nt]);
        }

        const bool diag = (t == qt);
#pragma unroll
        for (int nt = 0; nt < 8; nt++) {
#pragma unroll
            for (int c = 0; c < 4; c++) {
                float v = sacc[nt][c] * scale;
                if (diag) {
                    int kcol = nt * 8 + 2 * tq + (c & 1);
                    int qr = warp * 16 + g + ((c >= 2) ? 8 : 0);
                    if (kcol > qr) v = -1.0e30f;
                }
                sacc[nt][c] = v;
            }
        }

        float rm0 = -3.0e38f, rm1 = -3.0e38f;
#pragma unroll
        for (int nt = 0; nt < 8; nt++) {
            rm0 = fmaxf(rm0, fmaxf(sacc[nt][0], sacc[nt][1]));
            rm1 = fmaxf(rm1, fmaxf(sacc[nt][2], sacc[nt][3]));
        }
        rm0 = fmaxf(rm0, __shfl_xor_sync(0xffffffffu, rm0, 1));
        rm0 = fmaxf(rm0, __shfl_xor_sync(0xffffffffu, rm0, 2));
        rm1 = fmaxf(rm1, __shfl_xor_sync(0xffffffffu, rm1, 1));
        rm1 = fmaxf(rm1, __shfl_xor_sync(0xffffffffu, rm1, 2));
        float mn0 = fmaxf(m0, rm0), mn1 = fmaxf(m1, rm1);
        float a0 = expf(m0 - mn0), a1 = expf(m1 - mn1);
        m0 = mn0; m1 = mn1;
        float rs0 = 0.f, rs1 = 0.f;
#pragma unroll
        for (int nt = 0; nt < 8; nt++) {
            float p0 = expf(sacc[nt][0] - mn0);
            float p1 = expf(sacc[nt][1] - mn0);
            float p2 = expf(sacc[nt][2] - mn1);
            float p3 = expf(sacc[nt][3] - mn1);
            sacc[nt][0] = p0; sacc[nt][1] = p1; sacc[nt][2] = p2; sacc[nt][3] = p3;
            rs0 += p0 + p1; rs1 += p2 + p3;
        }
        rs0 += __shfl_xor_sync(0xffffffffu, rs0, 1);
        rs0 += __shfl_xor_sync(0xffffffffu, rs0, 2);
        rs1 += __shfl_xor_sync(0xffffffffu, rs1, 1);
        rs1 += __shfl_xor_sync(0xffffffffu, rs1, 2);
        l0 = l0 * a0 + rs0;
        l1 = l1 * a1 + rs1;
#pragma unroll
        for (int nt = 0; nt < 16; nt++) {
            oacc[nt][0] *= a0; oacc[nt][1] *= a0;
            oacc[nt][2] *= a1; oacc[nt][3] *= a1;
        }

        uint32_t pf[4][4];
#pragma unroll
        for (int s4 = 0; s4 < 4; s4++) {
            pf[s4][0] = f22u(sacc[2 * s4][0],     sacc[2 * s4][1]);
            pf[s4][1] = f22u(sacc[2 * s4][2],     sacc[2 * s4][3]);
            pf[s4][2] = f22u(sacc[2 * s4 + 1][0], sacc[2 * s4 + 1][1]);
            pf[s4][3] = f22u(sacc[2 * s4 + 1][2], sacc[2 * s4 + 1][3]);
        }

#pragma unroll
        for (int s4 = 0; s4 < 4; s4++) {
#pragma unroll
            for (int bt = 0; bt < 8; bt++) {
                int dm = 2 * bt + (sel >> 1);
                int km2 = 2 * s4 + (sel & 1);
                uint32_t r4[4];
                LDSM4(r4, Vb + (uint32_t)(((dm << 3) + km2) * 128 + rowin * 16));
                MMA_F16(oacc[2 * bt],     pf[s4], r4);
                MMA_F16(oacc[2 * bt + 1], pf[s4], (r4 + 2));
            }
        }

        __syncthreads();
        if (tid == 0 && t + 2 < NT) {
            MBAR_EXPECT_TX(s0 + s * 8, 2 * 16384);
            bulk_g2s(Kb, gK + ((size_t)(t + 2) << 13), 16384, s0 + s * 8);
            bulk_g2s(Vb, gV + ((size_t)(t + 2) << 13), 16384, s0 + s * 8);
        }
    }

    // Epilogue: normalize; write packed fp16 (128-row A tiles for GEMM2)
    float i0 = 1.0f / l0, i1 = 1.0f / l1;
    int rowg = b * SEQ + qt * 64 + warp * 16 + g;
#pragma unroll
    for (int nt = 0; nt < 16; nt++) {
        int c8 = h * 16 + nt;
        int ktl = c8 >> 2, kc = c8 & 3;
        {
            int r = rowg;
            size_t mb = r >> 7; int rr = r & 127;
            __half* d = g_attn_pk + (((mb << 7) + ktl) << 12)
                      + (((((rr >> 3) << 2) + kc) << 6) + ((rr & 7) << 3)) + 2 * tq;
            *(__half2*)d = __floats2half2_rn(oacc[nt][0] * i0, oacc[nt][1] * i0);
        }
        {
            int r = rowg + 8;
            size_t mb = r >> 7; int rr = r & 127;
            __half* d = g_attn_pk + (((mb << 7) + ktl) << 12)
                      + (((((rr >> 3) << 2) + kc) << 6) + ((rr & 7) << 3)) + 2 * tq;
            *(__half2*)d = __floats2half2_rn(oacc[nt][2] * i1, oacc[nt][3] * i1);
        }
    }
}

// ---------------------------------------------------------------------------
// Launch
// ---------------------------------------------------------------------------
extern "C" void kernel_launch(void* const* d_in, const int* in_sizes, int n_in,
                              void* d_out, int out_size) {
    const int*   positions = (const int*)d_in[0];
    const float* hidden    = (const float*)d_in[1];
    const float* w_qkv     = (const float*)d_in[2];
    const float* w_o       = (const float*)d_in[3];
    float*       out       = (float*)d_out;

    static __half *hid_pk, *wqkv_pk, *wo_pk, *attn_pk;
    static float* qkv;
    static bool init = false;
    if (!init) {
        cudaGetSymbolAddress((void**)&hid_pk,  g_hid_pk);
        cudaGetSymbolAddress((void**)&wqkv_pk, g_wqkv_pk);
        cudaGetSymbolAddress((void**)&wo_pk,   g_wo_pk);
        cudaGetSymbolAddress((void**)&attn_pk, g_attn_pk);
        cudaGetSymbolAddress((void**)&qkv,     g_qkv);
        cudaFuncSetAttribute(gemm_f16, cudaFuncAttributeMaxDynamicSharedMemorySize,
                             GEMM_SMEM);
        cudaFuncSetAttribute(flash_mma, cudaFuncAttributeMaxDynamicSharedMemorySize,
                             FLASH_SMEM);
        init = true;
    }

    rope_tab<<<(BS_ROWS * 64 + 255) / 256, 256>>>(positions);
    act_pack<<<(BS_ROWS * 512 + 255) / 256, 256>>>(hidden, hid_pk);
    split_T_pack<<<dim3(QKV_N / 128, HID / 32), 256>>>(w_qkv, wqkv_pk, HID, QKV_N);
    split_T_pack<<<dim3(HID / 128, HID / 32), 256>>>(w_o, wo_pk, HID, HID);

    gemm_f16<<<dim3(QKV_N / 128, BS_ROWS / 128), 256, GEMM_SMEM>>>(
        hid_pk, wqkv_pk, qkv, QKV_N, HID);

    qk_pack<<<(BS_ROWS * 40 * 32 + 255) / 256, 256>>>();
    v_pack<<<dim3(16, NKV, BATCH), 256>>>();

    flash_mma<<<dim3(SEQ / 64, NQH, BATCH), 128, FLASH_SMEM>>>();

    gemm_f16<<<dim3(HID / 128, BS_ROWS / 128), 256, GEMM_SMEM>>>(
        attn_pk, wo_pk, out, HID, HID);
}

// round 15
// speedup vs baseline: 6.2346x; 1.0200x over previous
#include <cuda_runtime.h>
#include <cuda_fp16.h>
#include <math.h>
#include <stdint.h>

// Problem constants
#define BATCH   4
#define SEQ     1024
#define HID     4096
#define NQH     32
#define NKV     8
#define HD      128
#define QKV_N   6144
#define BS_ROWS 4096

// ---------------------------------------------------------------------------
// Scratch. Tile-packed fp16 layouts (8x8-matrix contiguous, 128B per matrix).
//  A tensors: 128x32 tiles (8KB), tile (mb,kt) at ((mb*(K/32)+kt)<<12) halves.
//  B tensors: 128x32 tiles (8KB), tile (nb,kt) at ((nb*(K/32)+kt)<<12) halves.
// ---------------------------------------------------------------------------
__device__ __half g_hid_pk[(size_t)BS_ROWS * HID];
__device__ __half g_wqkv_pk[(size_t)QKV_N * HID];
__device__ __half g_wo_pk[(size_t)HID * HID];
__device__ __half g_attn_pk[(size_t)BS_ROWS * HID];
__device__ __half g_q16[(size_t)BATCH * NQH * 16 * 8192];
__device__ __half g_k16[(size_t)BATCH * NKV * 16 * 8192];
__device__ __half g_vT16[(size_t)BATCH * NKV * 16 * 8192];
__device__ float2 g_rope[(size_t)BS_ROWS * 64];            // cos/sin per (row, i)

__device__ __forceinline__ uint32_t smem_u32(const void* p) {
    uint32_t a;
    asm("{ .reg .u64 t; cvta.to.shared.u64 t, %1; cvt.u32.u64 %0, t; }" : "=r"(a) : "l"(p));
    return a;
}
__device__ __forceinline__ uint32_t f22u(float a, float b) {
    __half2 h = __floats2half2_rn(a, b);
    return *(uint32_t*)&h;
}

#define MBAR_INIT(addr, cnt) \
    asm volatile("mbarrier.init.shared.b64 [%0], %1;" :: "r"(addr), "r"(cnt) : "memory")
#define MBAR_EXPECT_TX(addr, bytes) \
    asm volatile("mbarrier.arrive.expect_tx.shared.b64 _, [%0], %1;" \
                 :: "r"(addr), "r"(bytes) : "memory")
__device__ __forceinline__ void mbar_wait(uint32_t addr, uint32_t parity) {
    asm volatile(
        "{\n\t.reg .pred P;\n\t"
        "WL%=:\n\t"
        "mbarrier.try_wait.parity.acquire.cta.shared::cta.b64 P, [%0], %1, 0x989680;\n\t"
        "@!P bra WL%=;\n\t}"
        :: "r"(addr), "r"(parity) : "memory");
}
__device__ __forceinline__ void bulk_g2s(uint32_t dst, const void* src,
                                         uint32_t bytes, uint32_t mbar) {
    asm volatile(
        "cp.async.bulk.shared::cluster.global.mbarrier::complete_tx::bytes "
        "[%0], [%1], %2, [%3];"
        :: "r"(dst), "l"(src), "r"(bytes), "r"(mbar) : "memory");
}

#define LDSM4(R, ADDR) \
    asm volatile("ldmatrix.sync.aligned.m8n8.x4.shared.b16 {%0,%1,%2,%3}, [%4];" \
                 : "=r"((R)[0]), "=r"((R)[1]), "=r"((R)[2]), "=r"((R)[3]) : "r"(ADDR))
#define MMA_F16(ACC, A, B) \
    asm volatile("mma.sync.aligned.m16n8k16.row.col.f32.f16.f16.f32 " \
                 "{%0,%1,%2,%3}, {%4,%5,%6,%7}, {%8,%9}, {%0,%1,%2,%3};" \
                 : "+f"((ACC)[0]), "+f"((ACC)[1]), "+f"((ACC)[2]), "+f"((ACC)[3]) \
                 : "r"((A)[0]), "r"((A)[1]), "r"((A)[2]), "r"((A)[3]), \
                   "r"((B)[0]), "r"((B)[1]))

// ---------------------------------------------------------------------------
// Packing kernels
// ---------------------------------------------------------------------------
// hidden f32 -> packed fp16 A tiles, output-memory-order threads.
__global__ void act_pack(const float* __restrict__ in, __half* __restrict__ out) {
    int e = blockIdx.x * blockDim.x + threadIdx.x;
    if (e >= BS_ROWS * 512) return;
    int tile = e >> 9;
    int mb = tile >> 7;
    int kt = tile & 127;
    int m  = (e >> 3) & 63, rr = e & 7;
    int R  = m >> 2, kc = m & 3;
    int row = (mb << 7) + R * 8 + rr;
    const float* s = in + ((size_t)row << 12) + ((kt * 4 + kc) << 3);
    float4 v0 = ((const float4*)s)[0], v1 = ((const float4*)s)[1];
    __half2 h[4];
    h[0] = __floats2half2_rn(v0.x, v0.y);
    h[1] = __floats2half2_rn(v0.z, v0.w);
    h[2] = __floats2half2_rn(v1.x, v1.y);
    h[3] = __floats2half2_rn(v1.z, v1.w);
    *(uint4*)(out + ((size_t)tile << 12) + (m << 6) + (rr << 3)) = *(uint4*)h;
}

// W[Kdim, Ndim] f32 -> packed fp16 B tiles. Block = one full tile.
__global__ __launch_bounds__(256)
void split_T_pack(const float* __restrict__ W, __half* __restrict__ pk,
                  int Kdim, int Ndim) {
    __shared__ float st[32][133];
    const int nb = blockIdx.x;
    const int kt = blockIdx.y;
    const int tid = threadIdx.x;
    const float* src = W + (size_t)(kt * 32) * Ndim + nb * 128;
#pragma unroll
    for (int i = 0; i < 4; i++) {
        int e = tid + i * 256;
        int row = e >> 5;
        int c4  = (e & 31) << 2;
        float4 v = *(const float4*)(src + (size_t)row * Ndim + c4);
        st[row][c4] = v.x; st[row][c4 + 1] = v.y;
        st[row][c4 + 2] = v.z; st[row][c4 + 3] = v.w;
    }
    __syncthreads();
    __half* dst = pk + ((size_t)(nb * (Kdim >> 5) + kt) << 12);
#pragma unroll
    for (int i = 0; i < 2; i++) {
        int c = tid + i * 256;
        int m = c >> 3, rr = c & 7;
        int R = m >> 2, kc = m & 3;
        int r = R * 8 + rr;
        __half2 hv[4];
#pragma unroll
        for (int j = 0; j < 4; j++)
            hv[j] = __floats2half2_rn(st[kc * 8 + 2 * j][r], st[kc * 8 + 2 * j + 1][r]);
        *(uint4*)(dst + (m << 6) + (rr << 3)) = *(uint4*)hv;
    }
}

// RoPE cos/sin table: one entry per (row, freq index)
__global__ void rope_tab(const int* __restrict__ pos) {
    int idx = blockIdx.x * blockDim.x + threadIdx.x;
    if (idx >= BS_ROWS * 64) return;
    int i = idx & 63, row = idx >> 6;
    float ang = (float)pos[row] * expf(-(float)i * 0.14391156831212787f);
    float sn, cs;
    sincosf(ang, &sn, &cs);
    g_rope[idx] = make_float2(cs, sn);
}

// ---------------------------------------------------------------------------
// GEMM1 (QKV projection) with FUSED epilogue: rope+pack q/k, transpose+pack v.
// CTA 128x128 (one head per N-block), BK=32, 256 threads, 2 CTAs/SM.
// Epilogue stages acc in smem f32 [128][132] (reuses stage-buffer region).
// ---------------------------------------------------------------------------
#define STAGE_BYTES 16384
#define NSTAGE 4
#define SMEM_TILES 1024
#define A_OFF 0
#define B_OFF 8192
#define GEMM_SMEM (SMEM_TILES + NSTAGE * STAGE_BYTES)
#define QKV_SMEM  (SMEM_TILES + 128 * 132 * 4)     // 68608 >= GEMM_SMEM

__global__ __launch_bounds__(256, 2)
void gemm_qkv(const __half* __restrict__ Apk, const __half* __restrict__ Bpk)
{
    extern __shared__ char smx[];
    const uint32_t s0 = smem_u32(smx);
    const int tid  = threadIdx.x;
    const int wid  = tid >> 5;
    const int lane = tid & 31;
    const int wm   = wid >> 2;
    const int wn   = wid & 3;
    const int sel  = lane >> 3;
    const int rowin = lane & 7;
    const int g    = lane >> 2;
    const int tq   = lane & 3;
    const int NKT = HID >> 5;   // 128

    const __half* gA = Apk + ((size_t)(blockIdx.y * NKT) << 12);
    const __half* gB = Bpk + ((size_t)(blockIdx.x * NKT) << 12);

    if (tid == 0) {
#pragma unroll
        for (int s = 0; s < NSTAGE; s++) MBAR_INIT(s0 + s * 8, 1);
    }
    __syncthreads();

    if (tid == 0) {
#pragma unroll
        for (int p = 0; p < NSTAGE - 1; p++) {
            uint32_t mb = s0 + p * 8;
            uint32_t db = s0 + SMEM_TILES + p * STAGE_BYTES;
            MBAR_EXPECT_TX(mb, 16384);
            bulk_g2s(db + A_OFF, gA + ((size_t)p << 12), 8192, mb);
            bulk_g2s(db + B_OFF, gB + ((size_t)p << 12), 8192, mb);
        }
    }

    float acc[4][4][4];
#pragma unroll
    for (int i = 0; i < 4; i++)
#pragma unroll
        for (int j = 0; j < 4; j++)
#pragma unroll
            for (int k = 0; k < 4; k++) acc[i][j][k] = 0.f;

    for (int t = 0; t < NKT; t++) {
        const int s = t & (NSTAGE - 1);
        if (tid == 0 && t + NSTAGE - 1 < NKT) {
            const int tp = t + NSTAGE - 1;
            const int sp = tp & (NSTAGE - 1);
            uint32_t mb = s0 + sp * 8;
            uint32_t db = s0 + SMEM_TILES + sp * STAGE_BYTES;
            MBAR_EXPECT_TX(mb, 16384);
            bulk_g2s(db + A_OFF, gA + ((size_t)tp << 12), 8192, mb);
            bulk_g2s(db + B_OFF, gB + ((size_t)tp << 12), 8192, mb);
        }
        mbar_wait(s0 + s * 8, (t >> 2) & 1);

        const uint32_t sb = s0 + SMEM_TILES + s * STAGE_BYTES;
#pragma unroll
        for (int ks = 0; ks < 2; ks++) {
            uint32_t a[4][4], bf[4][2];
#pragma unroll
            for (int mt = 0; mt < 4; mt++) {
                int rm = wm * 8 + 2 * mt + (sel & 1);
                int km = 2 * ks + (sel >> 1);
                uint32_t off = (uint32_t)(((rm << 2) + km) * 128 + rowin * 16);
                LDSM4(a[mt], sb + A_OFF + off);
            }
#pragma unroll
            for (int bt = 0; bt < 2; bt++) {
                int nm = wn * 4 + 2 * bt + (sel >> 1);
                int km = 2 * ks + (sel & 1);
                uint32_t off = (uint32_t)(((nm << 2) + km) * 128 + rowin * 16);
                uint32_t r4[4];
                LDSM4(r4, sb + B_OFF + off);
                bf[2 * bt][0] = r4[0]; bf[2 * bt][1] = r4[1];
                bf[2 * bt + 1][0] = r4[2]; bf[2 * bt + 1][1] = r4[3];
            }
#pragma unroll
            for (int mt = 0; mt < 4; mt++)
#pragma unroll
                for (int nt = 0; nt < 4; nt++)
                    MMA_F16(acc[mt][nt], a[mt], bf[nt]);
        }
        __syncthreads();
    }

    // ---- Fused epilogue: stage acc to smem f32 [128][132] ----
    float* stf = (float*)(smx + SMEM_TILES);
#pragma unroll
    for (int mt = 0; mt < 4; mt++) {
        int r0 = wm * 64 + mt * 16 + g;
#pragma unroll
        for (int nt = 0; nt < 4; nt++) {
            int c = wn * 32 + nt * 8 + tq * 2;
            *(float2*)&stf[r0 * 132 + c]       = make_float2(acc[mt][nt][0], acc[mt][nt][1]);
            *(float2*)&stf[(r0 + 8) * 132 + c] = make_float2(acc[mt][nt][2], acc[mt][nt][3]);
        }
    }
    __syncthreads();

    const int hidx = blockIdx.x;                 // head index 0..47
    const int mb   = blockIdx.y;                 // 128-row block of B*S
    const int gb   = (mb << 7) >> 10;            // batch
    const int st0  = ((mb << 7) & (SEQ - 1)) >> 6;

    if (hidx < NQH + NKV) {
        // q/k head: rope + pack into 64x128 tiles
        __half* baseg = (hidx < NQH)
            ? g_q16 + ((size_t)((gb * NQH + hidx) * 16 + st0) << 13)
            : g_k16 + ((size_t)((gb * NKV + (hidx - NQH)) * 16 + st0) << 13);
        for (int e = tid; e < 4096; e += 256) {
            int row = e >> 5;
            int i0  = (e & 31) << 1;
            float x1a = stf[row * 132 + i0];
            float x1b = stf[row * 132 + i0 + 1];
            float x2a = stf[row * 132 + i0 + 64];
            float x2b = stf[row * 132 + i0 + 65];
            float4 cssn = *(const float4*)&g_rope[((size_t)(mb << 7) + row) * 64 + i0];
            float y1a = x1a * cssn.x - x2a * cssn.y;
            float y1b = x1b * cssn.z - x2b * cssn.w;
            float y2a = x2a * cssn.x + x1a * cssn.y;
            float y2b = x2b * cssn.z + x1b * cssn.w;
            int stl = row >> 6, r = row & 63;
            __half* bp = baseg + (stl << 13);
            int roff = ((r >> 3) << 10) + ((r & 7) << 3);
            *(__half2*)(bp + roff + ((i0 >> 3) << 6) + (i0 & 7)) = __floats2half2_rn(y1a, y1b);
            int c2 = i0 + 64;
            *(__half2*)(bp + roff + ((c2 >> 3) << 6) + (c2 & 7)) = __floats2half2_rn(y2a, y2b);
        }
    } else {
        // v head: transpose into V^T [128 d][64 k] tiles
        int kvh = hidx - (NQH + NKV);
        __half* dst0 = g_vT16 + ((size_t)((gb * NKV + kvh) * 16 + st0) << 13);
        for (int e = tid; e < 2048; e += 256) {
            int stl = e >> 10;
            int c = e & 1023;
            int m = c >> 3, rr = c & 7;
            int dr = ((m >> 3) << 3) + rr;       // d row in vT
            int k0 = (m & 7) << 3;               // k col base
            __half2 hv[4];
#pragma unroll
            for (int j = 0; j < 4; j++)
                hv[j] = __floats2half2_rn(stf[(stl * 64 + k0 + 2 * j) * 132 + dr],
                                          stf[(stl * 64 + k0 + 2 * j + 1) * 132 + dr]);
            *(uint4*)(dst0 + (stl << 13) + (m << 6) + (rr << 3)) = *(uint4*)hv;
        }
    }
}

// ---------------------------------------------------------------------------
// Generic HMMA GEMM (GEMM2): C[M,N] = A @ B^T, fp16, f32 out.
// ---------------------------------------------------------------------------
__global__ __launch_bounds__(256, 2)
void gemm_f16(const __half* __restrict__ Apk, const __half* __restrict__ Bpk,
              float* __restrict__ C, int N, int K)
{
    extern __shared__ char smx[];
    const uint32_t s0 = smem_u32(smx);
    const int tid  = threadIdx.x;
    const int wid  = tid >> 5;
    const int lane = tid & 31;
    const int wm   = wid >> 2;
    const int wn   = wid & 3;
    const int sel  = lane >> 3;
    const int rowin = lane & 7;
    const int g    = lane >> 2;
    const int tq   = lane & 3;
    const long bm = (long)blockIdx.y * 128;
    const long bn = (long)blockIdx.x * 128;
    const int NKT = K >> 5;

    const __half* gA = Apk + ((size_t)(blockIdx.y * NKT) << 12);
    const __half* gB = Bpk + ((size_t)(blockIdx.x * NKT) << 12);

    if (tid == 0) {
#pragma unroll
        for (int s = 0; s < NSTAGE; s++) MBAR_INIT(s0 + s * 8, 1);
    }
    __syncthreads();

    if (tid == 0) {
#pragma unroll
        for (int p = 0; p < NSTAGE - 1; p++) {
            uint32_t mb = s0 + p * 8;
            uint32_t db = s0 + SMEM_TILES + p * STAGE_BYTES;
            MBAR_EXPECT_TX(mb, 16384);
            bulk_g2s(db + A_OFF, gA + ((size_t)p << 12), 8192, mb);
            bulk_g2s(db + B_OFF, gB + ((size_t)p << 12), 8192, mb);
        }
    }

    float acc[4][4][4];
#pragma unroll
    for (int i = 0; i < 4; i++)
#pragma unroll
        for (int j = 0; j < 4; j++)
#pragma unroll
            for (int k = 0; k < 4; k++) acc[i][j][k] = 0.f;

    for (int t = 0; t < NKT; t++) {
        const int s = t & (NSTAGE - 1);
        if (tid == 0 && t + NSTAGE - 1 < NKT) {
            const int tp = t + NSTAGE - 1;
            const int sp = tp & (NSTAGE - 1);
            uint32_t mb = s0 + sp * 8;
            uint32_t db = s0 + SMEM_TILES + sp * STAGE_BYTES;
            MBAR_EXPECT_TX(mb, 16384);
            bulk_g2s(db + A_OFF, gA + ((size_t)tp << 12), 8192, mb);
            bulk_g2s(db + B_OFF, gB + ((size_t)tp << 12), 8192, mb);
        }
        mbar_wait(s0 + s * 8, (t >> 2) & 1);

        const uint32_t sb = s0 + SMEM_TILES + s * STAGE_BYTES;
#pragma unroll
        for (int ks = 0; ks < 2; ks++) {
            uint32_t a[4][4], bf[4][2];
#pragma unroll
            for (int mt = 0; mt < 4; mt++) {
                int rm = wm * 8 + 2 * mt + (sel & 1);
                int km = 2 * ks + (sel >> 1);
                uint32_t off = (uint32_t)(((rm << 2) + km) * 128 + rowin * 16);
                LDSM4(a[mt], sb + A_OFF + off);
            }
#pragma unroll
            for (int bt = 0; bt < 2; bt++) {
                int nm = wn * 4 + 2 * bt + (sel >> 1);
                int km = 2 * ks + (sel & 1);
                uint32_t off = (uint32_t)(((nm << 2) + km) * 128 + rowin * 16);
                uint32_t r4[4];
                LDSM4(r4, sb + B_OFF + off);
                bf[2 * bt][0] = r4[0]; bf[2 * bt][1] = r4[1];
                bf[2 * bt + 1][0] = r4[2]; bf[2 * bt + 1][1] = r4[3];
            }
#pragma unroll
            for (int mt = 0; mt < 4; mt++)
#pragma unroll
                for (int nt = 0; nt < 4; nt++)
                    MMA_F16(acc[mt][nt], a[mt], bf[nt]);
        }
        __syncthreads();
    }

#pragma unroll
    for (int mt = 0; mt < 4; mt++) {
        long row0 = bm + wm * 64 + mt * 16 + g;
#pragma unroll
        for (int nt = 0; nt < 4; nt++) {
            long col = bn + wn * 32 + nt * 8 + tq * 2;
            *(float2*)&C[row0 * N + col]       = make_float2(acc[mt][nt][0], acc[mt][nt][1]);
            *(float2*)&C[(row0 + 8) * N + col] = make_float2(acc[mt][nt][2], acc[mt][nt][3]);
        }
    }
}

// ---------------------------------------------------------------------------
// Flash attention with mma.sync (unchanged)
// ---------------------------------------------------------------------------
#define FQ_OFF 1024
#define FK_OFF (1024 + 16384)
#define FV_OFF (1024 + 16384 + 16384)
#define FSTAGE 32768
#define FLASH_SMEM (1024 + 16384 + 2 * FSTAGE)

__global__ __launch_bounds__(128, 2) void flash_mma() {
    extern __shared__ char smf[];
    const uint32_t s0 = smem_u32(smf);
    const int tid  = threadIdx.x;
    const int warp = tid >> 5;
    const int lane = tid & 31;
    const int g    = lane >> 2;
    const int tq   = lane & 3;
    const int sel  = lane >> 3;
    const int rowin = lane & 7;
    const int qt = blockIdx.x, h = blockIdx.y, b = blockIdx.z;
    const int kvh = h >> 2;

    const __half* gQ = g_q16 + ((size_t)((b * NQH + h) * 16 + qt) << 13);
    const __half* gK = g_k16 + ((size_t)((b * NKV + kvh) * 16) << 13);
    const __half* gV = g_vT16 + ((size_t)((b * NKV + kvh) * 16) << 13);

    if (tid == 0) { MBAR_INIT(s0, 1); MBAR_INIT(s0 + 8, 1); }
    __syncthreads();
    const int NT = qt + 1;
    if (tid == 0) {
        MBAR_EXPECT_TX(s0, 3 * 16384);
        bulk_g2s(s0 + FQ_OFF, gQ, 16384, s0);
        bulk_g2s(s0 + FK_OFF, gK, 16384, s0);
        bulk_g2s(s0 + FV_OFF, gV, 16384, s0);
        if (NT > 1) {
            MBAR_EXPECT_TX(s0 + 8, 2 * 16384);
            bulk_g2s(s0 + FK_OFF + FSTAGE, gK + 8192, 16384, s0 + 8);
            bulk_g2s(s0 + FV_OFF + FSTAGE, gV + 8192, 16384, s0 + 8);
        }
    }

    float oacc[16][4];
#pragma unroll
    for (int i = 0; i < 16; i++)
#pragma unroll
        for (int j = 0; j < 4; j++) oacc[i][j] = 0.f;
    float m0 = -3.0e38f, m1 = -3.0e38f, l0 = 0.f, l1 = 0.f;
    const float scale = 0.08838834764831845f;

    for (int t = 0; t < NT; t++) {
        const int s = t & 1;
        mbar_wait(s0 + s * 8, (t >> 1) & 1);
        const uint32_t Qb = s0 + FQ_OFF;
        const uint32_t Kb = s0 + FK_OFF + s * FSTAGE;
        const uint32_t Vb = s0 + FV_OFF + s * FSTAGE;

        float sacc[8][4];
#pragma unroll
        for (int i = 0; i < 8; i++)
#pragma unroll
            for (int j = 0; j < 4; j++) sacc[i][j] = 0.f;

#pragma unroll
        for (int ks = 0; ks < 8; ks++) {
            uint32_t qa[4];
            {
                int rm = warp * 2 + (sel & 1);
                int km = 2 * ks + (sel >> 1);
                LDSM4(qa, Qb + (uint32_t)(((rm << 4) + km) * 128 + rowin * 16));
            }
            uint32_t kb[8][2];
#pragma unroll
            for (int bt = 0; bt < 4; bt++) {
                int nm = 2 * bt + (sel >> 1);
                int km = 2 * ks + (sel & 1);
                uint32_t r4[4];
                LDSM4(r4, Kb + (uint32_t)(((nm << 4) + km) * 128 + rowin * 16));
                kb[2 * bt][0] = r4[0]; kb[2 * bt][1] = r4[1];
                kb[2 * bt + 1][0] = r4[2]; kb[2 * bt + 1][1] = r4[3];
            }
#pragma unroll
            for (int nt = 0; nt < 8; nt++) MMA_F16(sacc[nt], qa, kb[nt]);
        }

        const bool diag = (t == qt);
#pragma unroll
        for (int nt = 0; nt < 8; nt++) {
#pragma unroll
            for (int c = 0; c < 4; c++) {
                float v = sacc[nt][c] * scale;
                if (diag) {
                    int kcol = nt * 8 + 2 * tq + (c & 1);
                    int qr = warp * 16 + g + ((c >= 2) ? 8 : 0);
                    if (kcol > qr) v = -1.0e30f;
                }
                sacc[nt][c] = v;
            }
        }

        float rm0 = -3.0e38f, rm1 = -3.0e38f;
#pragma unroll
        for (int nt = 0; nt < 8; nt++) {
            rm0 = fmaxf(rm0, fmaxf(sacc[nt][0], sacc[nt][1]));
            rm1 = fmaxf(rm1, fmaxf(sacc[nt][2], sacc[nt][3]));
        }
        rm0 = fmaxf(rm0, __shfl_xor_sync(0xffffffffu, rm0, 1));
        rm0 = fmaxf(rm0, __shfl_xor_sync(0xffffffffu, rm0, 2));
        rm1 = fmaxf(rm1, __shfl_xor_sync(0xffffffffu, rm1, 1));
        rm1 = fmaxf(rm1, __shfl_xor_sync(0xffffffffu, rm1, 2));
        float mn0 = fmaxf(m0, rm0), mn1 = fmaxf(m1, rm1);
        float a0 = expf(m0 - mn0), a1 = expf(m1 - mn1);
        m0 = mn0; m1 = mn1;
        float rs0 = 0.f, rs1 = 0.f;
#pragma unroll
        for (int nt = 0; nt < 8; nt++) {
            float p0 = expf(sacc[nt][0] - mn0);
            float p1 = expf(sacc[nt][1] - mn0);
            float p2 = expf(sacc[nt][2] - mn1);
            float p3 = expf(sacc[nt][3] - mn1);
            sacc[nt][0] = p0; sacc[nt][1] = p1; sacc[nt][2] = p2; sacc[nt][3] = p3;
            rs0 += p0 + p1; rs1 += p2 + p3;
        }
        rs0 += __shfl_xor_sync(0xffffffffu, rs0, 1);
        rs0 += __shfl_xor_sync(0xffffffffu, rs0, 2);
        rs1 += __shfl_xor_sync(0xffffffffu, rs1, 1);
        rs1 += __shfl_xor_sync(0xffffffffu, rs1, 2);
        l0 = l0 * a0 + rs0;
        l1 = l1 * a1 + rs1;
#pragma unroll
        for (int nt = 0; nt < 16; nt++) {
            oacc[nt][0] *= a0; oacc[nt][1] *= a0;
            oacc[nt][2] *= a1; oacc[nt][3] *= a1;
        }

        uint32_t pf[4][4];
#pragma unroll
        for (int s4 = 0; s4 < 4; s4++) {
            pf[s4][0] = f22u(sacc[2 * s4][0],     sacc[2 * s4][1]);
            pf[s4][1] = f22u(sacc[2 * s4][2],     sacc[2 * s4][3]);
            pf[s4][2] = f22u(sacc[2 * s4 + 1][0], sacc[2 * s4 + 1][1]);
            pf[s4][3] = f22u(sacc[2 * s4 + 1][2], sacc[2 * s4 + 1][3]);
        }

#pragma unroll
        for (int s4 = 0; s4 < 4; s4++) {
#pragma unroll
            for (int bt = 0; bt < 8; bt++) {
                int dm = 2 * bt + (sel >> 1);
                int km2 = 2 * s4 + (sel & 1);
                uint32_t r4[4];
                LDSM4(r4, Vb + (uint32_t)(((dm << 3) + km2) * 128 + rowin * 16));
                MMA_F16(oacc[2 * bt],     pf[s4], r4);
                MMA_F16(oacc[2 * bt + 1], pf[s4], (r4 + 2));
            }
        }

        __syncthreads();
        if (tid == 0 && t + 2 < NT) {
            MBAR_EXPECT_TX(s0 + s * 8, 2 * 16384);
            bulk_g2s(Kb, gK + ((size_t)(t + 2) << 13), 16384, s0 + s * 8);
            bulk_g2s(Vb, gV + ((size_t)(t + 2) << 13), 16384, s0 + s * 8);
        }
    }

    // Epilogue: normalize; write packed fp16 (128-row A tiles for GEMM2)
    float i0 = 1.0f / l0, i1 = 1.0f / l1;
    int rowg = b * SEQ + qt * 64 + warp * 16 + g;
#pragma unroll
    for (int nt = 0; nt < 16; nt++) {
        int c8 = h * 16 + nt;
        int ktl = c8 >> 2, kc = c8 & 3;
        {
            int r = rowg;
            size_t mb = r >> 7; int rr = r & 127;
            __half* d = g_attn_pk + (((mb << 7) + ktl) << 12)
                      + (((((rr >> 3) << 2) + kc) << 6) + ((rr & 7) << 3)) + 2 * tq;
            *(__half2*)d = __floats2half2_rn(oacc[nt][0] * i0, oacc[nt][1] * i0);
        }
        {
            int r = rowg + 8;
            size_t mb = r >> 7; int rr = r & 127;
            __half* d = g_attn_pk + (((mb << 7) + ktl) << 12)
                      + (((((rr >> 3) << 2) + kc) << 6) + ((rr & 7) << 3)) + 2 * tq;
            *(__half2*)d = __floats2half2_rn(oacc[nt][2] * i1, oacc[nt][3] * i1);
        }
    }
}

// ---------------------------------------------------------------------------
// Launch
// ---------------------------------------------------------------------------
extern "C" void kernel_launch(void* const* d_in, const int* in_sizes, int n_in,
                              void* d_out, int out_size) {
    const int*   positions = (const int*)d_in[0];
    const float* hidden    = (const float*)d_in[1];
    const float* w_qkv     = (const float*)d_in[2];
    const float* w_o       = (const float*)d_in[3];
    float*       out       = (float*)d_out;

    static __half *hid_pk, *wqkv_pk, *wo_pk, *attn_pk;
    static bool init = false;
    if (!init) {
        cudaGetSymbolAddress((void**)&hid_pk,  g_hid_pk);
        cudaGetSymbolAddress((void**)&wqkv_pk, g_wqkv_pk);
        cudaGetSymbolAddress((void**)&wo_pk,   g_wo_pk);
        cudaGetSymbolAddress((void**)&attn_pk, g_attn_pk);
        cudaFuncSetAttribute(gemm_qkv, cudaFuncAttributeMaxDynamicSharedMemorySize,
                             QKV_SMEM);
        cudaFuncSetAttribute(gemm_f16, cudaFuncAttributeMaxDynamicSharedMemorySize,
                             GEMM_SMEM);
        cudaFuncSetAttribute(flash_mma, cudaFuncAttributeMaxDynamicSharedMemorySize,
                             FLASH_SMEM);
        init = true;
    }

    rope_tab<<<(BS_ROWS * 64 + 255) / 256, 256>>>(positions);
    act_pack<<<(BS_ROWS * 512 + 255) / 256, 256>>>(hidden, hid_pk);
    split_T_pack<<<dim3(QKV_N / 128, HID / 32), 256>>>(w_qkv, wqkv_pk, HID, QKV_N);
    split_T_pack<<<dim3(HID / 128, HID / 32), 256>>>(w_o, wo_pk, HID, HID);

    // QKV projection with fused rope/pack epilogue
    gemm_qkv<<<dim3(QKV_N / 128, BS_ROWS / 128), 256, QKV_SMEM>>>(hid_pk, wqkv_pk);

    flash_mma<<<dim3(SEQ / 64, NQH, BATCH), 128, FLASH_SMEM>>>();

    gemm_f16<<<dim3(HID / 128, BS_ROWS / 128), 256, GEMM_SMEM>>>(
        attn_pk, wo_pk, out, HID, HID);
}

// round 16
// speedup vs baseline: 6.3867x; 1.0244x over previous
#include <cuda_runtime.h>
#include <cuda_fp16.h>
#include <math.h>
#include <stdint.h>

// Problem constants
#define BATCH   4
#define SEQ     1024
#define HID     4096
#define NQH     32
#define NKV     8
#define HD      128
#define QKV_N   6144
#define BS_ROWS 4096

// ---------------------------------------------------------------------------
// Scratch. Tile-packed fp16 layouts (8x8-matrix contiguous, 128B per matrix).
//  A/B tensors: 128x32 tiles (8KB), tile (xb,kt) at ((xb*(K/32)+kt)<<12) halves.
//  Consecutive kt tiles are contiguous -> one 16KB bulk copy = 64 k-cols.
// ---------------------------------------------------------------------------
__device__ __half g_hid_pk[(size_t)BS_ROWS * HID];
__device__ __half g_wqkv_pk[(size_t)QKV_N * HID];
__device__ __half g_wo_pk[(size_t)HID * HID];
__device__ __half g_attn_pk[(size_t)BS_ROWS * HID];
__device__ __half g_q16[(size_t)BATCH * NQH * 16 * 8192];
__device__ __half g_k16[(size_t)BATCH * NKV * 16 * 8192];
__device__ __half g_vT16[(size_t)BATCH * NKV * 16 * 8192];
__device__ float2 g_rope[(size_t)BS_ROWS * 64];

__device__ __forceinline__ uint32_t smem_u32(const void* p) {
    uint32_t a;
    asm("{ .reg .u64 t; cvta.to.shared.u64 t, %1; cvt.u32.u64 %0, t; }" : "=r"(a) : "l"(p));
    return a;
}
__device__ __forceinline__ uint32_t f22u(float a, float b) {
    __half2 h = __floats2half2_rn(a, b);
    return *(uint32_t*)&h;
}

#define MBAR_INIT(addr, cnt) \
    asm volatile("mbarrier.init.shared.b64 [%0], %1;" :: "r"(addr), "r"(cnt) : "memory")
#define MBAR_EXPECT_TX(addr, bytes) \
    asm volatile("mbarrier.arrive.expect_tx.shared.b64 _, [%0], %1;" \
                 :: "r"(addr), "r"(bytes) : "memory")
__device__ __forceinline__ void mbar_wait(uint32_t addr, uint32_t parity) {
    asm volatile(
        "{\n\t.reg .pred P;\n\t"
        "WL%=:\n\t"
        "mbarrier.try_wait.parity.acquire.cta.shared::cta.b64 P, [%0], %1, 0x989680;\n\t"
        "@!P bra WL%=;\n\t}"
        :: "r"(addr), "r"(parity) : "memory");
}
__device__ __forceinline__ void bulk_g2s(uint32_t dst, const void* src,
                                         uint32_t bytes, uint32_t mbar) {
    asm volatile(
        "cp.async.bulk.shared::cluster.global.mbarrier::complete_tx::bytes "
        "[%0], [%1], %2, [%3];"
        :: "r"(dst), "l"(src), "r"(bytes), "r"(mbar) : "memory");
}

#define LDSM4(R, ADDR) \
    asm volatile("ldmatrix.sync.aligned.m8n8.x4.shared.b16 {%0,%1,%2,%3}, [%4];" \
                 : "=r"((R)[0]), "=r"((R)[1]), "=r"((R)[2]), "=r"((R)[3]) : "r"(ADDR))
#define MMA_F16(ACC, A, B) \
    asm volatile("mma.sync.aligned.m16n8k16.row.col.f32.f16.f16.f32 " \
                 "{%0,%1,%2,%3}, {%4,%5,%6,%7}, {%8,%9}, {%0,%1,%2,%3};" \
                 : "+f"((ACC)[0]), "+f"((ACC)[1]), "+f"((ACC)[2]), "+f"((ACC)[3]) \
                 : "r"((A)[0]), "r"((A)[1]), "r"((A)[2]), "r"((A)[3]), \
                   "r"((B)[0]), "r"((B)[1]))

// ---------------------------------------------------------------------------
// Packing kernels (unchanged from round 15)
// ---------------------------------------------------------------------------
__global__ void act_pack(const float* __restrict__ in, __half* __restrict__ out) {
    int e = blockIdx.x * blockDim.x + threadIdx.x;
    if (e >= BS_ROWS * 512) return;
    int tile = e >> 9;
    int mb = tile >> 7;
    int kt = tile & 127;
    int m  = (e >> 3) & 63, rr = e & 7;
    int R  = m >> 2, kc = m & 3;
    int row = (mb << 7) + R * 8 + rr;
    const float* s = in + ((size_t)row << 12) + ((kt * 4 + kc) << 3);
    float4 v0 = ((const float4*)s)[0], v1 = ((const float4*)s)[1];
    __half2 h[4];
    h[0] = __floats2half2_rn(v0.x, v0.y);
    h[1] = __floats2half2_rn(v0.z, v0.w);
    h[2] = __floats2half2_rn(v1.x, v1.y);
    h[3] = __floats2half2_rn(v1.z, v1.w);
    *(uint4*)(out + ((size_t)tile << 12) + (m << 6) + (rr << 3)) = *(uint4*)h;
}

__global__ __launch_bounds__(256)
void split_T_pack(const float* __restrict__ W, __half* __restrict__ pk,
                  int Kdim, int Ndim) {
    __shared__ float st[32][133];
    const int nb = blockIdx.x;
    const int kt = blockIdx.y;
    const int tid = threadIdx.x;
    const float* src = W + (size_t)(kt * 32) * Ndim + nb * 128;
#pragma unroll
    for (int i = 0; i < 4; i++) {
        int e = tid + i * 256;
        int row = e >> 5;
        int c4  = (e & 31) << 2;
        float4 v = *(const float4*)(src + (size_t)row * Ndim + c4);
        st[row][c4] = v.x; st[row][c4 + 1] = v.y;
        st[row][c4 + 2] = v.z; st[row][c4 + 3] = v.w;
    }
    __syncthreads();
    __half* dst = pk + ((size_t)(nb * (Kdim >> 5) + kt) << 12);
#pragma unroll
    for (int i = 0; i < 2; i++) {
        int c = tid + i * 256;
        int m = c >> 3, rr = c & 7;
        int R = m >> 2, kc = m & 3;
        int r = R * 8 + rr;
        __half2 hv[4];
#pragma unroll
        for (int j = 0; j < 4; j++)
            hv[j] = __floats2half2_rn(st[kc * 8 + 2 * j][r], st[kc * 8 + 2 * j + 1][r]);
        *(uint4*)(dst + (m << 6) + (rr << 3)) = *(uint4*)hv;
    }
}

__global__ void rope_tab(const int* __restrict__ pos) {
    int idx = blockIdx.x * blockDim.x + threadIdx.x;
    if (idx >= BS_ROWS * 64) return;
    int i = idx & 63, row = idx >> 6;
    float ang = (float)pos[row] * expf(-(float)i * 0.14391156831212787f);
    float sn, cs;
    sincosf(ang, &sn, &cs);
    g_rope[idx] = make_float2(cs, sn);
}

// ---------------------------------------------------------------------------
// GEMM core: BK=64, 3-stage ring (32KB stage: A 16KB | B 16KB), 256 threads,
// 8 warps (2Mx4N), warp tile 64x32, 2 CTAs/SM.
// ---------------------------------------------------------------------------
#define STAGE_BYTES 32768
#define NSTAGE 3
#define SMEM_TILES 1024
#define A_OFF 0
#define B_OFF 16384
#define GEMM_SMEM (SMEM_TILES + NSTAGE * STAGE_BYTES)     // 99328
#define QKV_SMEM  GEMM_SMEM                               // epilogue fits in stages

// Mainloop shared by both GEMMs (acc left in registers).
#define GEMM_MAINLOOP(gA, gB, NKT)                                              \
    if (tid == 0) {                                                             \
        for (int s = 0; s < NSTAGE; s++) MBAR_INIT(s0 + s * 8, 1);              \
    }                                                                           \
    __syncthreads();                                                            \
    if (tid == 0) {                                                             \
        for (int p = 0; p < 2; p++) {                                           \
            uint32_t mb = s0 + p * 8;                                           \
            uint32_t db = s0 + SMEM_TILES + p * STAGE_BYTES;                    \
            MBAR_EXPECT_TX(mb, 32768);                                          \
            bulk_g2s(db + A_OFF, (gA) + ((size_t)p << 13), 16384, mb);          \
            bulk_g2s(db + B_OFF, (gB) + ((size_t)p << 13), 16384, mb);          \
        }                                                                       \
    }                                                                           \
    int s_cur = 0, s_nxt = 2;                                                   \
    uint32_t ph0 = 0, ph1 = 0, ph2 = 0;                                         \
    for (int t = 0; t < (NKT); t++) {                                           \
        if (tid == 0 && t + 2 < (NKT)) {                                        \
            uint32_t mb = s0 + s_nxt * 8;                                       \
            uint32_t db = s0 + SMEM_TILES + s_nxt * STAGE_BYTES;                \
            MBAR_EXPECT_TX(mb, 32768);                                          \
            bulk_g2s(db + A_OFF, (gA) + ((size_t)(t + 2) << 13), 16384, mb);    \
            bulk_g2s(db + B_OFF, (gB) + ((size_t)(t + 2) << 13), 16384, mb);    \
        }                                                                       \
        uint32_t phc = (s_cur == 0) ? ph0 : (s_cur == 1) ? ph1 : ph2;           \
        mbar_wait(s0 + s_cur * 8, phc);                                         \
        if (s_cur == 0) ph0 ^= 1; else if (s_cur == 1) ph1 ^= 1; else ph2 ^= 1; \
        const uint32_t sb = s0 + SMEM_TILES + s_cur * STAGE_BYTES;              \
        _Pragma("unroll")                                                       \
        for (int ks = 0; ks < 4; ks++) {                                        \
            const uint32_t ab = sb + A_OFF + ((ks >> 1) << 13);                 \
            const uint32_t bb = sb + B_OFF + ((ks >> 1) << 13);                 \
            const int kl = ks & 1;                                              \
            uint32_t a[4][4], bf[4][2];                                         \
            _Pragma("unroll")                                                   \
            for (int mt = 0; mt < 4; mt++) {                                    \
                int rm = wm * 8 + 2 * mt + (sel & 1);                           \
                int km = 2 * kl + (sel >> 1);                                   \
                LDSM4(a[mt], ab + (uint32_t)(((rm << 2) + km) * 128 + rowin * 16)); \
            }                                                                   \
            _Pragma("unroll")                                                   \
            for (int bt = 0; bt < 2; bt++) {                                    \
                int nm = wn * 4 + 2 * bt + (sel >> 1);                          \
                int km = 2 * kl + (sel & 1);                                    \
                uint32_t r4[4];                                                 \
                LDSM4(r4, bb + (uint32_t)(((nm << 2) + km) * 128 + rowin * 16));\
                bf[2 * bt][0] = r4[0]; bf[2 * bt][1] = r4[1];                   \
                bf[2 * bt + 1][0] = r4[2]; bf[2 * bt + 1][1] = r4[3];           \
            }                                                                   \
            _Pragma("unroll")                                                   \
            for (int mt = 0; mt < 4; mt++)                                      \
                _Pragma("unroll")                                               \
                for (int nt = 0; nt < 4; nt++)                                  \
                    MMA_F16(acc[mt][nt], a[mt], bf[nt]);                        \
        }                                                                       \
        __syncthreads();                                                        \
        s_cur = (s_cur == 2) ? 0 : s_cur + 1;                                   \
        s_nxt = (s_nxt == 2) ? 0 : s_nxt + 1;                                   \
    }

// GEMM1 (QKV) with fused rope/pack epilogue.
__global__ __launch_bounds__(256, 2)
void gemm_qkv(const __half* __restrict__ Apk, const __half* __restrict__ Bpk)
{
    extern __shared__ char smx[];
    const uint32_t s0 = smem_u32(smx);
    const int tid  = threadIdx.x;
    const int wid  = tid >> 5;
    const int lane = tid & 31;
    const int wm   = wid >> 2;
    const int wn   = wid & 3;
    const int sel  = lane >> 3;
    const int rowin = lane & 7;
    const int g    = lane >> 2;
    const int tq   = lane & 3;
    const int NKT = HID >> 6;   // 64

    const __half* gA = Apk + ((size_t)(blockIdx.y * (HID >> 5)) << 12);
    const __half* gB = Bpk + ((size_t)(blockIdx.x * (HID >> 5)) << 12);

    float acc[4][4][4];
#pragma unroll
    for (int i = 0; i < 4; i++)
#pragma unroll
        for (int j = 0; j < 4; j++)
#pragma unroll
            for (int k = 0; k < 4; k++) acc[i][j][k] = 0.f;

    GEMM_MAINLOOP(gA, gB, NKT)

    // ---- Fused epilogue: stage acc to smem f32 [128][132] ----
    float* stf = (float*)(smx + SMEM_TILES);
#pragma unroll
    for (int mt = 0; mt < 4; mt++) {
        int r0 = wm * 64 + mt * 16 + g;
#pragma unroll
        for (int nt = 0; nt < 4; nt++) {
            int c = wn * 32 + nt * 8 + tq * 2;
            *(float2*)&stf[r0 * 132 + c]       = make_float2(acc[mt][nt][0], acc[mt][nt][1]);
            *(float2*)&stf[(r0 + 8) * 132 + c] = make_float2(acc[mt][nt][2], acc[mt][nt][3]);
        }
    }
    __syncthreads();

    const int hidx = blockIdx.x;
    const int mb   = blockIdx.y;
    const int gb   = (mb << 7) >> 10;
    const int st0  = ((mb << 7) & (SEQ - 1)) >> 6;

    if (hidx < NQH + NKV) {
        __half* baseg = (hidx < NQH)
            ? g_q16 + ((size_t)((gb * NQH + hidx) * 16 + st0) << 13)
            : g_k16 + ((size_t)((gb * NKV + (hidx - NQH)) * 16 + st0) << 13);
        for (int e = tid; e < 4096; e += 256) {
            int row = e >> 5;
            int i0  = (e & 31) << 1;
            float x1a = stf[row * 132 + i0];
            float x1b = stf[row * 132 + i0 + 1];
            float x2a = stf[row * 132 + i0 + 64];
            float x2b = stf[row * 132 + i0 + 65];
            float4 cssn = *(const float4*)&g_rope[((size_t)(mb << 7) + row) * 64 + i0];
            float y1a = x1a * cssn.x - x2a * cssn.y;
            float y1b = x1b * cssn.z - x2b * cssn.w;
            float y2a = x2a * cssn.x + x1a * cssn.y;
            float y2b = x2b * cssn.z + x1b * cssn.w;
            int stl = row >> 6, r = row & 63;
            __half* bp = baseg + (stl << 13);
            int roff = ((r >> 3) << 10) + ((r & 7) << 3);
            *(__half2*)(bp + roff + ((i0 >> 3) << 6) + (i0 & 7)) = __floats2half2_rn(y1a, y1b);
            int c2 = i0 + 64;
            *(__half2*)(bp + roff + ((c2 >> 3) << 6) + (c2 & 7)) = __floats2half2_rn(y2a, y2b);
        }
    } else {
        int kvh = hidx - (NQH + NKV);
        __half* dst0 = g_vT16 + ((size_t)((gb * NKV + kvh) * 16 + st0) << 13);
        for (int e = tid; e < 2048; e += 256) {
            int stl = e >> 10;
            int c = e & 1023;
            int m = c >> 3, rr = c & 7;
            int dr = ((m >> 3) << 3) + rr;
            int k0 = (m & 7) << 3;
            __half2 hv[4];
#pragma unroll
            for (int j = 0; j < 4; j++)
                hv[j] = __floats2half2_rn(stf[(stl * 64 + k0 + 2 * j) * 132 + dr],
                                          stf[(stl * 64 + k0 + 2 * j + 1) * 132 + dr]);
            *(uint4*)(dst0 + (stl << 13) + (m << 6) + (rr << 3)) = *(uint4*)hv;
        }
    }
}

// GEMM2: C = A @ B^T, f32 out.
__global__ __launch_bounds__(256, 2)
void gemm_f16(const __half* __restrict__ Apk, const __half* __restrict__ Bpk,
              float* __restrict__ C, int N, int K)
{
    extern __shared__ char smx[];
    const uint32_t s0 = smem_u32(smx);
    const int tid  = threadIdx.x;
    const int wid  = tid >> 5;
    const int lane = tid & 31;
    const int wm   = wid >> 2;
    const int wn   = wid & 3;
    const int sel  = lane >> 3;
    const int rowin = lane & 7;
    const int g    = lane >> 2;
    const int tq   = lane & 3;
    const long bm = (long)blockIdx.y * 128;
    const long bn = (long)blockIdx.x * 128;
    const int NKT = K >> 6;

    const __half* gA = Apk + ((size_t)(blockIdx.y * (K >> 5)) << 12);
    const __half* gB = Bpk + ((size_t)(blockIdx.x * (K >> 5)) << 12);

    float acc[4][4][4];
#pragma unroll
    for (int i = 0; i < 4; i++)
#pragma unroll
        for (int j = 0; j < 4; j++)
#pragma unroll
            for (int k = 0; k < 4; k++) acc[i][j][k] = 0.f;

    GEMM_MAINLOOP(gA, gB, NKT)

#pragma unroll
    for (int mt = 0; mt < 4; mt++) {
        long row0 = bm + wm * 64 + mt * 16 + g;
#pragma unroll
        for (int nt = 0; nt < 4; nt++) {
            long col = bn + wn * 32 + nt * 8 + tq * 2;
            *(float2*)&C[row0 * N + col]       = make_float2(acc[mt][nt][0], acc[mt][nt][1]);
            *(float2*)&C[(row0 + 8) * N + col] = make_float2(acc[mt][nt][2], acc[mt][nt][3]);
        }
    }
}

// ---------------------------------------------------------------------------
// Flash attention with mma.sync (unchanged)
// ---------------------------------------------------------------------------
#define FQ_OFF 1024
#define FK_OFF (1024 + 16384)
#define FV_OFF (1024 + 16384 + 16384)
#define FSTAGE 32768
#define FLASH_SMEM (1024 + 16384 + 2 * FSTAGE)

__global__ __launch_bounds__(128, 2) void flash_mma() {
    extern __shared__ char smf[];
    const uint32_t s0 = smem_u32(smf);
    const int tid  = threadIdx.x;
    const int warp = tid >> 5;
    const int lane = tid & 31;
    const int g    = lane >> 2;
    const int tq   = lane & 3;
    const int sel  = lane >> 3;
    const int rowin = lane & 7;
    const int qt = blockIdx.x, h = blockIdx.y, b = blockIdx.z;
    const int kvh = h >> 2;

    const __half* gQ = g_q16 + ((size_t)((b * NQH + h) * 16 + qt) << 13);
    const __half* gK = g_k16 + ((size_t)((b * NKV + kvh) * 16) << 13);
    const __half* gV = g_vT16 + ((size_t)((b * NKV + kvh) * 16) << 13);

    if (tid == 0) { MBAR_INIT(s0, 1); MBAR_INIT(s0 + 8, 1); }
    __syncthreads();
    const int NT = qt + 1;
    if (tid == 0) {
        MBAR_EXPECT_TX(s0, 3 * 16384);
        bulk_g2s(s0 + FQ_OFF, gQ, 16384, s0);
        bulk_g2s(s0 + FK_OFF, gK, 16384, s0);
        bulk_g2s(s0 + FV_OFF, gV, 16384, s0);
        if (NT > 1) {
            MBAR_EXPECT_TX(s0 + 8, 2 * 16384);
            bulk_g2s(s0 + FK_OFF + FSTAGE, gK + 8192, 16384, s0 + 8);
            bulk_g2s(s0 + FV_OFF + FSTAGE, gV + 8192, 16384, s0 + 8);
        }
    }

    float oacc[16][4];
#pragma unroll
    for (int i = 0; i < 16; i++)
#pragma unroll
        for (int j = 0; j < 4; j++) oacc[i][j] = 0.f;
    float m0 = -3.0e38f, m1 = -3.0e38f, l0 = 0.f, l1 = 0.f;
    const float scale = 0.08838834764831845f;

    for (int t = 0; t < NT; t++) {
        const int s = t & 1;
        mbar_wait(s0 + s * 8, (t >> 1) & 1);
        const uint32_t Qb = s0 + FQ_OFF;
        const uint32_t Kb = s0 + FK_OFF + s * FSTAGE;
        const uint32_t Vb = s0 + FV_OFF + s * FSTAGE;

        float sacc[8][4];
#pragma unroll
        for (int i = 0; i < 8; i++)
#pragma unroll
            for (int j = 0; j < 4; j++) sacc[i][j] = 0.f;

#pragma unroll
        for (int ks = 0; ks < 8; ks++) {
            uint32_t qa[4];
            {
                int rm = warp * 2 + (sel & 1);
                int km = 2 * ks + (sel >> 1);
                LDSM4(qa, Qb + (uint32_t)(((rm << 4) + km) * 128 + rowin * 16));
            }
            uint32_t kb[8][2];
#pragma unroll
            for (int bt = 0; bt < 4; bt++) {
                int nm = 2 * bt + (sel >> 1);
                int km = 2 * ks + (sel & 1);
                uint32_t r4[4];
                LDSM4(r4, Kb + (uint32_t)(((nm << 4) + km) * 128 + rowin * 16));
                kb[2 * bt][0] = r4[0]; kb[2 * bt][1] = r4[1];
                kb[2 * bt + 1][0] = r4[2]; kb[2 * bt + 1][1] = r4[3];
            }
#pragma unroll
            for (int nt = 0; nt < 8; nt++) MMA_F16(sacc[nt], qa, kb[nt]);
        }

        const bool diag = (t == qt);
#pragma unroll
        for (int nt = 0; nt < 8; nt++) {
#pragma unroll
            for (int c = 0; c < 4; c++) {
                float v = sacc[nt][c] * scale;
                if (diag) {
                    int kcol = nt * 8 + 2 * tq + (c & 1);
                    int qr = warp * 16 + g + ((c >= 2) ? 8 : 0);
                    if (kcol > qr) v = -1.0e30f;
                }
                sacc[nt][c] = v;
            }
        }

        float rm0 = -3.0e38f, rm1 = -3.0e38f;
#pragma unroll
        for (int nt = 0; nt < 8; nt++) {
            rm0 = fmaxf(rm0, fmaxf(sacc[nt][0], sacc[nt][1]));
            rm1 = fmaxf(rm1, fmaxf(sacc[nt][2], sacc[nt][3]));
        }
        rm0 = fmaxf(rm0, __shfl_xor_sync(0xffffffffu, rm0, 1));
        rm0 = fmaxf(rm0, __shfl_xor_sync(0xffffffffu, rm0, 2));
        rm1 = fmaxf(rm1, __shfl_xor_sync(0xffffffffu, rm1, 1));
        rm1 = fmaxf(rm1, __shfl_xor_sync(0xffffffffu, rm1, 2));
        float mn0 = fmaxf(m0, rm0), mn1 = fmaxf(m1, rm1);
        float a0 = expf(m0 - mn0), a1 = expf(m1 - mn1);
        m0 = mn0; m1 = mn1;
        float rs0 = 0.f, rs1 = 0.f;
#pragma unroll
        for (int nt = 0; nt < 8; nt++) {
            float p0 = expf(sacc[nt][0] - mn0);
            float p1 = expf(sacc[nt][1] - mn0);
            float p2 = expf(sacc[nt][2] - mn1);
            float p3 = expf(sacc[nt][3] - mn1);
            sacc[nt][0] = p0; sacc[nt][1] = p1; sacc[nt][2] = p2; sacc[nt][3] = p3;
            rs0 += p0 + p1; rs1 += p2 + p3;
        }
        rs0 += __shfl_xor_sync(0xffffffffu, rs0, 1);
        rs0 += __shfl_xor_sync(0xffffffffu, rs0, 2);
        rs1 += __shfl_xor_sync(0xffffffffu, rs1, 1);
        rs1 += __shfl_xor_sync(0xffffffffu, rs1, 2);
        l0 = l0 * a0 + rs0;
        l1 = l1 * a1 + rs1;
#pragma unroll
        for (int nt = 0; nt < 16; nt++) {
            oacc[nt][0] *= a0; oacc[nt][1] *= a0;
            oacc[nt][2] *= a1; oacc[nt][3] *= a1;
        }

        uint32_t pf[4][4];
#pragma unroll
        for (int s4 = 0; s4 < 4; s4++) {
            pf[s4][0] = f22u(sacc[2 * s4][0],     sacc[2 * s4][1]);
            pf[s4][1] = f22u(sacc[2 * s4][2],     sacc[2 * s4][3]);
            pf[s4][2] = f22u(sacc[2 * s4 + 1][0], sacc[2 * s4 + 1][1]);
            pf[s4][3] = f22u(sacc[2 * s4 + 1][2], sacc[2 * s4 + 1][3]);
        }

#pragma unroll
        for (int s4 = 0; s4 < 4; s4++) {
#pragma unroll
            for (int bt = 0; bt < 8; bt++) {
                int dm = 2 * bt + (sel >> 1);
                int km2 = 2 * s4 + (sel & 1);
                uint32_t r4[4];
                LDSM4(r4, Vb + (uint32_t)(((dm << 3) + km2) * 128 + rowin * 16));
                MMA_F16(oacc[2 * bt],     pf[s4], r4);
                MMA_F16(oacc[2 * bt + 1], pf[s4], (r4 + 2));
            }
        }

        __syncthreads();
        if (tid == 0 && t + 2 < NT) {
            MBAR_EXPECT_TX(s0 + s * 8, 2 * 16384);
            bulk_g2s(Kb, gK + ((size_t)(t + 2) << 13), 16384, s0 + s * 8);
            bulk_g2s(Vb, gV + ((size_t)(t + 2) << 13), 16384, s0 + s * 8);
        }
    }

    float i0 = 1.0f / l0, i1 = 1.0f / l1;
    int rowg = b * SEQ + qt * 64 + warp * 16 + g;
#pragma unroll
    for (int nt = 0; nt < 16; nt++) {
        int c8 = h * 16 + nt;
        int ktl = c8 >> 2, kc = c8 & 3;
        {
            int r = rowg;
            size_t mb = r >> 7; int rr = r & 127;
            __half* d = g_attn_pk + (((mb << 7) + ktl) << 12)
                      + (((((rr >> 3) << 2) + kc) << 6) + ((rr & 7) << 3)) + 2 * tq;
            *(__half2*)d = __floats2half2_rn(oacc[nt][0] * i0, oacc[nt][1] * i0);
        }
        {
            int r = rowg + 8;
            size_t mb = r >> 7; int rr = r & 127;
            __half* d = g_attn_pk + (((mb << 7) + ktl) << 12)
                      + (((((rr >> 3) << 2) + kc) << 6) + ((rr & 7) << 3)) + 2 * tq;
            *(__half2*)d = __floats2half2_rn(oacc[nt][2] * i1, oacc[nt][3] * i1);
        }
    }
}

// ---------------------------------------------------------------------------
// Launch
// ---------------------------------------------------------------------------
extern "C" void kernel_launch(void* const* d_in, const int* in_sizes, int n_in,
                              void* d_out, int out_size) {
    const int*   positions = (const int*)d_in[0];
    const float* hidden    = (const float*)d_in[1];
    const float* w_qkv     = (const float*)d_in[2];
    const float* w_o       = (const float*)d_in[3];
    float*       out       = (float*)d_out;

    static __half *hid_pk, *wqkv_pk, *wo_pk, *attn_pk;
    static bool init = false;
    if (!init) {
        cudaGetSymbolAddress((void**)&hid_pk,  g_hid_pk);
        cudaGetSymbolAddress((void**)&wqkv_pk, g_wqkv_pk);
        cudaGetSymbolAddress((void**)&wo_pk,   g_wo_pk);
        cudaGetSymbolAddress((void**)&attn_pk, g_attn_pk);
        cudaFuncSetAttribute(gemm_qkv, cudaFuncAttributeMaxDynamicSharedMemorySize,
                             QKV_SMEM);
        cudaFuncSetAttribute(gemm_f16, cudaFuncAttributeMaxDynamicSharedMemorySize,
                             GEMM_SMEM);
        cudaFuncSetAttribute(flash_mma, cudaFuncAttributeMaxDynamicSharedMemorySize,
                             FLASH_SMEM);
        init = true;
    }

    rope_tab<<<(BS_ROWS * 64 + 255) / 256, 256>>>(positions);
    act_pack<<<(BS_ROWS * 512 + 255) / 256, 256>>>(hidden, hid_pk);
    split_T_pack<<<dim3(QKV_N / 128, HID / 32), 256>>>(w_qkv, wqkv_pk, HID, QKV_N);
    split_T_pack<<<dim3(HID / 128, HID / 32), 256>>>(w_o, wo_pk, HID, HID);

    gemm_qkv<<<dim3(QKV_N / 128, BS_ROWS / 128), 256, QKV_SMEM>>>(hid_pk, wqkv_pk);

    flash_mma<<<dim3(SEQ / 64, NQH, BATCH), 128, FLASH_SMEM>>>();

    gemm_f16<<<dim3(HID / 128, BS_ROWS / 128), 256, GEMM_SMEM>>>(
        attn_pk, wo_pk, out, HID, HID);
}